// round 1
// baseline (speedup 1.0000x reference)
#include <cuda_runtime.h>
#include <cuda_bf16.h>
#include <cstdint>

#define NN 8192
#define FIN 1433
#define HIDD 128
#define OUTD 64
#define MAXE (1 << 20)

// ---------------- scratch (device globals; no allocations) ----------------
__device__ float g_h1p[NN * 256];      // feat @ W1  [N,2,128]
__device__ float g_agg1[NN * 256];     // layer1 aggregation -> h1 (in-place finalize)
__device__ float g_h2p[NN * 128];      // h1 @ W2    [N,2,64]
__device__ float g_agg2[NN * 128];     // layer2 aggregation
__device__ float g_h2[NN * 64];        // mean-head layer2 output
__device__ float g_agg3[2 * NN * 64];  // layer3 input-space aggregation [h][n][64]
__device__ float g_xs[2 * NN * FIN];   // decoder per-head projections
__device__ float g_el[3 * NN * 2];
__device__ float g_er[3 * NN * 2];
__device__ float g_m[3 * NN * 2];
__device__ float g_s[3 * NN * 2];
__device__ float g_ee[MAXE * 2];
__device__ float g_uv[2 * 64 * 2];     // u (el proj) then v (er proj), [2 heads][64]

// ---------------- helpers ----------------
__device__ __forceinline__ void atomicMaxF(float* addr, float v) {
    int old = __float_as_int(*addr);
    while (__int_as_float(old) < v) {
        int assumed = old;
        old = atomicCAS((int*)addr, assumed, __float_as_int(v));
        if (old == assumed) break;
    }
}

__device__ __forceinline__ float lrelu(float x, float a) { return x > 0.f ? x : a * x; }

// ---------------- init ----------------
__global__ void k_init(float* agg1, float* agg2, float* agg3, float* s_, float* m_) {
    int i = blockIdx.x * blockDim.x + threadIdx.x;
    int stride = gridDim.x * blockDim.x;
    for (int t = i; t < NN * 256; t += stride) agg1[t] = 0.f;
    for (int t = i; t < NN * 128; t += stride) agg2[t] = 0.f;
    for (int t = i; t < 2 * NN * 64; t += stride) agg3[t] = 0.f;
    for (int t = i; t < 3 * NN * 2; t += stride) { s_[t] = 0.f; m_[t] = -3.0e38f; }
}

// ---------------- generic SGEMM 128x128x8, 256 threads, 8x8 microtile ----------------
// A row-major [M,K] lda; B row-major [K,N] ldb (or [N,K] if TRANSB); C row-major [M,N] ldc.
template <bool TRANSB>
__global__ void sgemm128(const float* __restrict__ A, const float* __restrict__ B,
                         float* __restrict__ C, int M, int Nn, int K,
                         int lda, int ldb, int ldc) {
    __shared__ float As[8][128];
    __shared__ float Bs[8][128];
    const int tid = threadIdx.x;
    const int tx = tid & 15, ty = tid >> 4;
    const int rowBase = blockIdx.y * 128;
    const int colBase = blockIdx.x * 128;
    float acc[8][8];
#pragma unroll
    for (int i = 0; i < 8; i++)
#pragma unroll
        for (int j = 0; j < 8; j++) acc[i][j] = 0.f;

    for (int k0 = 0; k0 < K; k0 += 8) {
#pragma unroll
        for (int i = 0; i < 4; i++) {
            int lin = tid + i * 256;
            int m = lin >> 3, k = lin & 7;
            int gm = rowBase + m, gk = k0 + k;
            As[k][m] = (gm < M && gk < K) ? A[(size_t)gm * lda + gk] : 0.f;
        }
#pragma unroll
        for (int i = 0; i < 4; i++) {
            int lin = tid + i * 256;
            if (!TRANSB) {
                int k = lin >> 7, n = lin & 127;
                int gk = k0 + k, gn = colBase + n;
                Bs[k][n] = (gk < K && gn < Nn) ? B[(size_t)gk * ldb + gn] : 0.f;
            } else {
                int n = lin >> 3, k = lin & 7;
                int gk = k0 + k, gn = colBase + n;
                Bs[k][n] = (gk < K && gn < Nn) ? B[(size_t)gn * ldb + gk] : 0.f;
            }
        }
        __syncthreads();
#pragma unroll
        for (int k = 0; k < 8; k++) {
            float a[8], b[8];
#pragma unroll
            for (int i = 0; i < 8; i++) a[i] = As[k][ty * 8 + i];
#pragma unroll
            for (int j = 0; j < 8; j++) b[j] = Bs[k][tx * 8 + j];
#pragma unroll
            for (int i = 0; i < 8; i++)
#pragma unroll
                for (int j = 0; j < 8; j++) acc[i][j] = fmaf(a[i], b[j], acc[i][j]);
        }
        __syncthreads();
    }
#pragma unroll
    for (int i = 0; i < 8; i++) {
        int gm = rowBase + ty * 8 + i;
        if (gm >= M) continue;
#pragma unroll
        for (int j = 0; j < 8; j++) {
            int gn = colBase + tx * 8 + j;
            if (gn < Nn) C[(size_t)gm * ldc + gn] = acc[i][j];
        }
    }
}

// ---------------- attention logit (el/er) kernels ----------------
// hp [N, H*D], al/ar [H*D] -> el/er [N*2]. One warp per (n,h).
__global__ void k_elr(const float* __restrict__ hp, const float* __restrict__ al,
                      const float* __restrict__ ar, float* el, float* er, int D) {
    int w = (blockIdx.x * blockDim.x + threadIdx.x) >> 5;
    int lane = threadIdx.x & 31;
    if (w >= NN * 2) return;
    int n = w >> 1, h = w & 1;
    const float* row = hp + (size_t)n * (2 * D) + h * D;
    const float* a = al + h * D;
    const float* b = ar + h * D;
    float sl = 0.f, sr = 0.f;
    for (int d = lane; d < D; d += 32) { float x = row[d]; sl += x * a[d]; sr += x * b[d]; }
#pragma unroll
    for (int o = 16; o; o >>= 1) {
        sl += __shfl_down_sync(0xffffffffu, sl, o);
        sr += __shfl_down_sync(0xffffffffu, sr, o);
    }
    if (lane == 0) { el[w] = sl; er[w] = sr; }
}

// decoder: u[h][64] = W3_h @ al3_h, v likewise. One warp per (h,k) pair -> 128 warps.
__global__ void k_uv(const float* __restrict__ W3, const float* __restrict__ al3,
                     const float* __restrict__ ar3, float* uv) {
    int w = (blockIdx.x * blockDim.x + threadIdx.x) >> 5;
    int lane = threadIdx.x & 31;
    if (w >= 128) return;
    int h = w >> 6, k = w & 63;
    const float* Wr = W3 + (size_t)k * (2 * FIN) + h * FIN;
    const float* a = al3 + (size_t)h * FIN;
    const float* b = ar3 + (size_t)h * FIN;
    float su = 0.f, sv = 0.f;
    for (int f = lane; f < FIN; f += 32) { float ww = Wr[f]; su += ww * a[f]; sv += ww * b[f]; }
#pragma unroll
    for (int o = 16; o; o >>= 1) {
        su += __shfl_down_sync(0xffffffffu, su, o);
        sv += __shfl_down_sync(0xffffffffu, sv, o);
    }
    if (lane == 0) { uv[h * 64 + k] = su; uv[128 + h * 64 + k] = sv; }
}

// el3/er3: warp per (n,h), dot over 64 with u/v.
__global__ void k_elr3(const float* __restrict__ h2, const float* __restrict__ uv,
                       float* el, float* er) {
    int w = (blockIdx.x * blockDim.x + threadIdx.x) >> 5;
    int lane = threadIdx.x & 31;
    if (w >= NN * 2) return;
    int n = w >> 1, h = w & 1;
    const float* row = h2 + (size_t)n * 64;
    const float* u = uv + h * 64;
    const float* v = uv + 128 + h * 64;
    float sl = 0.f, sr = 0.f;
    for (int d = lane; d < 64; d += 32) { float x = row[d]; sl += x * u[d]; sr += x * v[d]; }
#pragma unroll
    for (int o = 16; o; o >>= 1) {
        sl += __shfl_down_sync(0xffffffffu, sl, o);
        sr += __shfl_down_sync(0xffffffffu, sr, o);
    }
    if (lane == 0) { el[w] = sl; er[w] = sr; }
}

// ---------------- edge softmax kernels ----------------
__global__ void k_edge_attn(const int* __restrict__ src, const int* __restrict__ dst,
                            const float* __restrict__ el, const float* __restrict__ er,
                            float* ee, float* m, int E) {
    int e = blockIdx.x * blockDim.x + threadIdx.x;
    if (e >= E) return;
    int s = src[e], d = dst[e];
#pragma unroll
    for (int h = 0; h < 2; h++) {
        float x = el[s * 2 + h] + er[d * 2 + h];
        x = x > 0.f ? x : 0.2f * x;
        ee[(size_t)e * 2 + h] = x;
        atomicMaxF(&m[d * 2 + h], x);
    }
}

__global__ void k_edge_exp(const int* __restrict__ dst, float* ee,
                           const float* __restrict__ m, float* s_, int E) {
    int e = blockIdx.x * blockDim.x + threadIdx.x;
    if (e >= E) return;
    int d = dst[e];
#pragma unroll
    for (int h = 0; h < 2; h++) {
        float ex = __expf(ee[(size_t)e * 2 + h] - m[d * 2 + h]);
        ee[(size_t)e * 2 + h] = ex;
        atomicAdd(&s_[d * 2 + h], ex);
    }
}

// generic output-space aggregation: hp/agg [N, H*D]; one block per edge.
__global__ void k_edge_agg(const int* __restrict__ src, const int* __restrict__ dst,
                           const float* __restrict__ ee, const float* __restrict__ s_,
                           const float* __restrict__ hp, float* agg, int HD, int D) {
    int e = blockIdx.x;
    int sN = src[e], d = dst[e];
    float a0 = ee[(size_t)e * 2] / s_[d * 2];
    float a1 = ee[(size_t)e * 2 + 1] / s_[d * 2 + 1];
    const float* row = hp + (size_t)sN * HD;
    float* orow = agg + (size_t)d * HD;
    for (int t = threadIdx.x; t < HD; t += blockDim.x) {
        float alpha = (t < D) ? a0 : a1;
        atomicAdd(&orow[t], alpha * row[t]);
    }
}

// decoder input-space aggregation: agg3 [h][n][64]; 64 threads per edge.
__global__ void k_edge_agg3(const int* __restrict__ src, const int* __restrict__ dst,
                            const float* __restrict__ ee, const float* __restrict__ s_,
                            const float* __restrict__ h2, float* agg3) {
    int e = blockIdx.x;
    int sN = src[e], d = dst[e];
    float a0 = ee[(size_t)e * 2] / s_[d * 2];
    float a1 = ee[(size_t)e * 2 + 1] / s_[d * 2 + 1];
    int t = threadIdx.x;
    float x = h2[(size_t)sN * 64 + t];
    atomicAdd(&agg3[(size_t)d * 64 + t], a0 * x);
    atomicAdd(&agg3[(size_t)(NN + d) * 64 + t], a1 * x);
}

// ---------------- finalize kernels ----------------
__global__ void k_final1(float* agg1, const float* __restrict__ b1) {
    int i = blockIdx.x * blockDim.x + threadIdx.x;
    if (i >= NN * 256) return;
    float x = agg1[i] + b1[i & 255];
    agg1[i] = lrelu(x, 0.01f);
}

__global__ void k_final2(const float* __restrict__ agg2, const float* __restrict__ b2,
                         float* h2) {
    int i = blockIdx.x * blockDim.x + threadIdx.x;
    if (i >= NN * 64) return;
    int n = i >> 6, d = i & 63;
    float x0 = lrelu(agg2[(size_t)n * 128 + d] + b2[d], 0.01f);
    float x1 = lrelu(agg2[(size_t)n * 128 + 64 + d] + b2[64 + d], 0.01f);
    h2[i] = 0.5f * (x0 + x1);
}

__global__ void k_final3(const float* __restrict__ xs, const float* __restrict__ b3,
                         float* x_hat) {
    int i = blockIdx.x * blockDim.x + threadIdx.x;
    if (i >= NN * FIN) return;
    int n = i / FIN, f = i - n * FIN;
    float x0 = lrelu(xs[(size_t)n * FIN + f] + b3[f], 0.01f);
    float x1 = lrelu(xs[(size_t)(NN + n) * FIN + f] + b3[FIN + f], 0.01f);
    x_hat[i] = 0.5f * (x0 + x1);
}

// ---------------- launch ----------------
extern "C" void kernel_launch(void* const* d_in, const int* in_sizes, int n_in,
                              void* d_out, int out_size) {
    const float* feat = (const float*)d_in[0];
    const int* src = (const int*)d_in[1];
    const int* dst = (const int*)d_in[2];
    const float* W1 = (const float*)d_in[3];
    const float* al1 = (const float*)d_in[4];
    const float* ar1 = (const float*)d_in[5];
    const float* b1 = (const float*)d_in[6];
    const float* W2 = (const float*)d_in[7];
    const float* al2 = (const float*)d_in[8];
    const float* ar2 = (const float*)d_in[9];
    const float* b2 = (const float*)d_in[10];
    const float* W3 = (const float*)d_in[11];
    const float* al3 = (const float*)d_in[12];
    const float* ar3 = (const float*)d_in[13];
    const float* b3 = (const float*)d_in[14];

    float* a_hat = (float*)d_out;
    float* x_hat = a_hat + (size_t)NN * NN;
    const int E = in_sizes[1];

    float *h1p, *agg1, *h2p, *agg2, *h2, *agg3, *xs, *el, *er, *m, *s, *ee, *uv;
    cudaGetSymbolAddress((void**)&h1p, g_h1p);
    cudaGetSymbolAddress((void**)&agg1, g_agg1);
    cudaGetSymbolAddress((void**)&h2p, g_h2p);
    cudaGetSymbolAddress((void**)&agg2, g_agg2);
    cudaGetSymbolAddress((void**)&h2, g_h2);
    cudaGetSymbolAddress((void**)&agg3, g_agg3);
    cudaGetSymbolAddress((void**)&xs, g_xs);
    cudaGetSymbolAddress((void**)&el, g_el);
    cudaGetSymbolAddress((void**)&er, g_er);
    cudaGetSymbolAddress((void**)&m, g_m);
    cudaGetSymbolAddress((void**)&s, g_s);
    cudaGetSymbolAddress((void**)&ee, g_ee);
    cudaGetSymbolAddress((void**)&uv, g_uv);

    float *el1 = el, *el2 = el + NN * 2, *el3 = el + 2 * NN * 2;
    float *er1 = er, *er2 = er + NN * 2, *er3 = er + 2 * NN * 2;
    float *m1 = m, *m2 = m + NN * 2, *m3 = m + 2 * NN * 2;
    float *s1 = s, *s2 = s + NN * 2, *s3 = s + 2 * NN * 2;

    const int eb = (E + 255) / 256;

    k_init<<<4096, 256>>>(agg1, agg2, agg3, s, m);

    // ---- layer 1: F(1433) -> [N,2,128] ----
    {
        dim3 grid((256 + 127) / 128, (NN + 127) / 128);
        sgemm128<false><<<grid, 256>>>(feat, W1, h1p, NN, 256, FIN, FIN, 256, 256);
    }
    k_elr<<<(NN * 2 * 32 + 255) / 256, 256>>>(h1p, al1, ar1, el1, er1, HIDD);
    k_edge_attn<<<eb, 256>>>(src, dst, el1, er1, ee, m1, E);
    k_edge_exp<<<eb, 256>>>(dst, ee, m1, s1, E);
    k_edge_agg<<<E, 256>>>(src, dst, ee, s1, h1p, agg1, 256, 128);
    k_final1<<<(NN * 256 + 255) / 256, 256>>>(agg1, b1);

    // ---- layer 2: 256 -> [N,2,64] -> mean -> h2 [N,64] ----
    {
        dim3 grid((128 + 127) / 128, (NN + 127) / 128);
        sgemm128<false><<<grid, 256>>>(agg1, W2, h2p, NN, 128, 256, 256, 128, 128);
    }
    k_elr<<<(NN * 2 * 32 + 255) / 256, 256>>>(h2p, al2, ar2, el2, er2, OUTD);
    k_edge_attn<<<eb, 256>>>(src, dst, el2, er2, ee, m2, E);
    k_edge_exp<<<eb, 256>>>(dst, ee, m2, s2, E);
    k_edge_agg<<<E, 128>>>(src, dst, ee, s2, h2p, agg2, 128, 64);
    k_final2<<<(NN * 64 + 255) / 256, 256>>>(agg2, b2, h2);

    // ---- structure decoder: a_hat = h2 @ h2^T ----
    {
        dim3 grid(NN / 128, NN / 128);
        sgemm128<true><<<grid, 256>>>(h2, h2, a_hat, NN, NN, 64, 64, 64, NN);
    }

    // ---- attribute decoder: aggregate in 64-dim input space, then project ----
    k_uv<<<16, 256>>>(W3, al3, ar3, uv);
    k_elr3<<<(NN * 2 * 32 + 255) / 256, 256>>>(h2, uv, el3, er3);
    k_edge_attn<<<eb, 256>>>(src, dst, el3, er3, ee, m3, E);
    k_edge_exp<<<eb, 256>>>(dst, ee, m3, s3, E);
    k_edge_agg3<<<E, 64>>>(src, dst, ee, s3, h2, agg3);
    {
        dim3 grid((FIN + 127) / 128, (NN + 127) / 128);
        sgemm128<false><<<grid, 256>>>(agg3, W3, xs, NN, FIN, 64, 64, 2 * FIN, FIN);
        sgemm128<false><<<grid, 256>>>(agg3 + (size_t)NN * 64, W3 + FIN,
                                       xs + (size_t)NN * FIN, NN, FIN, 64, 64, 2 * FIN, FIN);
    }
    k_final3<<<(NN * FIN + 255) / 256, 256>>>(xs, b3, x_hat);
}

// round 2
// speedup vs baseline: 1.4199x; 1.4199x over previous
#include <cuda_runtime.h>
#include <cuda_bf16.h>
#include <cstdint>

#define NN 8192
#define FIN 1433
#define FINP 1436      // padded to multiple of 4
#define HIDD 128
#define OUTD 64
#define MAXE (1 << 20)

// ---------------- scratch (device globals; no allocations) ----------------
__device__ float g_featp[NN * FINP];     // padded feat
__device__ float g_w3p0[64 * FINP];      // W3 head0, padded rows
__device__ float g_w3p1[64 * FINP];      // W3 head1, padded rows
__device__ float g_h1p[NN * 256];        // feat @ W1  [N,2,128]
__device__ float g_agg1[NN * 256];       // layer1 aggregation (finalized in place)
__device__ float g_h2p[NN * 128];        // h1 @ W2    [N,2,64]
__device__ float g_agg2[NN * 128];       // layer2 aggregation
__device__ float g_h2[NN * 64];          // mean-head layer2 output
__device__ float g_agg3[2 * NN * 64];    // layer3 input-space aggregation [h][n][64]
__device__ float g_xs[2 * NN * FIN];     // decoder per-head projections
__device__ float g_el[3 * NN * 2];
__device__ float g_er[3 * NN * 2];
__device__ float g_s[3 * NN * 2];
__device__ float g_ee[MAXE * 2];
__device__ float g_uv[2 * 64 * 2];

__device__ __forceinline__ float lrelu(float x, float a) { return x > 0.f ? x : a * x; }

// ---------------- init ----------------
__global__ void k_init(float* agg1, float* agg2, float* agg3, float* s_) {
    int i = blockIdx.x * blockDim.x + threadIdx.x;
    int stride = gridDim.x * blockDim.x;
    for (int t = i; t < NN * 256; t += stride) agg1[t] = 0.f;
    for (int t = i; t < NN * 128; t += stride) agg2[t] = 0.f;
    for (int t = i; t < 2 * NN * 64; t += stride) agg3[t] = 0.f;
    for (int t = i; t < 3 * NN * 2; t += stride) s_[t] = 0.f;
}

// ---------------- repack kernels (alignment) ----------------
__global__ void k_pack_feat(const float* __restrict__ feat, float* __restrict__ featp) {
    int n = blockIdx.x;
    for (int f = threadIdx.x; f < FINP; f += blockDim.x)
        featp[(size_t)n * FINP + f] = (f < FIN) ? feat[(size_t)n * FIN + f] : 0.f;
}
__global__ void k_pack_w3(const float* __restrict__ W3, float* __restrict__ p0,
                          float* __restrict__ p1) {
    int k = blockIdx.x;  // 64 rows
    for (int f = threadIdx.x; f < FINP; f += blockDim.x) {
        p0[(size_t)k * FINP + f] = (f < FIN) ? W3[(size_t)k * (2 * FIN) + f] : 0.f;
        p1[(size_t)k * FINP + f] = (f < FIN) ? W3[(size_t)k * (2 * FIN) + FIN + f] : 0.f;
    }
}

// ---------------- SGEMM: 128x128, BK=16, double-buffered, f32x2 FMA ----------------
// A row-major [M,K] lda (M multiple of 128, loads float4 aligned: lda%4==0 or guarded).
// B row-major [K,N] ldb (TRANSB: [N,K] ldb). C row-major [M,N] ldc.
// SYM: 1D triangular grid over (row>=col) 128-blocks; mirror-stores transpose tile.
typedef unsigned long long u64t;

template <bool TRANSB, bool SYM>
__global__ void __launch_bounds__(256)
sgemm_db(const float* __restrict__ A, const float* __restrict__ B, float* __restrict__ C,
         int M, int Nn, int K, int lda, int ldb, int ldc) {
    __shared__ float As[2][16][128];
    __shared__ float Bs[2][16][128];
    const int tid = threadIdx.x;
    const int tx = tid & 15, ty = tid >> 4;

    int rowBlk, colBlk;
    if (SYM) {
        int t = blockIdx.x;
        int r = (int)((sqrtf(8.f * (float)t + 1.f) - 1.f) * 0.5f);
        while ((r + 1) * (r + 2) / 2 <= t) r++;
        while (r * (r + 1) / 2 > t) r--;
        rowBlk = r;
        colBlk = t - r * (r + 1) / 2;
    } else {
        rowBlk = blockIdx.y;
        colBlk = blockIdx.x;
    }
    const int rowBase = rowBlk * 128;
    const int colBase = colBlk * 128;

    // staging index precompute
    const int am = tid & 127, ac = tid >> 7;           // A: row, chunk base (chunks ac, ac+2)
    const int bn4 = tid & 31, bk = tid >> 5;           // B no-trans: col4, k (k and k+8)
    const int tn = tid & 127, tc = tid >> 7;           // B trans: col, chunk base

    const int nk = (K + 15) >> 4;

    u64t acc[8][4];
#pragma unroll
    for (int i = 0; i < 8; i++)
#pragma unroll
        for (int p = 0; p < 4; p++) acc[i][p] = 0ULL;

    // ---- helpers as macros (guarded float4 global load) ----
#define LD4A(dst, gk)                                                       \
    {                                                                       \
        int _gk = (gk);                                                     \
        const float* _p = A + (size_t)(rowBase + am) * lda + _gk;           \
        if (_gk + 3 < K) dst = *(const float4*)_p;                          \
        else {                                                              \
            dst.x = (_gk + 0 < K) ? _p[0] : 0.f;                            \
            dst.y = (_gk + 1 < K) ? _p[1] : 0.f;                            \
            dst.z = (_gk + 2 < K) ? _p[2] : 0.f;                            \
            dst.w = (_gk + 3 < K) ? _p[3] : 0.f;                            \
        }                                                                   \
    }
#define LD4BN(dst, gk, gn)                                                  \
    {                                                                       \
        int _gk = (gk), _gn = (gn);                                         \
        const float* _p = B + (size_t)_gk * ldb + _gn;                      \
        if (_gk < K && _gn + 3 < Nn) dst = *(const float4*)_p;              \
        else {                                                              \
            dst.x = (_gk < K && _gn + 0 < Nn) ? _p[0] : 0.f;                \
            dst.y = (_gk < K && _gn + 1 < Nn) ? _p[1] : 0.f;                \
            dst.z = (_gk < K && _gn + 2 < Nn) ? _p[2] : 0.f;                \
            dst.w = (_gk < K && _gn + 3 < Nn) ? _p[3] : 0.f;                \
        }                                                                   \
    }
#define LD4BT(dst, gk, gn)                                                  \
    {                                                                       \
        int _gk = (gk), _gn = (gn);                                         \
        const float* _p = B + (size_t)_gn * ldb + _gk;                      \
        bool _v = (_gn < Nn);                                               \
        if (_v && _gk + 3 < K) dst = *(const float4*)_p;                    \
        else {                                                              \
            dst.x = (_v && _gk + 0 < K) ? _p[0] : 0.f;                      \
            dst.y = (_v && _gk + 1 < K) ? _p[1] : 0.f;                      \
            dst.z = (_v && _gk + 2 < K) ? _p[2] : 0.f;                      \
            dst.w = (_v && _gk + 3 < K) ? _p[3] : 0.f;                      \
        }                                                                   \
    }
#define STSA(buf, v, chunk)                                                 \
    {                                                                       \
        As[buf][(chunk) * 4 + 0][am] = v.x;                                 \
        As[buf][(chunk) * 4 + 1][am] = v.y;                                 \
        As[buf][(chunk) * 4 + 2][am] = v.z;                                 \
        As[buf][(chunk) * 4 + 3][am] = v.w;                                 \
    }
#define STSBT(buf, v, chunk)                                                \
    {                                                                       \
        Bs[buf][(chunk) * 4 + 0][tn] = v.x;                                 \
        Bs[buf][(chunk) * 4 + 1][tn] = v.y;                                 \
        Bs[buf][(chunk) * 4 + 2][tn] = v.z;                                 \
        Bs[buf][(chunk) * 4 + 3][tn] = v.w;                                 \
    }

    // prologue: stage 0 directly
    {
        float4 ra0, ra1;
        LD4A(ra0, ac * 4);
        LD4A(ra1, (ac + 2) * 4);
        STSA(0, ra0, ac);
        STSA(0, ra1, ac + 2);
        if (!TRANSB) {
            float4 rb0, rb1;
            LD4BN(rb0, bk, colBase + bn4 * 4);
            LD4BN(rb1, bk + 8, colBase + bn4 * 4);
            *(float4*)&Bs[0][bk][bn4 * 4] = rb0;
            *(float4*)&Bs[0][bk + 8][bn4 * 4] = rb1;
        } else {
            float4 rb0, rb1;
            LD4BT(rb0, tc * 4, colBase + tn);
            LD4BT(rb1, (tc + 2) * 4, colBase + tn);
            STSBT(0, rb0, tc);
            STSBT(0, rb1, tc + 2);
        }
    }
    __syncthreads();

    for (int t = 0; t < nk; ++t) {
        const int buf = t & 1;
        const bool more = (t + 1 < nk);
        float4 ra0, ra1, rb0, rb1;
        if (more) {
            int k0 = (t + 1) * 16;
            LD4A(ra0, k0 + ac * 4);
            LD4A(ra1, k0 + (ac + 2) * 4);
            if (!TRANSB) {
                LD4BN(rb0, k0 + bk, colBase + bn4 * 4);
                LD4BN(rb1, k0 + bk + 8, colBase + bn4 * 4);
            } else {
                LD4BT(rb0, k0 + tc * 4, colBase + tn);
                LD4BT(rb1, k0 + (tc + 2) * 4, colBase + tn);
            }
        }

        // compute on buf
#pragma unroll
        for (int k = 0; k < 16; k++) {
            float4 bq0 = *(const float4*)&Bs[buf][k][tx * 8];
            float4 bq1 = *(const float4*)&Bs[buf][k][tx * 8 + 4];
            u64t b2[4];
            b2[0] = ((const u64t*)&bq0)[0];
            b2[1] = ((const u64t*)&bq0)[1];
            b2[2] = ((const u64t*)&bq1)[0];
            b2[3] = ((const u64t*)&bq1)[1];
            float4 aq0 = *(const float4*)&As[buf][k][ty * 8];
            float4 aq1 = *(const float4*)&As[buf][k][ty * 8 + 4];
            float av[8] = {aq0.x, aq0.y, aq0.z, aq0.w, aq1.x, aq1.y, aq1.z, aq1.w};
#pragma unroll
            for (int i = 0; i < 8; i++) {
                u64t a2;
                asm("mov.b64 %0, {%1, %1};" : "=l"(a2) : "f"(av[i]));
#pragma unroll
                for (int p = 0; p < 4; p++) {
                    asm("fma.rn.f32x2 %0, %1, %2, %0;"
                        : "+l"(acc[i][p]) : "l"(a2), "l"(b2[p]));
                }
            }
        }

        if (more) {
            const int nb = buf ^ 1;
            STSA(nb, ra0, ac);
            STSA(nb, ra1, ac + 2);
            if (!TRANSB) {
                *(float4*)&Bs[nb][bk][bn4 * 4] = rb0;
                *(float4*)&Bs[nb][bk + 8][bn4 * 4] = rb1;
            } else {
                STSBT(nb, rb0, tc);
                STSBT(nb, rb1, tc + 2);
            }
        }
        __syncthreads();
    }

    // store
#pragma unroll
    for (int i = 0; i < 8; i++) {
        int gm = rowBase + ty * 8 + i;
#pragma unroll
        for (int p = 0; p < 4; p++) {
            float lo, hi;
            asm("mov.b64 {%0, %1}, %2;" : "=f"(lo), "=f"(hi) : "l"(acc[i][p]));
            int gn = colBase + tx * 8 + 2 * p;
            if (gn < Nn) C[(size_t)gm * ldc + gn] = lo;
            if (gn + 1 < Nn) C[(size_t)gm * ldc + gn + 1] = hi;
            if (SYM) {
                C[(size_t)gn * ldc + gm] = lo;
                C[(size_t)(gn + 1) * ldc + gm] = hi;
            }
        }
    }
#undef LD4A
#undef LD4BN
#undef LD4BT
#undef STSA
#undef STSBT
}

// ---------------- attention logit (el/er) kernels ----------------
__global__ void k_elr(const float* __restrict__ hp, const float* __restrict__ al,
                      const float* __restrict__ ar, float* el, float* er, int D) {
    int w = (blockIdx.x * blockDim.x + threadIdx.x) >> 5;
    int lane = threadIdx.x & 31;
    if (w >= NN * 2) return;
    int n = w >> 1, h = w & 1;
    const float* row = hp + (size_t)n * (2 * D) + h * D;
    const float* a = al + h * D;
    const float* b = ar + h * D;
    float sl = 0.f, sr = 0.f;
    for (int d = lane; d < D; d += 32) { float x = row[d]; sl += x * a[d]; sr += x * b[d]; }
#pragma unroll
    for (int o = 16; o; o >>= 1) {
        sl += __shfl_down_sync(0xffffffffu, sl, o);
        sr += __shfl_down_sync(0xffffffffu, sr, o);
    }
    if (lane == 0) { el[w] = sl; er[w] = sr; }
}

__global__ void k_uv(const float* __restrict__ W3, const float* __restrict__ al3,
                     const float* __restrict__ ar3, float* uv) {
    int w = (blockIdx.x * blockDim.x + threadIdx.x) >> 5;
    int lane = threadIdx.x & 31;
    if (w >= 128) return;
    int h = w >> 6, k = w & 63;
    const float* Wr = W3 + (size_t)k * (2 * FIN) + h * FIN;
    const float* a = al3 + (size_t)h * FIN;
    const float* b = ar3 + (size_t)h * FIN;
    float su = 0.f, sv = 0.f;
    for (int f = lane; f < FIN; f += 32) { float ww = Wr[f]; su += ww * a[f]; sv += ww * b[f]; }
#pragma unroll
    for (int o = 16; o; o >>= 1) {
        su += __shfl_down_sync(0xffffffffu, su, o);
        sv += __shfl_down_sync(0xffffffffu, sv, o);
    }
    if (lane == 0) { uv[h * 64 + k] = su; uv[128 + h * 64 + k] = sv; }
}

__global__ void k_elr3(const float* __restrict__ h2, const float* __restrict__ uv,
                       float* el, float* er) {
    int w = (blockIdx.x * blockDim.x + threadIdx.x) >> 5;
    int lane = threadIdx.x & 31;
    if (w >= NN * 2) return;
    int n = w >> 1, h = w & 1;
    const float* row = h2 + (size_t)n * 64;
    const float* u = uv + h * 64;
    const float* v = uv + 128 + h * 64;
    float sl = 0.f, sr = 0.f;
    for (int d = lane; d < 64; d += 32) { float x = row[d]; sl += x * u[d]; sr += x * v[d]; }
#pragma unroll
    for (int o = 16; o; o >>= 1) {
        sl += __shfl_down_sync(0xffffffffu, sl, o);
        sr += __shfl_down_sync(0xffffffffu, sr, o);
    }
    if (lane == 0) { el[w] = sl; er[w] = sr; }
}

// ---------------- fused edge softmax (no max pass; logits bounded) ----------------
__global__ void k_edge_soft(const int* __restrict__ src, const int* __restrict__ dst,
                            const float* __restrict__ el, const float* __restrict__ er,
                            float* __restrict__ ee, float* __restrict__ s_, int E) {
    int e = blockIdx.x * blockDim.x + threadIdx.x;
    if (e >= E) return;
    int s = src[e], d = dst[e];
    float2 l = *(const float2*)&el[s * 2];
    float2 r = *(const float2*)&er[d * 2];
    float e0 = l.x + r.x; e0 = e0 > 0.f ? e0 : 0.2f * e0;
    float e1 = l.y + r.y; e1 = e1 > 0.f ? e1 : 0.2f * e1;
    float x0 = __expf(e0), x1 = __expf(e1);
    *(float2*)&ee[(size_t)e * 2] = make_float2(x0, x1);
    atomicAdd(&s_[d * 2], x0);
    atomicAdd(&s_[d * 2 + 1], x1);
}

// ---------------- warp-per-edge aggregation ----------------
__global__ void k_agg1(const int* __restrict__ src, const int* __restrict__ dst,
                       const float* __restrict__ ee, const float* __restrict__ s_,
                       const float* __restrict__ hp, float* __restrict__ agg, int E) {
    int w = (blockIdx.x * blockDim.x + threadIdx.x) >> 5;
    int lane = threadIdx.x & 31;
    if (w >= E) return;
    int sN = src[w], d = dst[w];
    float a0 = 0.f, a1 = 0.f;
    if (lane == 0) {
        float2 ev = *(const float2*)&ee[(size_t)w * 2];
        float2 sv = *(const float2*)&s_[d * 2];
        a0 = ev.x / sv.x; a1 = ev.y / sv.y;
    }
    a0 = __shfl_sync(0xffffffffu, a0, 0);
    a1 = __shfl_sync(0xffffffffu, a1, 0);
    const float4* row = (const float4*)(hp + (size_t)sN * 256);
    float* o = agg + (size_t)d * 256;
    float4 v0 = row[lane];
    float4 v1 = row[32 + lane];
    int b = lane * 4;
    atomicAdd(&o[b + 0], a0 * v0.x); atomicAdd(&o[b + 1], a0 * v0.y);
    atomicAdd(&o[b + 2], a0 * v0.z); atomicAdd(&o[b + 3], a0 * v0.w);
    atomicAdd(&o[128 + b + 0], a1 * v1.x); atomicAdd(&o[128 + b + 1], a1 * v1.y);
    atomicAdd(&o[128 + b + 2], a1 * v1.z); atomicAdd(&o[128 + b + 3], a1 * v1.w);
}

__global__ void k_agg2(const int* __restrict__ src, const int* __restrict__ dst,
                       const float* __restrict__ ee, const float* __restrict__ s_,
                       const float* __restrict__ hp, float* __restrict__ agg, int E) {
    int w = (blockIdx.x * blockDim.x + threadIdx.x) >> 5;
    int lane = threadIdx.x & 31;
    if (w >= E) return;
    int sN = src[w], d = dst[w];
    float a0 = 0.f, a1 = 0.f;
    if (lane == 0) {
        float2 ev = *(const float2*)&ee[(size_t)w * 2];
        float2 sv = *(const float2*)&s_[d * 2];
        a0 = ev.x / sv.x; a1 = ev.y / sv.y;
    }
    a0 = __shfl_sync(0xffffffffu, a0, 0);
    a1 = __shfl_sync(0xffffffffu, a1, 0);
    float alpha = (lane < 16) ? a0 : a1;
    const float4* row = (const float4*)(hp + (size_t)sN * 128);
    float* o = agg + (size_t)d * 128;
    float4 v = row[lane];
    int b = lane * 4;
    atomicAdd(&o[b + 0], alpha * v.x); atomicAdd(&o[b + 1], alpha * v.y);
    atomicAdd(&o[b + 2], alpha * v.z); atomicAdd(&o[b + 3], alpha * v.w);
}

__global__ void k_agg3(const int* __restrict__ src, const int* __restrict__ dst,
                       const float* __restrict__ ee, const float* __restrict__ s_,
                       const float* __restrict__ h2, float* __restrict__ agg3, int E) {
    int w = (blockIdx.x * blockDim.x + threadIdx.x) >> 5;
    int lane = threadIdx.x & 31;
    if (w >= E) return;
    int sN = src[w], d = dst[w];
    float a0 = 0.f, a1 = 0.f;
    if (lane == 0) {
        float2 ev = *(const float2*)&ee[(size_t)w * 2];
        float2 sv = *(const float2*)&s_[d * 2];
        a0 = ev.x / sv.x; a1 = ev.y / sv.y;
    }
    a0 = __shfl_sync(0xffffffffu, a0, 0);
    a1 = __shfl_sync(0xffffffffu, a1, 0);
    float2 v = ((const float2*)(h2 + (size_t)sN * 64))[lane];
    int b = lane * 2;
    atomicAdd(&agg3[(size_t)d * 64 + b], a0 * v.x);
    atomicAdd(&agg3[(size_t)d * 64 + b + 1], a0 * v.y);
    atomicAdd(&agg3[(size_t)(NN + d) * 64 + b], a1 * v.x);
    atomicAdd(&agg3[(size_t)(NN + d) * 64 + b + 1], a1 * v.y);
}

// ---------------- finalize kernels ----------------
__global__ void k_final1(float* agg1, const float* __restrict__ b1) {
    int i = blockIdx.x * blockDim.x + threadIdx.x;
    if (i >= NN * 256) return;
    float x = agg1[i] + b1[i & 255];
    agg1[i] = lrelu(x, 0.01f);
}

__global__ void k_final2(const float* __restrict__ agg2, const float* __restrict__ b2,
                         float* h2) {
    int i = blockIdx.x * blockDim.x + threadIdx.x;
    if (i >= NN * 64) return;
    int n = i >> 6, d = i & 63;
    float x0 = lrelu(agg2[(size_t)n * 128 + d] + b2[d], 0.01f);
    float x1 = lrelu(agg2[(size_t)n * 128 + 64 + d] + b2[64 + d], 0.01f);
    h2[i] = 0.5f * (x0 + x1);
}

__global__ void k_final3(const float* __restrict__ xs, const float* __restrict__ b3,
                         float* x_hat) {
    int i = blockIdx.x * blockDim.x + threadIdx.x;
    if (i >= NN * FIN) return;
    int n = i / FIN, f = i - n * FIN;
    float x0 = lrelu(xs[(size_t)n * FIN + f] + b3[f], 0.01f);
    float x1 = lrelu(xs[(size_t)(NN + n) * FIN + f] + b3[FIN + f], 0.01f);
    x_hat[i] = 0.5f * (x0 + x1);
}

// ---------------- launch ----------------
extern "C" void kernel_launch(void* const* d_in, const int* in_sizes, int n_in,
                              void* d_out, int out_size) {
    const float* feat = (const float*)d_in[0];
    const int* src = (const int*)d_in[1];
    const int* dst = (const int*)d_in[2];
    const float* W1 = (const float*)d_in[3];
    const float* al1 = (const float*)d_in[4];
    const float* ar1 = (const float*)d_in[5];
    const float* b1 = (const float*)d_in[6];
    const float* W2 = (const float*)d_in[7];
    const float* al2 = (const float*)d_in[8];
    const float* ar2 = (const float*)d_in[9];
    const float* b2 = (const float*)d_in[10];
    const float* W3 = (const float*)d_in[11];
    const float* al3 = (const float*)d_in[12];
    const float* ar3 = (const float*)d_in[13];
    const float* b3 = (const float*)d_in[14];

    float* a_hat = (float*)d_out;
    float* x_hat = a_hat + (size_t)NN * NN;
    const int E = in_sizes[1];

    float *featp, *w3p0, *w3p1, *h1p, *agg1, *h2p, *agg2, *h2, *agg3, *xs, *el, *er, *s, *ee, *uv;
    cudaGetSymbolAddress((void**)&featp, g_featp);
    cudaGetSymbolAddress((void**)&w3p0, g_w3p0);
    cudaGetSymbolAddress((void**)&w3p1, g_w3p1);
    cudaGetSymbolAddress((void**)&h1p, g_h1p);
    cudaGetSymbolAddress((void**)&agg1, g_agg1);
    cudaGetSymbolAddress((void**)&h2p, g_h2p);
    cudaGetSymbolAddress((void**)&agg2, g_agg2);
    cudaGetSymbolAddress((void**)&h2, g_h2);
    cudaGetSymbolAddress((void**)&agg3, g_agg3);
    cudaGetSymbolAddress((void**)&xs, g_xs);
    cudaGetSymbolAddress((void**)&el, g_el);
    cudaGetSymbolAddress((void**)&er, g_er);
    cudaGetSymbolAddress((void**)&s, g_s);
    cudaGetSymbolAddress((void**)&ee, g_ee);
    cudaGetSymbolAddress((void**)&uv, g_uv);

    float *el1 = el, *el2 = el + NN * 2, *el3 = el + 2 * NN * 2;
    float *er1 = er, *er2 = er + NN * 2, *er3 = er + 2 * NN * 2;
    float *s1 = s, *s2 = s + NN * 2, *s3 = s + 2 * NN * 2;

    const int eb = (E + 255) / 256;
    const int wb = (E * 32 + 255) / 256;  // warp-per-edge grids

    k_init<<<2048, 256>>>(agg1, agg2, agg3, s);
    k_pack_feat<<<NN, 256>>>(feat, featp);
    k_pack_w3<<<64, 256>>>(W3, w3p0, w3p1);

    // ---- layer 1: F(1433) -> [N,2,128] ----
    {
        dim3 grid(2, 64);
        sgemm_db<false, false><<<grid, 256>>>(featp, W1, h1p, NN, 256, FIN, FINP, 256, 256);
    }
    k_elr<<<(NN * 2 * 32 + 255) / 256, 256>>>(h1p, al1, ar1, el1, er1, HIDD);
    k_edge_soft<<<eb, 256>>>(src, dst, el1, er1, ee, s1, E);
    k_agg1<<<wb, 256>>>(src, dst, ee, s1, h1p, agg1, E);
    k_final1<<<(NN * 256 + 255) / 256, 256>>>(agg1, b1);

    // ---- layer 2: 256 -> [N,2,64] -> mean -> h2 [N,64] ----
    {
        dim3 grid(1, 64);
        sgemm_db<false, false><<<grid, 256>>>(agg1, W2, h2p, NN, 128, 256, 256, 128, 128);
    }
    k_elr<<<(NN * 2 * 32 + 255) / 256, 256>>>(h2p, al2, ar2, el2, er2, OUTD);
    k_edge_soft<<<eb, 256>>>(src, dst, el2, er2, ee, s2, E);
    k_agg2<<<wb, 256>>>(src, dst, ee, s2, h2p, agg2, E);
    k_final2<<<(NN * 64 + 255) / 256, 256>>>(agg2, b2, h2);

    // ---- structure decoder: a_hat = h2 @ h2^T (symmetric, triangular grid) ----
    {
        int nb = NN / 128;
        int tblocks = nb * (nb + 1) / 2;  // 2080
        sgemm_db<true, true><<<tblocks, 256>>>(h2, h2, a_hat, NN, NN, 64, 64, 64, NN);
    }

    // ---- attribute decoder: aggregate in 64-dim input space, then project ----
    k_uv<<<16, 256>>>(W3, al3, ar3, uv);
    k_elr3<<<(NN * 2 * 32 + 255) / 256, 256>>>(h2, uv, el3, er3);
    k_edge_soft<<<eb, 256>>>(src, dst, el3, er3, ee, s3, E);
    k_agg3<<<wb, 256>>>(src, dst, ee, s3, h2, agg3, E);
    {
        dim3 grid(12, 64);
        sgemm_db<false, false><<<grid, 256>>>(agg3, w3p0, xs, NN, FIN, 64, 64, FINP, FIN);
        sgemm_db<false, false><<<grid, 256>>>(agg3 + (size_t)NN * 64, w3p1,
                                              xs + (size_t)NN * FIN, NN, FIN, 64, 64, FINP, FIN);
    }
    k_final3<<<(NN * FIN + 255) / 256, 256>>>(xs, b3, x_hat);
}

// round 3
// speedup vs baseline: 1.6319x; 1.1493x over previous
#include <cuda_runtime.h>
#include <cuda_bf16.h>
#include <cstdint>

#define NN 8192
#define FIN 1433
#define FINP 1436
#define MAXE (1 << 20)

typedef unsigned long long u64t;

// ---------------- scratch (device globals) ----------------
__device__ float g_featp[NN * FINP];
__device__ float g_w3p0[64 * FINP];
__device__ float g_w3p1[64 * FINP];
__device__ float g_h1p[NN * 256];
__device__ float g_agg1[NN * 256];
__device__ float g_h2p[NN * 128];
__device__ float g_h2[NN * 64];
__device__ float g_agg3[2 * NN * 64];
__device__ float g_xs[2 * NN * FIN];
__device__ float g_el[3 * NN * 2];
__device__ float g_er[3 * NN * 2];
__device__ float g_sinv[3 * NN * 2];
__device__ float g_uv[2 * 64 * 2];
__device__ int g_deg[NN];
__device__ int g_cursor[NN];
__device__ int g_rowptr[NN + 1];
__device__ int g_csrsrc[MAXE];

__device__ __forceinline__ float lrelu(float x, float a) { return x > 0.f ? x : a * x; }

// ================= CSR build =================
__global__ void k_zerodeg(int* deg) {
    int i = blockIdx.x * blockDim.x + threadIdx.x;
    if (i < NN) deg[i] = 0;
}
__global__ void k_deg(const int* __restrict__ dst, int* deg, int E) {
    int e = blockIdx.x * blockDim.x + threadIdx.x;
    if (e < E) atomicAdd(&deg[dst[e]], 1);
}
// single block, 256 threads, 8192 = 256*32 values
__global__ void k_scan(const int* __restrict__ deg, int* rowptr, int* cursor) {
    __shared__ int partx[257];
    int t = threadIdx.x;
    int base = t * 32;
    int loc[32];
    int s = 0;
#pragma unroll
    for (int i = 0; i < 32; i++) { loc[i] = s; s += deg[base + i]; }
    __shared__ int part[256];
    part[t] = s;
    __syncthreads();
    if (t == 0) {
        int acc = 0;
        for (int i = 0; i < 256; i++) { partx[i] = acc; acc += part[i]; }
        partx[256] = acc;
    }
    __syncthreads();
    int off = partx[t];
#pragma unroll
    for (int i = 0; i < 32; i++) {
        int v = off + loc[i];
        rowptr[base + i] = v;
        cursor[base + i] = v;
    }
    if (t == 0) rowptr[NN] = partx[256];
}
__global__ void k_scatter(const int* __restrict__ src, const int* __restrict__ dst,
                          int* cursor, int* csrsrc, int E) {
    int e = blockIdx.x * blockDim.x + threadIdx.x;
    if (e >= E) return;
    int d = dst[e];
    int idx = atomicAdd(&cursor[d], 1);
    csrsrc[idx] = src[e];
}

// ================= repack =================
__global__ void k_pack_feat(const float* __restrict__ feat, float* __restrict__ featp) {
    int n = blockIdx.x;
    for (int f = threadIdx.x; f < FINP; f += blockDim.x)
        featp[(size_t)n * FINP + f] = (f < FIN) ? feat[(size_t)n * FIN + f] : 0.f;
}
__global__ void k_pack_w3(const float* __restrict__ W3, float* __restrict__ p0,
                          float* __restrict__ p1) {
    int k = blockIdx.x;
    for (int f = threadIdx.x; f < FINP; f += blockDim.x) {
        p0[(size_t)k * FINP + f] = (f < FIN) ? W3[(size_t)k * (2 * FIN) + f] : 0.f;
        p1[(size_t)k * FINP + f] = (f < FIN) ? W3[(size_t)k * (2 * FIN) + FIN + f] : 0.f;
    }
}

// ================= SGEMM BM=64 BN=128 BK=16, f32x2, frag double-buffer =================
__global__ void __launch_bounds__(256)
sgemm64(const float* __restrict__ A, const float* __restrict__ B, float* __restrict__ C,
        int M, int Nn, int K, int lda, int ldb, int ldc) {
    __shared__ float As[2][16][68];   // padded row (16B-aligned rows, reduced conflicts)
    __shared__ float Bs[2][16][128];
    const int tid = threadIdx.x;
    const int tx = tid & 15, ty = tid >> 4;
    const int rowBase = blockIdx.y * 64;
    const int colBase = blockIdx.x * 128;

    const int am = tid >> 2, akc = tid & 3;     // A: row, k-chunk (coalesced along K)
    const int bn4 = tid & 31, bk = tid >> 5;    // B: col*4, k rows bk and bk+8

    const int nk = (K + 15) >> 4;

    u64t acc[4][4];
#pragma unroll
    for (int i = 0; i < 4; i++)
#pragma unroll
        for (int p = 0; p < 4; p++) acc[i][p] = 0ULL;

#define LD4A(dst, gk)                                                   \
    {                                                                   \
        int _gk = (gk);                                                 \
        const float* _p = A + (size_t)(rowBase + am) * lda + _gk;       \
        if (_gk + 3 < K) dst = *(const float4*)_p;                      \
        else {                                                          \
            dst.x = (_gk + 0 < K) ? _p[0] : 0.f;                        \
            dst.y = (_gk + 1 < K) ? _p[1] : 0.f;                        \
            dst.z = (_gk + 2 < K) ? _p[2] : 0.f;                        \
            dst.w = (_gk + 3 < K) ? _p[3] : 0.f;                        \
        }                                                               \
    }
#define LD4B(dst, gk, gn)                                               \
    {                                                                   \
        int _gk = (gk), _gn = (gn);                                     \
        const float* _p = B + (size_t)_gk * ldb + _gn;                  \
        if (_gk < K && _gn + 3 < Nn) dst = *(const float4*)_p;          \
        else {                                                          \
            dst.x = (_gk < K && _gn + 0 < Nn) ? _p[0] : 0.f;            \
            dst.y = (_gk < K && _gn + 1 < Nn) ? _p[1] : 0.f;            \
            dst.z = (_gk < K && _gn + 2 < Nn) ? _p[2] : 0.f;            \
            dst.w = (_gk < K && _gn + 3 < Nn) ? _p[3] : 0.f;            \
        }                                                               \
    }
#define STAGE(buf, ra, rb0, rb1)                                        \
    {                                                                   \
        As[buf][akc * 4 + 0][am] = ra.x;                                \
        As[buf][akc * 4 + 1][am] = ra.y;                                \
        As[buf][akc * 4 + 2][am] = ra.z;                                \
        As[buf][akc * 4 + 3][am] = ra.w;                                \
        *(float4*)&Bs[buf][bk][bn4 * 4] = rb0;                          \
        *(float4*)&Bs[buf][bk + 8][bn4 * 4] = rb1;                      \
    }

    {
        float4 ra, rb0, rb1;
        LD4A(ra, akc * 4);
        LD4B(rb0, bk, colBase + bn4 * 4);
        LD4B(rb1, bk + 8, colBase + bn4 * 4);
        STAGE(0, ra, rb0, rb1);
    }
    __syncthreads();

    for (int t = 0; t < nk; ++t) {
        const int buf = t & 1;
        const bool more = (t + 1 < nk);
        float4 ra, rb0, rb1;
        if (more) {
            int k0 = (t + 1) * 16;
            LD4A(ra, k0 + akc * 4);
            LD4B(rb0, k0 + bk, colBase + bn4 * 4);
            LD4B(rb1, k0 + bk + 8, colBase + bn4 * 4);
        }

        float af[2][4];
        u64t bf[2][4];
        {
            float4 a4 = *(const float4*)&As[buf][0][ty * 4];
            af[0][0] = a4.x; af[0][1] = a4.y; af[0][2] = a4.z; af[0][3] = a4.w;
            float4 b40 = *(const float4*)&Bs[buf][0][tx * 8];
            float4 b41 = *(const float4*)&Bs[buf][0][tx * 8 + 4];
            bf[0][0] = ((u64t*)&b40)[0]; bf[0][1] = ((u64t*)&b40)[1];
            bf[0][2] = ((u64t*)&b41)[0]; bf[0][3] = ((u64t*)&b41)[1];
        }
#pragma unroll
        for (int k = 0; k < 16; k++) {
            const int cur = k & 1;
            if (k < 15) {
                float4 a4 = *(const float4*)&As[buf][k + 1][ty * 4];
                af[cur ^ 1][0] = a4.x; af[cur ^ 1][1] = a4.y;
                af[cur ^ 1][2] = a4.z; af[cur ^ 1][3] = a4.w;
                float4 b40 = *(const float4*)&Bs[buf][k + 1][tx * 8];
                float4 b41 = *(const float4*)&Bs[buf][k + 1][tx * 8 + 4];
                bf[cur ^ 1][0] = ((u64t*)&b40)[0]; bf[cur ^ 1][1] = ((u64t*)&b40)[1];
                bf[cur ^ 1][2] = ((u64t*)&b41)[0]; bf[cur ^ 1][3] = ((u64t*)&b41)[1];
            }
#pragma unroll
            for (int i = 0; i < 4; i++) {
                u64t a2;
                asm("mov.b64 %0, {%1, %1};" : "=l"(a2) : "f"(af[cur][i]));
#pragma unroll
                for (int p = 0; p < 4; p++)
                    asm("fma.rn.f32x2 %0, %1, %2, %0;"
                        : "+l"(acc[i][p]) : "l"(a2), "l"(bf[cur][p]));
            }
        }
        if (more) { STAGE(buf ^ 1, ra, rb0, rb1); }
        __syncthreads();
    }

#pragma unroll
    for (int i = 0; i < 4; i++) {
        int gm = rowBase + ty * 4 + i;
#pragma unroll
        for (int p = 0; p < 4; p++) {
            float lo, hi;
            asm("mov.b64 {%0, %1}, %2;" : "=f"(lo), "=f"(hi) : "l"(acc[i][p]));
            int gn = colBase + tx * 8 + 2 * p;
            if (gn < Nn) C[(size_t)gm * ldc + gn] = lo;
            if (gn + 1 < Nn) C[(size_t)gm * ldc + gn + 1] = hi;
        }
    }
#undef LD4A
#undef LD4B
#undef STAGE
}

// ================= symmetric a_hat GEMM (128x128, TRANSB, mirror store) =================
__global__ void __launch_bounds__(256)
sgemm_sym(const float* __restrict__ A, float* __restrict__ C, int K, int lda, int ldc) {
    __shared__ float As[2][16][128];
    __shared__ float Bs[2][16][128];
    const int tid = threadIdx.x;
    const int tx = tid & 15, ty = tid >> 4;

    int t = blockIdx.x;
    int r = (int)((sqrtf(8.f * (float)t + 1.f) - 1.f) * 0.5f);
    while ((r + 1) * (r + 2) / 2 <= t) r++;
    while (r * (r + 1) / 2 > t) r--;
    const int rowBase = r * 128;
    const int colBase = (t - r * (r + 1) / 2) * 128;

    const int am = tid >> 1, akc = tid & 1;  // row, k-chunk (k = akc*4..+3 then +8)

    const int nk = (K + 15) >> 4;
    u64t acc[8][4];
#pragma unroll
    for (int i = 0; i < 8; i++)
#pragma unroll
        for (int p = 0; p < 4; p++) acc[i][p] = 0ULL;

#define STAGEP(buf, base, k0)                                              \
    {                                                                      \
        const float* _pa = A + (size_t)(rowBase + am) * lda + k0 + akc * 4;\
        float4 _ra = *(const float4*)_pa;                                  \
        float4 _ra2 = *(const float4*)(_pa + 8);                           \
        As[buf][akc * 4 + 0][am] = _ra.x;  As[buf][akc * 4 + 1][am] = _ra.y; \
        As[buf][akc * 4 + 2][am] = _ra.z;  As[buf][akc * 4 + 3][am] = _ra.w; \
        As[buf][akc * 4 + 8][am] = _ra2.x; As[buf][akc * 4 + 9][am] = _ra2.y; \
        As[buf][akc * 4 + 10][am] = _ra2.z; As[buf][akc * 4 + 11][am] = _ra2.w; \
        const float* _pb = A + (size_t)(colBase + am) * lda + k0 + akc * 4;\
        float4 _rb = *(const float4*)_pb;                                  \
        float4 _rb2 = *(const float4*)(_pb + 8);                           \
        Bs[buf][akc * 4 + 0][am] = _rb.x;  Bs[buf][akc * 4 + 1][am] = _rb.y; \
        Bs[buf][akc * 4 + 2][am] = _rb.z;  Bs[buf][akc * 4 + 3][am] = _rb.w; \
        Bs[buf][akc * 4 + 8][am] = _rb2.x; Bs[buf][akc * 4 + 9][am] = _rb2.y; \
        Bs[buf][akc * 4 + 10][am] = _rb2.z; Bs[buf][akc * 4 + 11][am] = _rb2.w; \
    }

    STAGEP(0, 0, 0);
    __syncthreads();

    for (int tt = 0; tt < nk; ++tt) {
        const int buf = tt & 1;
        if (tt + 1 < nk) STAGEP(buf ^ 1, 0, (tt + 1) * 16);
#pragma unroll
        for (int k = 0; k < 16; k++) {
            float4 bq0 = *(const float4*)&Bs[buf][k][tx * 8];
            float4 bq1 = *(const float4*)&Bs[buf][k][tx * 8 + 4];
            u64t b2[4];
            b2[0] = ((const u64t*)&bq0)[0];
            b2[1] = ((const u64t*)&bq0)[1];
            b2[2] = ((const u64t*)&bq1)[0];
            b2[3] = ((const u64t*)&bq1)[1];
            float4 aq0 = *(const float4*)&As[buf][k][ty * 8];
            float4 aq1 = *(const float4*)&As[buf][k][ty * 8 + 4];
            float av[8] = {aq0.x, aq0.y, aq0.z, aq0.w, aq1.x, aq1.y, aq1.z, aq1.w};
#pragma unroll
            for (int i = 0; i < 8; i++) {
                u64t a2;
                asm("mov.b64 %0, {%1, %1};" : "=l"(a2) : "f"(av[i]));
#pragma unroll
                for (int p = 0; p < 4; p++)
                    asm("fma.rn.f32x2 %0, %1, %2, %0;"
                        : "+l"(acc[i][p]) : "l"(a2), "l"(b2[p]));
            }
        }
        __syncthreads();
    }

#pragma unroll
    for (int i = 0; i < 8; i++) {
        int gm = rowBase + ty * 8 + i;
#pragma unroll
        for (int p = 0; p < 4; p++) {
            float lo, hi;
            asm("mov.b64 {%0, %1}, %2;" : "=f"(lo), "=f"(hi) : "l"(acc[i][p]));
            int gn = colBase + tx * 8 + 2 * p;
            C[(size_t)gm * ldc + gn] = lo;
            C[(size_t)gm * ldc + gn + 1] = hi;
            C[(size_t)gn * ldc + gm] = lo;
            C[(size_t)(gn + 1) * ldc + gm] = hi;
        }
    }
#undef STAGEP
}

// ================= attention logits =================
__global__ void k_elr(const float* __restrict__ hp, const float* __restrict__ al,
                      const float* __restrict__ ar, float* el, float* er, int D) {
    int w = (blockIdx.x * blockDim.x + threadIdx.x) >> 5;
    int lane = threadIdx.x & 31;
    if (w >= NN * 2) return;
    int n = w >> 1, h = w & 1;
    const float* row = hp + (size_t)n * (2 * D) + h * D;
    const float* a = al + h * D;
    const float* b = ar + h * D;
    float sl = 0.f, sr = 0.f;
    for (int d = lane; d < D; d += 32) { float x = row[d]; sl += x * a[d]; sr += x * b[d]; }
#pragma unroll
    for (int o = 16; o; o >>= 1) {
        sl += __shfl_down_sync(0xffffffffu, sl, o);
        sr += __shfl_down_sync(0xffffffffu, sr, o);
    }
    if (lane == 0) { el[w] = sl; er[w] = sr; }
}

__global__ void k_uv(const float* __restrict__ W3, const float* __restrict__ al3,
                     const float* __restrict__ ar3, float* uv) {
    int w = (blockIdx.x * blockDim.x + threadIdx.x) >> 5;
    int lane = threadIdx.x & 31;
    if (w >= 128) return;
    int h = w >> 6, k = w & 63;
    const float* Wr = W3 + (size_t)k * (2 * FIN) + h * FIN;
    const float* a = al3 + (size_t)h * FIN;
    const float* b = ar3 + (size_t)h * FIN;
    float su = 0.f, sv = 0.f;
    for (int f = lane; f < FIN; f += 32) { float ww = Wr[f]; su += ww * a[f]; sv += ww * b[f]; }
#pragma unroll
    for (int o = 16; o; o >>= 1) {
        su += __shfl_down_sync(0xffffffffu, su, o);
        sv += __shfl_down_sync(0xffffffffu, sv, o);
    }
    if (lane == 0) { uv[h * 64 + k] = su; uv[128 + h * 64 + k] = sv; }
}

__global__ void k_elr3(const float* __restrict__ h2, const float* __restrict__ uv,
                       float* el, float* er) {
    int w = (blockIdx.x * blockDim.x + threadIdx.x) >> 5;
    int lane = threadIdx.x & 31;
    if (w >= NN * 2) return;
    int n = w >> 1, h = w & 1;
    const float* row = h2 + (size_t)n * 64;
    const float* u = uv + h * 64;
    const float* v = uv + 128 + h * 64;
    float sl = 0.f, sr = 0.f;
    for (int d = lane; d < 64; d += 32) { float x = row[d]; sl += x * u[d]; sr += x * v[d]; }
#pragma unroll
    for (int o = 16; o; o >>= 1) {
        sl += __shfl_down_sync(0xffffffffu, sl, o);
        sr += __shfl_down_sync(0xffffffffu, sr, o);
    }
    if (lane == 0) { el[w] = sl; er[w] = sr; }
}

// ================= CSR softmax denominators (warp per dst) =================
__global__ void k_sum(const int* __restrict__ rowptr, const int* __restrict__ csrsrc,
                      const float* __restrict__ el, const float* __restrict__ er,
                      float* __restrict__ sinv) {
    int d = blockIdx.x * (blockDim.x >> 5) + (threadIdx.x >> 5);
    int lane = threadIdx.x & 31;
    if (d >= NN) return;
    int b = rowptr[d], e = rowptr[d + 1];
    float2 r = *(const float2*)&er[d * 2];
    float s0 = 0.f, s1 = 0.f;
    for (int i = b + lane; i < e; i += 32) {
        int s = csrsrc[i];
        float2 l = *(const float2*)&el[s * 2];
        float e0 = l.x + r.x; e0 = e0 > 0.f ? e0 : 0.2f * e0;
        float e1 = l.y + r.y; e1 = e1 > 0.f ? e1 : 0.2f * e1;
        s0 += __expf(e0); s1 += __expf(e1);
    }
#pragma unroll
    for (int o = 16; o; o >>= 1) {
        s0 += __shfl_down_sync(0xffffffffu, s0, o);
        s1 += __shfl_down_sync(0xffffffffu, s1, o);
    }
    if (lane == 0) { sinv[d * 2] = 1.f / s0; sinv[d * 2 + 1] = 1.f / s1; }
}

// ================= CSR gather aggregation =================
// layer1: block 256 per dst; out = lrelu(sum alpha*h1p + b1)
__global__ void __launch_bounds__(256)
k_agg1(const int* __restrict__ rowptr, const int* __restrict__ csrsrc,
       const float* __restrict__ el, const float* __restrict__ er,
       const float* __restrict__ sinv, const float* __restrict__ hp,
       const float* __restrict__ b1, float* __restrict__ out) {
    int d = blockIdx.x;
    int t = threadIdx.x;
    __shared__ float2 sal[128];
    __shared__ int ssrc[128];
    int b = rowptr[d], en = rowptr[d + 1];
    float2 r = *(const float2*)&er[d * 2];
    float2 inv = *(const float2*)&sinv[d * 2];
    float acc = 0.f;
    int h = t >> 7;
    for (int c = b; c < en; c += 128) {
        int cnt = min(128, en - c);
        __syncthreads();
        if (t < cnt) {
            int s = csrsrc[c + t];
            float2 l = *(const float2*)&el[s * 2];
            float e0 = l.x + r.x; e0 = e0 > 0.f ? e0 : 0.2f * e0;
            float e1 = l.y + r.y; e1 = e1 > 0.f ? e1 : 0.2f * e1;
            sal[t] = make_float2(__expf(e0) * inv.x, __expf(e1) * inv.y);
            ssrc[t] = s;
        }
        __syncthreads();
#pragma unroll 4
        for (int i = 0; i < cnt; i++) {
            float a = h ? sal[i].y : sal[i].x;
            acc = fmaf(a, hp[(size_t)ssrc[i] * 256 + t], acc);
        }
    }
    float x = acc + b1[t];
    out[(size_t)d * 256 + t] = lrelu(x, 0.01f);
}

// layer2: block 128 per dst; writes mean-head h2 = 0.5*(lrelu(o0+b)+lrelu(o1+b))
__global__ void __launch_bounds__(128)
k_agg2(const int* __restrict__ rowptr, const int* __restrict__ csrsrc,
       const float* __restrict__ el, const float* __restrict__ er,
       const float* __restrict__ sinv, const float* __restrict__ hp,
       const float* __restrict__ b2, float* __restrict__ h2) {
    int d = blockIdx.x;
    int t = threadIdx.x;
    __shared__ float2 sal[128];
    __shared__ int ssrc[128];
    __shared__ float o[128];
    int b = rowptr[d], en = rowptr[d + 1];
    float2 r = *(const float2*)&er[d * 2];
    float2 inv = *(const float2*)&sinv[d * 2];
    float acc = 0.f;
    int h = t >> 6;
    for (int c = b; c < en; c += 128) {
        int cnt = min(128, en - c);
        __syncthreads();
        if (t < cnt) {
            int s = csrsrc[c + t];
            float2 l = *(const float2*)&el[s * 2];
            float e0 = l.x + r.x; e0 = e0 > 0.f ? e0 : 0.2f * e0;
            float e1 = l.y + r.y; e1 = e1 > 0.f ? e1 : 0.2f * e1;
            sal[t] = make_float2(__expf(e0) * inv.x, __expf(e1) * inv.y);
            ssrc[t] = s;
        }
        __syncthreads();
#pragma unroll 4
        for (int i = 0; i < cnt; i++) {
            float a = h ? sal[i].y : sal[i].x;
            acc = fmaf(a, hp[(size_t)ssrc[i] * 128 + t], acc);
        }
    }
    o[t] = acc;
    __syncthreads();
    if (t < 64) {
        float x0 = lrelu(o[t] + b2[t], 0.01f);
        float x1 = lrelu(o[64 + t] + b2[64 + t], 0.01f);
        h2[(size_t)d * 64 + t] = 0.5f * (x0 + x1);
    }
}

// layer3: input-space aggregation; block 128 per dst -> agg3[h][n][64]
__global__ void __launch_bounds__(128)
k_agg3(const int* __restrict__ rowptr, const int* __restrict__ csrsrc,
       const float* __restrict__ el, const float* __restrict__ er,
       const float* __restrict__ sinv, const float* __restrict__ h2,
       float* __restrict__ agg3) {
    int d = blockIdx.x;
    int t = threadIdx.x;
    __shared__ float2 sal[128];
    __shared__ int ssrc[128];
    int b = rowptr[d], en = rowptr[d + 1];
    float2 r = *(const float2*)&er[d * 2];
    float2 inv = *(const float2*)&sinv[d * 2];
    float acc = 0.f;
    int h = t >> 6, dd = t & 63;
    for (int c = b; c < en; c += 128) {
        int cnt = min(128, en - c);
        __syncthreads();
        if (t < cnt) {
            int s = csrsrc[c + t];
            float2 l = *(const float2*)&el[s * 2];
            float e0 = l.x + r.x; e0 = e0 > 0.f ? e0 : 0.2f * e0;
            float e1 = l.y + r.y; e1 = e1 > 0.f ? e1 : 0.2f * e1;
            sal[t] = make_float2(__expf(e0) * inv.x, __expf(e1) * inv.y);
            ssrc[t] = s;
        }
        __syncthreads();
#pragma unroll 4
        for (int i = 0; i < cnt; i++) {
            float a = h ? sal[i].y : sal[i].x;
            acc = fmaf(a, h2[(size_t)ssrc[i] * 64 + dd], acc);
        }
    }
    agg3[((size_t)h * NN + d) * 64 + dd] = acc;
}

// ================= finalize decoder =================
__global__ void k_final3(const float* __restrict__ xs, const float* __restrict__ b3,
                         float* x_hat) {
    int i = blockIdx.x * blockDim.x + threadIdx.x;
    if (i >= NN * FIN) return;
    int n = i / FIN, f = i - n * FIN;
    float x0 = lrelu(xs[(size_t)n * FIN + f] + b3[f], 0.01f);
    float x1 = lrelu(xs[(size_t)(NN + n) * FIN + f] + b3[FIN + f], 0.01f);
    x_hat[i] = 0.5f * (x0 + x1);
}

// ================= launch =================
extern "C" void kernel_launch(void* const* d_in, const int* in_sizes, int n_in,
                              void* d_out, int out_size) {
    const float* feat = (const float*)d_in[0];
    const int* src = (const int*)d_in[1];
    const int* dst = (const int*)d_in[2];
    const float* W1 = (const float*)d_in[3];
    const float* al1 = (const float*)d_in[4];
    const float* ar1 = (const float*)d_in[5];
    const float* b1 = (const float*)d_in[6];
    const float* W2 = (const float*)d_in[7];
    const float* al2 = (const float*)d_in[8];
    const float* ar2 = (const float*)d_in[9];
    const float* b2 = (const float*)d_in[10];
    const float* W3 = (const float*)d_in[11];
    const float* al3 = (const float*)d_in[12];
    const float* ar3 = (const float*)d_in[13];
    const float* b3 = (const float*)d_in[14];

    float* a_hat = (float*)d_out;
    float* x_hat = a_hat + (size_t)NN * NN;
    const int E = in_sizes[1];

    float *featp, *w3p0, *w3p1, *h1p, *agg1, *h2p, *h2, *agg3, *xs, *el, *er, *sinv, *uv;
    int *deg, *cursor, *rowptr, *csrsrc;
    cudaGetSymbolAddress((void**)&featp, g_featp);
    cudaGetSymbolAddress((void**)&w3p0, g_w3p0);
    cudaGetSymbolAddress((void**)&w3p1, g_w3p1);
    cudaGetSymbolAddress((void**)&h1p, g_h1p);
    cudaGetSymbolAddress((void**)&agg1, g_agg1);
    cudaGetSymbolAddress((void**)&h2p, g_h2p);
    cudaGetSymbolAddress((void**)&h2, g_h2);
    cudaGetSymbolAddress((void**)&agg3, g_agg3);
    cudaGetSymbolAddress((void**)&xs, g_xs);
    cudaGetSymbolAddress((void**)&el, g_el);
    cudaGetSymbolAddress((void**)&er, g_er);
    cudaGetSymbolAddress((void**)&sinv, g_sinv);
    cudaGetSymbolAddress((void**)&uv, g_uv);
    cudaGetSymbolAddress((void**)&deg, g_deg);
    cudaGetSymbolAddress((void**)&cursor, g_cursor);
    cudaGetSymbolAddress((void**)&rowptr, g_rowptr);
    cudaGetSymbolAddress((void**)&csrsrc, g_csrsrc);

    float *el1 = el, *el2 = el + NN * 2, *el3 = el + 2 * NN * 2;
    float *er1 = er, *er2 = er + NN * 2, *er3 = er + 2 * NN * 2;
    float *s1 = sinv, *s2 = sinv + NN * 2, *s3 = sinv + 2 * NN * 2;

    const int eb = (E + 255) / 256;

    // ---- CSR build ----
    k_zerodeg<<<(NN + 255) / 256, 256>>>(deg);
    k_deg<<<eb, 256>>>(dst, deg, E);
    k_scan<<<1, 256>>>(deg, rowptr, cursor);
    k_scatter<<<eb, 256>>>(src, dst, cursor, csrsrc, E);

    // ---- repack ----
    k_pack_feat<<<NN, 256>>>(feat, featp);
    k_pack_w3<<<64, 256>>>(W3, w3p0, w3p1);

    // ---- layer 1 ----
    {
        dim3 grid(2, 128);
        sgemm64<<<grid, 256>>>(featp, W1, h1p, NN, 256, FIN, FINP, 256, 256);
    }
    k_elr<<<(NN * 2 * 32 + 255) / 256, 256>>>(h1p, al1, ar1, el1, er1, 128);
    k_sum<<<NN / 8, 256>>>(rowptr, csrsrc, el1, er1, s1);
    k_agg1<<<NN, 256>>>(rowptr, csrsrc, el1, er1, s1, h1p, b1, agg1);

    // ---- layer 2 ----
    {
        dim3 grid(1, 128);
        sgemm64<<<grid, 256>>>(agg1, W2, h2p, NN, 128, 256, 256, 128, 128);
    }
    k_elr<<<(NN * 2 * 32 + 255) / 256, 256>>>(h2p, al2, ar2, el2, er2, 64);
    k_sum<<<NN / 8, 256>>>(rowptr, csrsrc, el2, er2, s2);
    k_agg2<<<NN, 128>>>(rowptr, csrsrc, el2, er2, s2, h2p, b2, h2);

    // ---- structure decoder: a_hat = h2 @ h2^T (symmetric) ----
    {
        int nb = NN / 128;
        sgemm_sym<<<nb * (nb + 1) / 2, 256>>>(h2, a_hat, 64, 64, NN);
    }

    // ---- attribute decoder ----
    k_uv<<<16, 256>>>(W3, al3, ar3, uv);
    k_elr3<<<(NN * 2 * 32 + 255) / 256, 256>>>(h2, uv, el3, er3);
    k_sum<<<NN / 8, 256>>>(rowptr, csrsrc, el3, er3, s3);
    k_agg3<<<NN, 128>>>(rowptr, csrsrc, el3, er3, s3, h2, agg3);
    {
        dim3 grid(12, 128);
        sgemm64<<<grid, 256>>>(agg3, w3p0, xs, NN, FIN, 64, 64, FINP, FIN);
        sgemm64<<<grid, 256>>>(agg3 + (size_t)NN * 64, w3p1,
                               xs + (size_t)NN * FIN, NN, FIN, 64, 64, FINP, FIN);
    }
    k_final3<<<(NN * FIN + 255) / 256, 256>>>(xs, b3, x_hat);
}

// round 5
// speedup vs baseline: 2.1632x; 1.3256x over previous
#include <cuda_runtime.h>
#include <cuda_bf16.h>
#include <cstdint>

#define NN 8192
#define FIN 1433
#define FINP 1436
#define MAXE (1 << 20)

typedef unsigned long long u64t;

// ---------------- scratch (device globals) ----------------
__device__ float g_featp[NN * FINP];
__device__ float g_w3p0[64 * FINP];
__device__ float g_w3p1[64 * FINP];
__device__ float g_h1p[NN * 256];
__device__ float g_agg1[NN * 256];
__device__ float g_h2p[NN * 128];
__device__ float g_h2[NN * 64];
__device__ __nv_bfloat16 g_h2hi[NN * 64];
__device__ __nv_bfloat16 g_h2lo[NN * 64];
__device__ float g_agg3[2 * NN * 64];
__device__ float g_el[3 * NN * 2];
__device__ float g_er[3 * NN * 2];
__device__ float g_sinv[3 * NN * 2];
__device__ float g_uv[2 * 64 * 2];
__device__ int g_deg[NN];
__device__ int g_cursor[NN];
__device__ int g_rowptr[NN + 1];
__device__ int g_csrsrc[MAXE];

__device__ __forceinline__ float lrelu(float x, float a) { return x > 0.f ? x : a * x; }

__device__ __forceinline__ uint32_t smem_u32(const void* p) {
    uint32_t a;
    asm("{ .reg .u64 t; cvta.to.shared.u64 t, %1; cvt.u32.u64 %0, t; }" : "=r"(a) : "l"(p));
    return a;
}

// ================= a_hat via mma.sync bf16 hi/lo split (HMMA tensor path) =================
// C[128,128] tile = Ahi*Bhi^T + Ahi*Blo^T + Alo*Bhi^T, K=64.
// 8 warps: warp (wid&3) -> 32 M rows, (wid>>2) -> 64 N cols.
#define APITCH 72                       // bf16 elems per smem row (144B, conflict-free ldmatrix)
#define AHAT_TILE_B (128 * APITCH * 2)  // bytes per tile
#define AHAT_SMEM (4 * AHAT_TILE_B)     // Ahi, Alo, Bhi, Blo = 73728 B

__device__ __forceinline__ void ldm_x4(uint32_t* r, uint32_t addr) {
    asm volatile("ldmatrix.sync.aligned.m8n8.x4.shared.b16 {%0,%1,%2,%3}, [%4];"
                 : "=r"(r[0]), "=r"(r[1]), "=r"(r[2]), "=r"(r[3]) : "r"(addr));
}
__device__ __forceinline__ void mma_bf16(float* c, const uint32_t* a, uint32_t b0, uint32_t b1) {
    asm volatile(
        "mma.sync.aligned.m16n8k16.row.col.f32.bf16.bf16.f32 "
        "{%0,%1,%2,%3}, {%4,%5,%6,%7}, {%8,%9}, {%0,%1,%2,%3};"
        : "+f"(c[0]), "+f"(c[1]), "+f"(c[2]), "+f"(c[3])
        : "r"(a[0]), "r"(a[1]), "r"(a[2]), "r"(a[3]), "r"(b0), "r"(b1));
}

__global__ void __launch_bounds__(256)
ahat_hmma(const __nv_bfloat16* __restrict__ hi, const __nv_bfloat16* __restrict__ lo,
          float* __restrict__ C) {
    extern __shared__ char smem[];
    __nv_bfloat16* sAhi = (__nv_bfloat16*)(smem);
    __nv_bfloat16* sAlo = (__nv_bfloat16*)(smem + AHAT_TILE_B);
    __nv_bfloat16* sBhi = (__nv_bfloat16*)(smem + 2 * AHAT_TILE_B);
    __nv_bfloat16* sBlo = (__nv_bfloat16*)(smem + 3 * AHAT_TILE_B);
    const int tid = threadIdx.x, wid = tid >> 5, lane = tid & 31;
    const int rowBase = blockIdx.y * 128, colBase = blockIdx.x * 128;

    // stage: 128 rows x 64 bf16 (8 x 16B chunks) per tile
    for (int idx = tid; idx < 128 * 8; idx += 256) {
        int row = idx >> 3, ch = idx & 7;
        const uint4* pAhi = (const uint4*)(hi + (size_t)(rowBase + row) * 64) + ch;
        const uint4* pAlo = (const uint4*)(lo + (size_t)(rowBase + row) * 64) + ch;
        const uint4* pBhi = (const uint4*)(hi + (size_t)(colBase + row) * 64) + ch;
        const uint4* pBlo = (const uint4*)(lo + (size_t)(colBase + row) * 64) + ch;
        int off = row * APITCH + ch * 8;
        *(uint4*)(sAhi + off) = *pAhi;
        *(uint4*)(sAlo + off) = *pAlo;
        *(uint4*)(sBhi + off) = *pBhi;
        *(uint4*)(sBlo + off) = *pBlo;
    }
    __syncthreads();

    const int wm = (wid & 3) * 32;   // warp M row base
    const int wn = (wid >> 2) * 64;  // warp N col base

    float acc[2][8][4];
#pragma unroll
    for (int i = 0; i < 2; i++)
#pragma unroll
        for (int j = 0; j < 8; j++)
#pragma unroll
            for (int q = 0; q < 4; q++) acc[i][j][q] = 0.f;

    const int lrow = lane & 15, lch = lane >> 4;
    const uint32_t sbAhi = smem_u32(sAhi), sbAlo = smem_u32(sAlo);
    const uint32_t sbBhi = smem_u32(sBhi), sbBlo = smem_u32(sBlo);

#pragma unroll
    for (int pass = 0; pass < 3; pass++) {
        const uint32_t aBase = (pass == 2) ? sbAlo : sbAhi;
        const uint32_t bBase = (pass == 1) ? sbBlo : sbBhi;
#pragma unroll
        for (int ks = 0; ks < 4; ks++) {
            uint32_t af[2][4];
#pragma unroll
            for (int i = 0; i < 2; i++)
                ldm_x4(af[i], aBase + ((wm + i * 16 + lrow) * APITCH) * 2 + (ks * 2 + lch) * 16);
            uint32_t bf[8][2];
#pragma unroll
            for (int jj = 0; jj < 4; jj++) {
                uint32_t r[4];
                ldm_x4(r, bBase + ((wn + jj * 16 + lrow) * APITCH) * 2 + (ks * 2 + lch) * 16);
                bf[2 * jj][0] = r[0]; bf[2 * jj][1] = r[2];
                bf[2 * jj + 1][0] = r[1]; bf[2 * jj + 1][1] = r[3];
            }
#pragma unroll
            for (int i = 0; i < 2; i++)
#pragma unroll
                for (int j = 0; j < 8; j++)
                    mma_bf16(acc[i][j], af[i], bf[j][0], bf[j][1]);
        }
    }

    // store: thread holds (r0, c0),(r0,c0+1),(r0+8,c0),(r0+8,c0+1) per (i,j)
    const int rr = lane >> 2, cc = (lane & 3) * 2;
#pragma unroll
    for (int i = 0; i < 2; i++) {
        int gr = rowBase + wm + i * 16 + rr;
        float* out0 = C + (size_t)gr * NN + colBase + wn + cc;
        float* out1 = out0 + 8 * NN;
#pragma unroll
        for (int j = 0; j < 8; j++) {
            *(float2*)(out0 + j * 8) = make_float2(acc[i][j][0], acc[i][j][1]);
            *(float2*)(out1 + j * 8) = make_float2(acc[i][j][2], acc[i][j][3]);
        }
    }
}

// ================= CSR build =================
__global__ void k_zerodeg(int* deg) {
    int i = blockIdx.x * blockDim.x + threadIdx.x;
    if (i < NN) deg[i] = 0;
}
__global__ void k_deg(const int* __restrict__ dst, int* deg, int E) {
    int e = blockIdx.x * blockDim.x + threadIdx.x;
    if (e < E) atomicAdd(&deg[dst[e]], 1);
}
__global__ void k_scan(const int* __restrict__ deg, int* rowptr, int* cursor) {
    __shared__ int partx[257];
    int t = threadIdx.x;
    int base = t * 32;
    int loc[32];
    int s = 0;
#pragma unroll
    for (int i = 0; i < 32; i++) { loc[i] = s; s += deg[base + i]; }
    __shared__ int part[256];
    part[t] = s;
    __syncthreads();
    if (t == 0) {
        int acc = 0;
        for (int i = 0; i < 256; i++) { partx[i] = acc; acc += part[i]; }
        partx[256] = acc;
    }
    __syncthreads();
    int off = partx[t];
#pragma unroll
    for (int i = 0; i < 32; i++) {
        int v = off + loc[i];
        rowptr[base + i] = v;
        cursor[base + i] = v;
    }
    if (t == 0) rowptr[NN] = partx[256];
}
__global__ void k_scatter(const int* __restrict__ src, const int* __restrict__ dst,
                          int* cursor, int* csrsrc, int E) {
    int e = blockIdx.x * blockDim.x + threadIdx.x;
    if (e >= E) return;
    int d = dst[e];
    int idx = atomicAdd(&cursor[d], 1);
    csrsrc[idx] = src[e];
}

// ================= repack =================
__global__ void k_pack_feat(const float* __restrict__ feat, float* __restrict__ featp) {
    int n = blockIdx.x;
    for (int f = threadIdx.x; f < FINP; f += blockDim.x)
        featp[(size_t)n * FINP + f] = (f < FIN) ? feat[(size_t)n * FIN + f] : 0.f;
}
__global__ void k_pack_w3(const float* __restrict__ W3, float* __restrict__ p0,
                          float* __restrict__ p1) {
    int k = blockIdx.x;
    for (int f = threadIdx.x; f < FINP; f += blockDim.x) {
        p0[(size_t)k * FINP + f] = (f < FIN) ? W3[(size_t)k * (2 * FIN) + f] : 0.f;
        p1[(size_t)k * FINP + f] = (f < FIN) ? W3[(size_t)k * (2 * FIN) + FIN + f] : 0.f;
    }
}

// ================= SGEMM BM=64 BN=128 BK=16, f32x2, frag double-buffer =================
__global__ void __launch_bounds__(256)
sgemm64(const float* __restrict__ A, const float* __restrict__ B, float* __restrict__ C,
        int M, int Nn, int K, int lda, int ldb, int ldc) {
    __shared__ float As[2][16][68];
    __shared__ float Bs[2][16][128];
    const int tid = threadIdx.x;
    const int tx = tid & 15, ty = tid >> 4;
    const int rowBase = blockIdx.y * 64;
    const int colBase = blockIdx.x * 128;

    const int am = tid >> 2, akc = tid & 3;
    const int bn4 = tid & 31, bk = tid >> 5;

    const int nk = (K + 15) >> 4;

    u64t acc[4][4];
#pragma unroll
    for (int i = 0; i < 4; i++)
#pragma unroll
        for (int p = 0; p < 4; p++) acc[i][p] = 0ULL;

#define LD4A(dst, gk)                                                   \
    {                                                                   \
        int _gk = (gk);                                                 \
        const float* _p = A + (size_t)(rowBase + am) * lda + _gk;       \
        if (_gk + 3 < K) dst = *(const float4*)_p;                      \
        else {                                                          \
            dst.x = (_gk + 0 < K) ? _p[0] : 0.f;                        \
            dst.y = (_gk + 1 < K) ? _p[1] : 0.f;                        \
            dst.z = (_gk + 2 < K) ? _p[2] : 0.f;                        \
            dst.w = (_gk + 3 < K) ? _p[3] : 0.f;                        \
        }                                                               \
    }
#define LD4B(dst, gk, gn)                                               \
    {                                                                   \
        int _gk = (gk), _gn = (gn);                                     \
        const float* _p = B + (size_t)_gk * ldb + _gn;                  \
        if (_gk < K && _gn + 3 < Nn) dst = *(const float4*)_p;          \
        else {                                                          \
            dst.x = (_gk < K && _gn + 0 < Nn) ? _p[0] : 0.f;            \
            dst.y = (_gk < K && _gn + 1 < Nn) ? _p[1] : 0.f;            \
            dst.z = (_gk < K && _gn + 2 < Nn) ? _p[2] : 0.f;            \
            dst.w = (_gk < K && _gn + 3 < Nn) ? _p[3] : 0.f;            \
        }                                                               \
    }
#define STAGE(buf, ra, rb0, rb1)                                        \
    {                                                                   \
        As[buf][akc * 4 + 0][am] = ra.x;                                \
        As[buf][akc * 4 + 1][am] = ra.y;                                \
        As[buf][akc * 4 + 2][am] = ra.z;                                \
        As[buf][akc * 4 + 3][am] = ra.w;                                \
        *(float4*)&Bs[buf][bk][bn4 * 4] = rb0;                          \
        *(float4*)&Bs[buf][bk + 8][bn4 * 4] = rb1;                      \
    }

    {
        float4 ra, rb0, rb1;
        LD4A(ra, akc * 4);
        LD4B(rb0, bk, colBase + bn4 * 4);
        LD4B(rb1, bk + 8, colBase + bn4 * 4);
        STAGE(0, ra, rb0, rb1);
    }
    __syncthreads();

    for (int t = 0; t < nk; ++t) {
        const int buf = t & 1;
        const bool more = (t + 1 < nk);
        float4 ra, rb0, rb1;
        if (more) {
            int k0 = (t + 1) * 16;
            LD4A(ra, k0 + akc * 4);
            LD4B(rb0, k0 + bk, colBase + bn4 * 4);
            LD4B(rb1, k0 + bk + 8, colBase + bn4 * 4);
        }

        float af[2][4];
        u64t bf[2][4];
        {
            float4 a4 = *(const float4*)&As[buf][0][ty * 4];
            af[0][0] = a4.x; af[0][1] = a4.y; af[0][2] = a4.z; af[0][3] = a4.w;
            float4 b40 = *(const float4*)&Bs[buf][0][tx * 8];
            float4 b41 = *(const float4*)&Bs[buf][0][tx * 8 + 4];
            bf[0][0] = ((u64t*)&b40)[0]; bf[0][1] = ((u64t*)&b40)[1];
            bf[0][2] = ((u64t*)&b41)[0]; bf[0][3] = ((u64t*)&b41)[1];
        }
#pragma unroll
        for (int k = 0; k < 16; k++) {
            const int cur = k & 1;
            if (k < 15) {
                float4 a4 = *(const float4*)&As[buf][k + 1][ty * 4];
                af[cur ^ 1][0] = a4.x; af[cur ^ 1][1] = a4.y;
                af[cur ^ 1][2] = a4.z; af[cur ^ 1][3] = a4.w;
                float4 b40 = *(const float4*)&Bs[buf][k + 1][tx * 8];
                float4 b41 = *(const float4*)&Bs[buf][k + 1][tx * 8 + 4];
                bf[cur ^ 1][0] = ((u64t*)&b40)[0]; bf[cur ^ 1][1] = ((u64t*)&b40)[1];
                bf[cur ^ 1][2] = ((u64t*)&b41)[0]; bf[cur ^ 1][3] = ((u64t*)&b41)[1];
            }
#pragma unroll
            for (int i = 0; i < 4; i++) {
                u64t a2;
                asm("mov.b64 %0, {%1, %1};" : "=l"(a2) : "f"(af[cur][i]));
#pragma unroll
                for (int p = 0; p < 4; p++)
                    asm("fma.rn.f32x2 %0, %1, %2, %0;"
                        : "+l"(acc[i][p]) : "l"(a2), "l"(bf[cur][p]));
            }
        }
        if (more) { STAGE(buf ^ 1, ra, rb0, rb1); }
        __syncthreads();
    }

#pragma unroll
    for (int i = 0; i < 4; i++) {
        int gm = rowBase + ty * 4 + i;
#pragma unroll
        for (int p = 0; p < 4; p++) {
            float lo, hi;
            asm("mov.b64 {%0, %1}, %2;" : "=f"(lo), "=f"(hi) : "l"(acc[i][p]));
            int gn = colBase + tx * 8 + 2 * p;
            if (gn < Nn) C[(size_t)gm * ldc + gn] = lo;
            if (gn + 1 < Nn) C[(size_t)gm * ldc + gn + 1] = hi;
        }
    }
#undef LD4A
#undef LD4B
#undef STAGE
}

// ================= fused attribute-decoder GEMM (both heads + bias + lrelu + mean) =====
__global__ void __launch_bounds__(256)
dec_gemm(const float* __restrict__ agg3, const float* __restrict__ B0,
         const float* __restrict__ B1, const float* __restrict__ b3,
         float* __restrict__ xhat) {
    __shared__ float As[16][68];
    __shared__ float Bs[16][128];
    const int tid = threadIdx.x;
    const int tx = tid & 15, ty = tid >> 4;
    const int rowBase = blockIdx.y * 64;
    const int colBase = blockIdx.x * 128;
    const int am = tid >> 2, akc = tid & 3;
    const int bn4 = tid & 31, bk = tid >> 5;

    u64t acc[2][4][4];
#pragma unroll
    for (int h = 0; h < 2; h++)
#pragma unroll
        for (int i = 0; i < 4; i++)
#pragma unroll
            for (int p = 0; p < 4; p++) acc[h][i][p] = 0ULL;

    for (int c = 0; c < 8; c++) {
        const int head = c >> 2;
        const int kc = (c & 3) * 16;
        const float* A = agg3 + (size_t)head * NN * 64;
        const float* B = head ? B1 : B0;
        __syncthreads();
        {
            float4 ra = *(const float4*)(A + (size_t)(rowBase + am) * 64 + kc + akc * 4);
            As[akc * 4 + 0][am] = ra.x;
            As[akc * 4 + 1][am] = ra.y;
            As[akc * 4 + 2][am] = ra.z;
            As[akc * 4 + 3][am] = ra.w;
        }
#pragma unroll
        for (int rr = 0; rr < 2; rr++) {
            int r = bk + rr * 8;
            int gn = colBase + bn4 * 4;
            const float* p = B + (size_t)(kc + r) * FINP + gn;
            float4 rb;
            if (gn + 3 < FINP) rb = *(const float4*)p;
            else {
                rb.x = (gn + 0 < FINP) ? p[0] : 0.f;
                rb.y = (gn + 1 < FINP) ? p[1] : 0.f;
                rb.z = (gn + 2 < FINP) ? p[2] : 0.f;
                rb.w = (gn + 3 < FINP) ? p[3] : 0.f;
            }
            *(float4*)&Bs[r][bn4 * 4] = rb;
        }
        __syncthreads();
#pragma unroll
        for (int k = 0; k < 16; k++) {
            float4 a4 = *(const float4*)&As[k][ty * 4];
            float av[4] = {a4.x, a4.y, a4.z, a4.w};
            float4 b40 = *(const float4*)&Bs[k][tx * 8];
            float4 b41 = *(const float4*)&Bs[k][tx * 8 + 4];
            u64t b2[4];
            b2[0] = ((u64t*)&b40)[0]; b2[1] = ((u64t*)&b40)[1];
            b2[2] = ((u64t*)&b41)[0]; b2[3] = ((u64t*)&b41)[1];
#pragma unroll
            for (int i = 0; i < 4; i++) {
                u64t a2;
                asm("mov.b64 %0, {%1, %1};" : "=l"(a2) : "f"(av[i]));
#pragma unroll
                for (int p = 0; p < 4; p++)
                    asm("fma.rn.f32x2 %0, %1, %2, %0;"
                        : "+l"(acc[head][i][p]) : "l"(a2), "l"(b2[p]));
            }
        }
    }

#pragma unroll
    for (int i = 0; i < 4; i++) {
        int gm = rowBase + ty * 4 + i;
#pragma unroll
        for (int p = 0; p < 4; p++) {
            float l0, h0, l1, h1;
            asm("mov.b64 {%0, %1}, %2;" : "=f"(l0), "=f"(h0) : "l"(acc[0][i][p]));
            asm("mov.b64 {%0, %1}, %2;" : "=f"(l1), "=f"(h1) : "l"(acc[1][i][p]));
            int gn = colBase + tx * 8 + 2 * p;
            if (gn < FIN)
                xhat[(size_t)gm * FIN + gn] =
                    0.5f * (lrelu(l0 + b3[gn], 0.01f) + lrelu(l1 + b3[FIN + gn], 0.01f));
            if (gn + 1 < FIN)
                xhat[(size_t)gm * FIN + gn + 1] =
                    0.5f * (lrelu(h0 + b3[gn + 1], 0.01f) + lrelu(h1 + b3[FIN + gn + 1], 0.01f));
        }
    }
}

// ================= attention logits =================
__global__ void k_elr(const float* __restrict__ hp, const float* __restrict__ al,
                      const float* __restrict__ ar, float* el, float* er, int D) {
    int w = (blockIdx.x * blockDim.x + threadIdx.x) >> 5;
    int lane = threadIdx.x & 31;
    if (w >= NN * 2) return;
    int n = w >> 1, h = w & 1;
    const float* row = hp + (size_t)n * (2 * D) + h * D;
    const float* a = al + h * D;
    const float* b = ar + h * D;
    float sl = 0.f, sr = 0.f;
    for (int d = lane; d < D; d += 32) { float x = row[d]; sl += x * a[d]; sr += x * b[d]; }
#pragma unroll
    for (int o = 16; o; o >>= 1) {
        sl += __shfl_down_sync(0xffffffffu, sl, o);
        sr += __shfl_down_sync(0xffffffffu, sr, o);
    }
    if (lane == 0) { el[w] = sl; er[w] = sr; }
}

__global__ void k_uv(const float* __restrict__ W3, const float* __restrict__ al3,
                     const float* __restrict__ ar3, float* uv) {
    int w = (blockIdx.x * blockDim.x + threadIdx.x) >> 5;
    int lane = threadIdx.x & 31;
    if (w >= 128) return;
    int h = w >> 6, k = w & 63;
    const float* Wr = W3 + (size_t)k * (2 * FIN) + h * FIN;
    const float* a = al3 + (size_t)h * FIN;
    const float* b = ar3 + (size_t)h * FIN;
    float su = 0.f, sv = 0.f;
    for (int f = lane; f < FIN; f += 32) { float ww = Wr[f]; su += ww * a[f]; sv += ww * b[f]; }
#pragma unroll
    for (int o = 16; o; o >>= 1) {
        su += __shfl_down_sync(0xffffffffu, su, o);
        sv += __shfl_down_sync(0xffffffffu, sv, o);
    }
    if (lane == 0) { uv[h * 64 + k] = su; uv[128 + h * 64 + k] = sv; }
}

__global__ void k_elr3(const float* __restrict__ h2, const float* __restrict__ uv,
                       float* el, float* er) {
    int w = (blockIdx.x * blockDim.x + threadIdx.x) >> 5;
    int lane = threadIdx.x & 31;
    if (w >= NN * 2) return;
    int n = w >> 1, h = w & 1;
    const float* row = h2 + (size_t)n * 64;
    const float* u = uv + h * 64;
    const float* v = uv + 128 + h * 64;
    float sl = 0.f, sr = 0.f;
    for (int d = lane; d < 64; d += 32) { float x = row[d]; sl += x * u[d]; sr += x * v[d]; }
#pragma unroll
    for (int o = 16; o; o >>= 1) {
        sl += __shfl_down_sync(0xffffffffu, sl, o);
        sr += __shfl_down_sync(0xffffffffu, sr, o);
    }
    if (lane == 0) { el[w] = sl; er[w] = sr; }
}

// ================= CSR softmax denominators =================
__global__ void k_sum(const int* __restrict__ rowptr, const int* __restrict__ csrsrc,
                      const float* __restrict__ el, const float* __restrict__ er,
                      float* __restrict__ sinv) {
    int d = blockIdx.x * (blockDim.x >> 5) + (threadIdx.x >> 5);
    int lane = threadIdx.x & 31;
    if (d >= NN) return;
    int b = rowptr[d], e = rowptr[d + 1];
    float2 r = *(const float2*)&er[d * 2];
    float s0 = 0.f, s1 = 0.f;
    for (int i = b + lane; i < e; i += 32) {
        int s = csrsrc[i];
        float2 l = *(const float2*)&el[s * 2];
        float e0 = l.x + r.x; e0 = e0 > 0.f ? e0 : 0.2f * e0;
        float e1 = l.y + r.y; e1 = e1 > 0.f ? e1 : 0.2f * e1;
        s0 += __expf(e0); s1 += __expf(e1);
    }
#pragma unroll
    for (int o = 16; o; o >>= 1) {
        s0 += __shfl_down_sync(0xffffffffu, s0, o);
        s1 += __shfl_down_sync(0xffffffffu, s1, o);
    }
    if (lane == 0) { sinv[d * 2] = 1.f / s0; sinv[d * 2 + 1] = 1.f / s1; }
}

// ================= CSR gather aggregation =================
__global__ void __launch_bounds__(256)
k_agg1(const int* __restrict__ rowptr, const int* __restrict__ csrsrc,
       const float* __restrict__ el, const float* __restrict__ er,
       const float* __restrict__ sinv, const float* __restrict__ hp,
       const float* __restrict__ b1, float* __restrict__ out) {
    int d = blockIdx.x;
    int t = threadIdx.x;
    __shared__ float2 sal[128];
    __shared__ int ssrc[128];
    int b = rowptr[d], en = rowptr[d + 1];
    float2 r = *(const float2*)&er[d * 2];
    float2 inv = *(const float2*)&sinv[d * 2];
    float acc = 0.f;
    int h = t >> 7;
    for (int c = b; c < en; c += 128) {
        int cnt = min(128, en - c);
        __syncthreads();
        if (t < cnt) {
            int s = csrsrc[c + t];
            float2 l = *(const float2*)&el[s * 2];
            float e0 = l.x + r.x; e0 = e0 > 0.f ? e0 : 0.2f * e0;
            float e1 = l.y + r.y; e1 = e1 > 0.f ? e1 : 0.2f * e1;
            sal[t] = make_float2(__expf(e0) * inv.x, __expf(e1) * inv.y);
            ssrc[t] = s;
        }
        __syncthreads();
#pragma unroll 4
        for (int i = 0; i < cnt; i++) {
            float a = h ? sal[i].y : sal[i].x;
            acc = fmaf(a, hp[(size_t)ssrc[i] * 256 + t], acc);
        }
    }
    float x = acc + b1[t];
    out[(size_t)d * 256 + t] = lrelu(x, 0.01f);
}

__global__ void __launch_bounds__(128)
k_agg2(const int* __restrict__ rowptr, const int* __restrict__ csrsrc,
       const float* __restrict__ el, const float* __restrict__ er,
       const float* __restrict__ sinv, const float* __restrict__ hp,
       const float* __restrict__ b2, float* __restrict__ h2,
       __nv_bfloat16* __restrict__ h2hi, __nv_bfloat16* __restrict__ h2lo) {
    int d = blockIdx.x;
    int t = threadIdx.x;
    __shared__ float2 sal[128];
    __shared__ int ssrc[128];
    __shared__ float o[128];
    int b = rowptr[d], en = rowptr[d + 1];
    float2 r = *(const float2*)&er[d * 2];
    float2 inv = *(const float2*)&sinv[d * 2];
    float acc = 0.f;
    int h = t >> 6;
    for (int c = b; c < en; c += 128) {
        int cnt = min(128, en - c);
        __syncthreads();
        if (t < cnt) {
            int s = csrsrc[c + t];
            float2 l = *(const float2*)&el[s * 2];
            float e0 = l.x + r.x; e0 = e0 > 0.f ? e0 : 0.2f * e0;
            float e1 = l.y + r.y; e1 = e1 > 0.f ? e1 : 0.2f * e1;
            sal[t] = make_float2(__expf(e0) * inv.x, __expf(e1) * inv.y);
            ssrc[t] = s;
        }
        __syncthreads();
#pragma unroll 4
        for (int i = 0; i < cnt; i++) {
            float a = h ? sal[i].y : sal[i].x;
            acc = fmaf(a, hp[(size_t)ssrc[i] * 128 + t], acc);
        }
    }
    o[t] = acc;
    __syncthreads();
    if (t < 64) {
        float x0 = lrelu(o[t] + b2[t], 0.01f);
        float x1 = lrelu(o[64 + t] + b2[64 + t], 0.01f);
        float v = 0.5f * (x0 + x1);
        h2[(size_t)d * 64 + t] = v;
        __nv_bfloat16 vh = __float2bfloat16(v);
        h2hi[(size_t)d * 64 + t] = vh;
        h2lo[(size_t)d * 64 + t] = __float2bfloat16(v - __bfloat162float(vh));
    }
}

__global__ void __launch_bounds__(128)
k_agg3(const int* __restrict__ rowptr, const int* __restrict__ csrsrc,
       const float* __restrict__ el, const float* __restrict__ er,
       const float* __restrict__ sinv, const float* __restrict__ h2,
       float* __restrict__ agg3) {
    int d = blockIdx.x;
    int t = threadIdx.x;
    __shared__ float2 sal[128];
    __shared__ int ssrc[128];
    int b = rowptr[d], en = rowptr[d + 1];
    float2 r = *(const float2*)&er[d * 2];
    float2 inv = *(const float2*)&sinv[d * 2];
    float acc = 0.f;
    int h = t >> 6, dd = t & 63;
    for (int c = b; c < en; c += 128) {
        int cnt = min(128, en - c);
        __syncthreads();
        if (t < cnt) {
            int s = csrsrc[c + t];
            float2 l = *(const float2*)&el[s * 2];
            float e0 = l.x + r.x; e0 = e0 > 0.f ? e0 : 0.2f * e0;
            float e1 = l.y + r.y; e1 = e1 > 0.f ? e1 : 0.2f * e1;
            sal[t] = make_float2(__expf(e0) * inv.x, __expf(e1) * inv.y);
            ssrc[t] = s;
        }
        __syncthreads();
#pragma unroll 4
        for (int i = 0; i < cnt; i++) {
            float a = h ? sal[i].y : sal[i].x;
            acc = fmaf(a, h2[(size_t)ssrc[i] * 64 + dd], acc);
        }
    }
    agg3[((size_t)h * NN + d) * 64 + dd] = acc;
}

// ================= launch =================
extern "C" void kernel_launch(void* const* d_in, const int* in_sizes, int n_in,
                              void* d_out, int out_size) {
    const float* feat = (const float*)d_in[0];
    const int* src = (const int*)d_in[1];
    const int* dst = (const int*)d_in[2];
    const float* W1 = (const float*)d_in[3];
    const float* al1 = (const float*)d_in[4];
    const float* ar1 = (const float*)d_in[5];
    const float* b1 = (const float*)d_in[6];
    const float* W2 = (const float*)d_in[7];
    const float* al2 = (const float*)d_in[8];
    const float* ar2 = (const float*)d_in[9];
    const float* b2 = (const float*)d_in[10];
    const float* W3 = (const float*)d_in[11];
    const float* al3 = (const float*)d_in[12];
    const float* ar3 = (const float*)d_in[13];
    const float* b3 = (const float*)d_in[14];

    float* a_hat = (float*)d_out;
    float* x_hat = a_hat + (size_t)NN * NN;
    const int E = in_sizes[1];

    float *featp, *w3p0, *w3p1, *h1p, *agg1, *h2p, *h2, *agg3, *el, *er, *sinv, *uv;
    __nv_bfloat16 *h2hi, *h2lo;
    int *deg, *cursor, *rowptr, *csrsrc;
    cudaGetSymbolAddress((void**)&featp, g_featp);
    cudaGetSymbolAddress((void**)&w3p0, g_w3p0);
    cudaGetSymbolAddress((void**)&w3p1, g_w3p1);
    cudaGetSymbolAddress((void**)&h1p, g_h1p);
    cudaGetSymbolAddress((void**)&agg1, g_agg1);
    cudaGetSymbolAddress((void**)&h2p, g_h2p);
    cudaGetSymbolAddress((void**)&h2, g_h2);
    cudaGetSymbolAddress((void**)&h2hi, g_h2hi);
    cudaGetSymbolAddress((void**)&h2lo, g_h2lo);
    cudaGetSymbolAddress((void**)&agg3, g_agg3);
    cudaGetSymbolAddress((void**)&el, g_el);
    cudaGetSymbolAddress((void**)&er, g_er);
    cudaGetSymbolAddress((void**)&sinv, g_sinv);
    cudaGetSymbolAddress((void**)&uv, g_uv);
    cudaGetSymbolAddress((void**)&deg, g_deg);
    cudaGetSymbolAddress((void**)&cursor, g_cursor);
    cudaGetSymbolAddress((void**)&rowptr, g_rowptr);
    cudaGetSymbolAddress((void**)&csrsrc, g_csrsrc);

    cudaFuncSetAttribute(ahat_hmma, cudaFuncAttributeMaxDynamicSharedMemorySize, AHAT_SMEM);

    float *el1 = el, *el2 = el + NN * 2, *el3 = el + 2 * NN * 2;
    float *er1 = er, *er2 = er + NN * 2, *er3 = er + 2 * NN * 2;
    float *s1 = sinv, *s2 = sinv + NN * 2, *s3 = sinv + 2 * NN * 2;

    const int eb = (E + 255) / 256;

    // ---- CSR build ----
    k_zerodeg<<<(NN + 255) / 256, 256>>>(deg);
    k_deg<<<eb, 256>>>(dst, deg, E);
    k_scan<<<1, 256>>>(deg, rowptr, cursor);
    k_scatter<<<eb, 256>>>(src, dst, cursor, csrsrc, E);

    // ---- repack ----
    k_pack_feat<<<NN, 256>>>(feat, featp);
    k_pack_w3<<<64, 256>>>(W3, w3p0, w3p1);

    // ---- layer 1 ----
    {
        dim3 grid(2, 128);
        sgemm64<<<grid, 256>>>(featp, W1, h1p, NN, 256, FIN, FINP, 256, 256);
    }
    k_elr<<<(NN * 2 * 32 + 255) / 256, 256>>>(h1p, al1, ar1, el1, er1, 128);
    k_sum<<<NN / 8, 256>>>(rowptr, csrsrc, el1, er1, s1);
    k_agg1<<<NN, 256>>>(rowptr, csrsrc, el1, er1, s1, h1p, b1, agg1);

    // ---- layer 2 ----
    {
        dim3 grid(1, 128);
        sgemm64<<<grid, 256>>>(agg1, W2, h2p, NN, 128, 256, 256, 128, 128);
    }
    k_elr<<<(NN * 2 * 32 + 255) / 256, 256>>>(h2p, al2, ar2, el2, er2, 64);
    k_sum<<<NN / 8, 256>>>(rowptr, csrsrc, el2, er2, s2);
    k_agg2<<<NN, 128>>>(rowptr, csrsrc, el2, er2, s2, h2p, b2, h2, h2hi, h2lo);

    // ---- structure decoder: a_hat = h2 @ h2^T via bf16-split HMMA ----
    {
        dim3 grid(NN / 128, NN / 128);
        ahat_hmma<<<grid, 256, AHAT_SMEM>>>(h2hi, h2lo, a_hat);
    }

    // ---- attribute decoder ----
    k_uv<<<16, 256>>>(W3, al3, ar3, uv);
    k_elr3<<<(NN * 2 * 32 + 255) / 256, 256>>>(h2, uv, el3, er3);
    k_sum<<<NN / 8, 256>>>(rowptr, csrsrc, el3, er3, s3);
    k_agg3<<<NN, 128>>>(rowptr, csrsrc, el3, er3, s3, h2, agg3);
    {
        dim3 grid(12, 128);
        dec_gemm<<<grid, 256>>>(agg3, w3p0, w3p1, b3, x_hat);
    }
}

// round 6
// speedup vs baseline: 3.3888x; 1.5666x over previous
#include <cuda_runtime.h>
#include <cuda_bf16.h>
#include <cstdint>

#define NN 8192
#define FIN 1433
#define FINB 1472      // FIN padded to multiple of 64
#define NDEC 1536      // decoder N padded to multiple of 64
#define MAXE (1 << 20)

typedef unsigned long long u64t;
typedef __nv_bfloat16 bf16;

// ---------------- scratch (device globals) ----------------
__device__ bf16 g_feathi[NN * FINB];
__device__ bf16 g_featlo[NN * FINB];
__device__ bf16 g_w1thi[256 * FINB];
__device__ bf16 g_w1tlo[256 * FINB];
__device__ bf16 g_w2thi[128 * 256];
__device__ bf16 g_w2tlo[128 * 256];
__device__ bf16 g_w3thi[2 * NDEC * 64];
__device__ bf16 g_w3tlo[2 * NDEC * 64];
__device__ float g_h1p[NN * 256];
__device__ bf16 g_agg1hi[NN * 256];
__device__ bf16 g_agg1lo[NN * 256];
__device__ float g_h2p[NN * 128];
__device__ float g_h2[NN * 64];
__device__ bf16 g_h2hi[NN * 64];
__device__ bf16 g_h2lo[NN * 64];
__device__ bf16 g_agg3hi[2 * NN * 64];
__device__ bf16 g_agg3lo[2 * NN * 64];
__device__ float g_el[3 * NN * 2];
__device__ float g_er[3 * NN * 2];
__device__ float g_sinv[3 * NN * 2];
__device__ float g_uv[2 * 64 * 2];
__device__ int g_deg[NN];
__device__ int g_cursor[NN];
__device__ int g_rowptr[NN + 1];
__device__ int g_csrsrc[MAXE];

__device__ __forceinline__ float lrelu(float x, float a) { return x > 0.f ? x : a * x; }

__device__ __forceinline__ uint32_t smem_u32(const void* p) {
    uint32_t a;
    asm("{ .reg .u64 t; cvta.to.shared.u64 t, %1; cvt.u32.u64 %0, t; }" : "=r"(a) : "l"(p));
    return a;
}
__device__ __forceinline__ void ldm_x4(uint32_t* r, uint32_t addr) {
    asm volatile("ldmatrix.sync.aligned.m8n8.x4.shared.b16 {%0,%1,%2,%3}, [%4];"
                 : "=r"(r[0]), "=r"(r[1]), "=r"(r[2]), "=r"(r[3]) : "r"(addr));
}
__device__ __forceinline__ void mma_bf16(float* c, const uint32_t* a, uint32_t b0, uint32_t b1) {
    asm volatile(
        "mma.sync.aligned.m16n8k16.row.col.f32.bf16.bf16.f32 "
        "{%0,%1,%2,%3}, {%4,%5,%6,%7}, {%8,%9}, {%0,%1,%2,%3};"
        : "+f"(c[0]), "+f"(c[1]), "+f"(c[2]), "+f"(c[3])
        : "r"(a[0]), "r"(a[1]), "r"(a[2]), "r"(a[3]), "r"(b0), "r"(b1));
}
__device__ __forceinline__ void split_bf16(float v, bf16* hi, bf16* lo) {
    bf16 h = __float2bfloat16(v);
    *hi = h;
    *lo = __float2bfloat16(v - __bfloat162float(h));
}

#define APITCH 72  // bf16 per smem row (144B) — conflict-free ldmatrix

// ================= generic bf16-split HMMA GEMM =================
// C[M,N] = Ahi*Bhi^T + Ahi*Blo^T + Alo*Bhi^T ; A [M,K] rows, B [N,K] rows.
// CTA tile 128x128, 8 warps (4M x 2N) each 32x64. K multiple of 64. M,N mult of 128.
#define HG_SMEM (4 * 128 * APITCH * 2)  // 73728 B

__global__ void __launch_bounds__(256)
hmma_gemm(const bf16* __restrict__ Ahi, const bf16* __restrict__ Alo,
          const bf16* __restrict__ Bhi, const bf16* __restrict__ Blo,
          float* __restrict__ C, int K, int lda, int ldb, int ldc) {
    extern __shared__ char smem[];
    bf16* sAhi = (bf16*)smem;
    bf16* sAlo = (bf16*)(smem + 18432);
    bf16* sBhi = (bf16*)(smem + 36864);
    bf16* sBlo = (bf16*)(smem + 55296);
    const int tid = threadIdx.x, wid = tid >> 5, lane = tid & 31;
    const int rowBase = blockIdx.y * 128, colBase = blockIdx.x * 128;
    const int wm = (wid & 3) * 32, wn = (wid >> 2) * 64;
    const int lrow = lane & 15, lch = lane >> 4;

    float acc[2][8][4];
#pragma unroll
    for (int i = 0; i < 2; i++)
#pragma unroll
        for (int j = 0; j < 8; j++)
#pragma unroll
            for (int q = 0; q < 4; q++) acc[i][j][q] = 0.f;

    const uint32_t sbAhi = smem_u32(sAhi), sbAlo = smem_u32(sAlo);
    const uint32_t sbBhi = smem_u32(sBhi), sbBlo = smem_u32(sBlo);

    for (int kc = 0; kc < K; kc += 64) {
        for (int idx = tid; idx < 1024; idx += 256) {
            int row = idx >> 3, ch = idx & 7;
            int off = row * APITCH + ch * 8;
            *(uint4*)(sAhi + off) = *(const uint4*)(Ahi + (size_t)(rowBase + row) * lda + kc + ch * 8);
            *(uint4*)(sAlo + off) = *(const uint4*)(Alo + (size_t)(rowBase + row) * lda + kc + ch * 8);
            *(uint4*)(sBhi + off) = *(const uint4*)(Bhi + (size_t)(colBase + row) * ldb + kc + ch * 8);
            *(uint4*)(sBlo + off) = *(const uint4*)(Blo + (size_t)(colBase + row) * ldb + kc + ch * 8);
        }
        __syncthreads();
#pragma unroll
        for (int ks = 0; ks < 4; ks++) {
            uint32_t afh[2][4], afl[2][4];
#pragma unroll
            for (int i = 0; i < 2; i++) {
                uint32_t ao = ((wm + i * 16 + lrow) * APITCH) * 2 + (ks * 2 + lch) * 16;
                ldm_x4(afh[i], sbAhi + ao);
                ldm_x4(afl[i], sbAlo + ao);
            }
            uint32_t bfh[8][2], bfl[8][2];
#pragma unroll
            for (int jj = 0; jj < 4; jj++) {
                uint32_t bo = ((wn + jj * 16 + lrow) * APITCH) * 2 + (ks * 2 + lch) * 16;
                uint32_t r[4];
                ldm_x4(r, sbBhi + bo);
                bfh[2 * jj][0] = r[0]; bfh[2 * jj][1] = r[2];
                bfh[2 * jj + 1][0] = r[1]; bfh[2 * jj + 1][1] = r[3];
                ldm_x4(r, sbBlo + bo);
                bfl[2 * jj][0] = r[0]; bfl[2 * jj][1] = r[2];
                bfl[2 * jj + 1][0] = r[1]; bfl[2 * jj + 1][1] = r[3];
            }
#pragma unroll
            for (int i = 0; i < 2; i++)
#pragma unroll
                for (int j = 0; j < 8; j++) {
                    mma_bf16(acc[i][j], afh[i], bfh[j][0], bfh[j][1]);
                    mma_bf16(acc[i][j], afh[i], bfl[j][0], bfl[j][1]);
                    mma_bf16(acc[i][j], afl[i], bfh[j][0], bfh[j][1]);
                }
        }
        __syncthreads();
    }

    const int rr = lane >> 2, cc = (lane & 3) * 2;
#pragma unroll
    for (int i = 0; i < 2; i++) {
        int gr = rowBase + wm + i * 16 + rr;
        float* out0 = C + (size_t)gr * ldc + colBase + wn + cc;
        float* out1 = out0 + 8 * ldc;
#pragma unroll
        for (int j = 0; j < 8; j++) {
            *(float2*)(out0 + j * 8) = make_float2(acc[i][j][0], acc[i][j][1]);
            *(float2*)(out1 + j * 8) = make_float2(acc[i][j][2], acc[i][j][3]);
        }
    }
}

// ================= a_hat HMMA (unchanged from r5, 128x128, K=64) =================
#define AHAT_TILE_B (128 * APITCH * 2)
#define AHAT_SMEM (4 * AHAT_TILE_B)

__global__ void __launch_bounds__(256)
ahat_hmma(const bf16* __restrict__ hi, const bf16* __restrict__ lo, float* __restrict__ C) {
    extern __shared__ char smem[];
    bf16* sAhi = (bf16*)(smem);
    bf16* sAlo = (bf16*)(smem + AHAT_TILE_B);
    bf16* sBhi = (bf16*)(smem + 2 * AHAT_TILE_B);
    bf16* sBlo = (bf16*)(smem + 3 * AHAT_TILE_B);
    const int tid = threadIdx.x, wid = tid >> 5, lane = tid & 31;
    const int rowBase = blockIdx.y * 128, colBase = blockIdx.x * 128;

    for (int idx = tid; idx < 128 * 8; idx += 256) {
        int row = idx >> 3, ch = idx & 7;
        int off = row * APITCH + ch * 8;
        *(uint4*)(sAhi + off) = *((const uint4*)(hi + (size_t)(rowBase + row) * 64) + ch);
        *(uint4*)(sAlo + off) = *((const uint4*)(lo + (size_t)(rowBase + row) * 64) + ch);
        *(uint4*)(sBhi + off) = *((const uint4*)(hi + (size_t)(colBase + row) * 64) + ch);
        *(uint4*)(sBlo + off) = *((const uint4*)(lo + (size_t)(colBase + row) * 64) + ch);
    }
    __syncthreads();

    const int wm = (wid & 3) * 32, wn = (wid >> 2) * 64;
    float acc[2][8][4];
#pragma unroll
    for (int i = 0; i < 2; i++)
#pragma unroll
        for (int j = 0; j < 8; j++)
#pragma unroll
            for (int q = 0; q < 4; q++) acc[i][j][q] = 0.f;

    const int lrow = lane & 15, lch = lane >> 4;
    const uint32_t sbAhi = smem_u32(sAhi), sbAlo = smem_u32(sAlo);
    const uint32_t sbBhi = smem_u32(sBhi), sbBlo = smem_u32(sBlo);

#pragma unroll
    for (int pass = 0; pass < 3; pass++) {
        const uint32_t aBase = (pass == 2) ? sbAlo : sbAhi;
        const uint32_t bBase = (pass == 1) ? sbBlo : sbBhi;
#pragma unroll
        for (int ks = 0; ks < 4; ks++) {
            uint32_t af[2][4];
#pragma unroll
            for (int i = 0; i < 2; i++)
                ldm_x4(af[i], aBase + ((wm + i * 16 + lrow) * APITCH) * 2 + (ks * 2 + lch) * 16);
            uint32_t bf[8][2];
#pragma unroll
            for (int jj = 0; jj < 4; jj++) {
                uint32_t r[4];
                ldm_x4(r, bBase + ((wn + jj * 16 + lrow) * APITCH) * 2 + (ks * 2 + lch) * 16);
                bf[2 * jj][0] = r[0]; bf[2 * jj][1] = r[2];
                bf[2 * jj + 1][0] = r[1]; bf[2 * jj + 1][1] = r[3];
            }
#pragma unroll
            for (int i = 0; i < 2; i++)
#pragma unroll
                for (int j = 0; j < 8; j++)
                    mma_bf16(acc[i][j], af[i], bf[j][0], bf[j][1]);
        }
    }

    const int rr = lane >> 2, cc = (lane & 3) * 2;
#pragma unroll
    for (int i = 0; i < 2; i++) {
        int gr = rowBase + wm + i * 16 + rr;
        float* out0 = C + (size_t)gr * NN + colBase + wn + cc;
        float* out1 = out0 + 8 * NN;
#pragma unroll
        for (int j = 0; j < 8; j++) {
            *(float2*)(out0 + j * 8) = make_float2(acc[i][j][0], acc[i][j][1]);
            *(float2*)(out1 + j * 8) = make_float2(acc[i][j][2], acc[i][j][3]);
        }
    }
}

// ================= fused decoder HMMA (2 heads + bias + lrelu + mean) =================
// CTA tile 128M x 64N, 8 warps (4M x 2N) each 32x32. K=64.
#define DEC_SMEM (2 * 128 * APITCH * 2 + 2 * 64 * APITCH * 2)  // 55296 B

__global__ void __launch_bounds__(256)
dec_hmma(const bf16* __restrict__ Ahi, const bf16* __restrict__ Alo,
         const bf16* __restrict__ Bhi, const bf16* __restrict__ Blo,
         const float* __restrict__ b3, float* __restrict__ xhat) {
    extern __shared__ char smem[];
    bf16* sAhi = (bf16*)smem;
    bf16* sAlo = (bf16*)(smem + 18432);
    bf16* sBhi = (bf16*)(smem + 36864);
    bf16* sBlo = (bf16*)(smem + 36864 + 9216);
    const int tid = threadIdx.x, wid = tid >> 5, lane = tid & 31;
    const int rowBase = blockIdx.y * 128, colBase = blockIdx.x * 64;
    const int wm = (wid & 3) * 32, wn = (wid >> 2) * 32;
    const int lrow = lane & 15, lch = lane >> 4;

    float acc[2][2][4][4];
#pragma unroll
    for (int h = 0; h < 2; h++)
#pragma unroll
        for (int i = 0; i < 2; i++)
#pragma unroll
            for (int j = 0; j < 4; j++)
#pragma unroll
                for (int q = 0; q < 4; q++) acc[h][i][j][q] = 0.f;

    const uint32_t sbAhi = smem_u32(sAhi), sbAlo = smem_u32(sAlo);
    const uint32_t sbBhi = smem_u32(sBhi), sbBlo = smem_u32(sBlo);

#pragma unroll
    for (int h = 0; h < 2; h++) {
        const bf16* ahp = Ahi + (size_t)h * NN * 64;
        const bf16* alp = Alo + (size_t)h * NN * 64;
        const bf16* bhp = Bhi + (size_t)h * NDEC * 64;
        const bf16* blp = Blo + (size_t)h * NDEC * 64;
        __syncthreads();
        for (int idx = tid; idx < 1024; idx += 256) {
            int row = idx >> 3, ch = idx & 7;
            int off = row * APITCH + ch * 8;
            *(uint4*)(sAhi + off) = *(const uint4*)(ahp + (size_t)(rowBase + row) * 64 + ch * 8);
            *(uint4*)(sAlo + off) = *(const uint4*)(alp + (size_t)(rowBase + row) * 64 + ch * 8);
        }
        for (int idx = tid; idx < 512; idx += 256) {
            int row = idx >> 3, ch = idx & 7;
            int off = row * APITCH + ch * 8;
            *(uint4*)(sBhi + off) = *(const uint4*)(bhp + (size_t)(colBase + row) * 64 + ch * 8);
            *(uint4*)(sBlo + off) = *(const uint4*)(blp + (size_t)(colBase + row) * 64 + ch * 8);
        }
        __syncthreads();
#pragma unroll
        for (int ks = 0; ks < 4; ks++) {
            uint32_t afh[2][4], afl[2][4];
#pragma unroll
            for (int i = 0; i < 2; i++) {
                uint32_t ao = ((wm + i * 16 + lrow) * APITCH) * 2 + (ks * 2 + lch) * 16;
                ldm_x4(afh[i], sbAhi + ao);
                ldm_x4(afl[i], sbAlo + ao);
            }
            uint32_t bfh[4][2], bfl[4][2];
#pragma unroll
            for (int jj = 0; jj < 2; jj++) {
                uint32_t bo = ((wn + jj * 16 + lrow) * APITCH) * 2 + (ks * 2 + lch) * 16;
                uint32_t r[4];
                ldm_x4(r, sbBhi + bo);
                bfh[2 * jj][0] = r[0]; bfh[2 * jj][1] = r[2];
                bfh[2 * jj + 1][0] = r[1]; bfh[2 * jj + 1][1] = r[3];
                ldm_x4(r, sbBlo + bo);
                bfl[2 * jj][0] = r[0]; bfl[2 * jj][1] = r[2];
                bfl[2 * jj + 1][0] = r[1]; bfl[2 * jj + 1][1] = r[3];
            }
#pragma unroll
            for (int i = 0; i < 2; i++)
#pragma unroll
                for (int j = 0; j < 4; j++) {
                    mma_bf16(acc[h][i][j], afh[i], bfh[j][0], bfh[j][1]);
                    mma_bf16(acc[h][i][j], afh[i], bfl[j][0], bfl[j][1]);
                    mma_bf16(acc[h][i][j], afl[i], bfh[j][0], bfh[j][1]);
                }
        }
    }

    const int rr = lane >> 2, cc = (lane & 3) * 2;
#pragma unroll
    for (int i = 0; i < 2; i++) {
#pragma unroll
        for (int j = 0; j < 4; j++) {
#pragma unroll
            for (int half = 0; half < 2; half++) {
                int gr = rowBase + wm + i * 16 + rr + half * 8;
                int gn = colBase + wn + j * 8 + cc;
                if (gn < FIN) {
                    float v0 = acc[0][i][j][half * 2], v1 = acc[1][i][j][half * 2];
                    xhat[(size_t)gr * FIN + gn] =
                        0.5f * (lrelu(v0 + b3[gn], 0.01f) + lrelu(v1 + b3[FIN + gn], 0.01f));
                }
                if (gn + 1 < FIN) {
                    float v0 = acc[0][i][j][half * 2 + 1], v1 = acc[1][i][j][half * 2 + 1];
                    xhat[(size_t)gr * FIN + gn + 1] =
                        0.5f * (lrelu(v0 + b3[gn + 1], 0.01f) + lrelu(v1 + b3[FIN + gn + 1], 0.01f));
                }
            }
        }
    }
}

// ================= CSR build =================
__global__ void k_zerodeg(int* deg) {
    int i = blockIdx.x * blockDim.x + threadIdx.x;
    if (i < NN) deg[i] = 0;
}
__global__ void k_deg(const int* __restrict__ dst, int* deg, int E) {
    int e = blockIdx.x * blockDim.x + threadIdx.x;
    if (e < E) atomicAdd(&deg[dst[e]], 1);
}
__global__ void k_scan(const int* __restrict__ deg, int* rowptr, int* cursor) {
    __shared__ int partx[257];
    int t = threadIdx.x;
    int base = t * 32;
    int loc[32];
    int s = 0;
#pragma unroll
    for (int i = 0; i < 32; i++) { loc[i] = s; s += deg[base + i]; }
    __shared__ int part[256];
    part[t] = s;
    __syncthreads();
    if (t == 0) {
        int acc = 0;
        for (int i = 0; i < 256; i++) { partx[i] = acc; acc += part[i]; }
        partx[256] = acc;
    }
    __syncthreads();
    int off = partx[t];
#pragma unroll
    for (int i = 0; i < 32; i++) {
        int v = off + loc[i];
        rowptr[base + i] = v;
        cursor[base + i] = v;
    }
    if (t == 0) rowptr[NN] = partx[256];
}
__global__ void k_scatter(const int* __restrict__ src, const int* __restrict__ dst,
                          int* cursor, int* csrsrc, int E) {
    int e = blockIdx.x * blockDim.x + threadIdx.x;
    if (e >= E) return;
    int d = dst[e];
    int idx = atomicAdd(&cursor[d], 1);
    csrsrc[idx] = src[e];
}

// ================= pack kernels (split + transpose) =================
__global__ void k_pack_feat(const float* __restrict__ feat, bf16* __restrict__ fhi,
                            bf16* __restrict__ flo) {
    int n = blockIdx.x;
    for (int f = threadIdx.x; f < FINB; f += blockDim.x) {
        float v = (f < FIN) ? feat[(size_t)n * FIN + f] : 0.f;
        split_bf16(v, &fhi[(size_t)n * FINB + f], &flo[(size_t)n * FINB + f]);
    }
}
__global__ void k_pack_w1t(const float* __restrict__ W1, bf16* __restrict__ whi,
                           bf16* __restrict__ wlo) {
    int n = blockIdx.x;  // 256
    for (int k = threadIdx.x; k < FINB; k += blockDim.x) {
        float v = (k < FIN) ? W1[(size_t)k * 256 + n] : 0.f;
        split_bf16(v, &whi[(size_t)n * FINB + k], &wlo[(size_t)n * FINB + k]);
    }
}
__global__ void k_pack_w2t(const float* __restrict__ W2, bf16* __restrict__ whi,
                           bf16* __restrict__ wlo) {
    int n = blockIdx.x;  // 128
    for (int k = threadIdx.x; k < 256; k += blockDim.x) {
        float v = W2[(size_t)k * 128 + n];
        split_bf16(v, &whi[(size_t)n * 256 + k], &wlo[(size_t)n * 256 + k]);
    }
}
__global__ void k_pack_w3t(const float* __restrict__ W3, bf16* __restrict__ whi,
                           bf16* __restrict__ wlo) {
    int f = blockIdx.x;  // NDEC rows
    int k = threadIdx.x; // 64
#pragma unroll
    for (int h = 0; h < 2; h++) {
        float v = (f < FIN) ? W3[(size_t)k * (2 * FIN) + h * FIN + f] : 0.f;
        split_bf16(v, &whi[((size_t)h * NDEC + f) * 64 + k], &wlo[((size_t)h * NDEC + f) * 64 + k]);
    }
}

// ================= attention logits =================
__global__ void k_elr(const float* __restrict__ hp, const float* __restrict__ al,
                      const float* __restrict__ ar, float* el, float* er, int D) {
    int w = (blockIdx.x * blockDim.x + threadIdx.x) >> 5;
    int lane = threadIdx.x & 31;
    if (w >= NN * 2) return;
    int n = w >> 1, h = w & 1;
    const float* row = hp + (size_t)n * (2 * D) + h * D;
    const float* a = al + h * D;
    const float* b = ar + h * D;
    float sl = 0.f, sr = 0.f;
    for (int d = lane; d < D; d += 32) { float x = row[d]; sl += x * a[d]; sr += x * b[d]; }
#pragma unroll
    for (int o = 16; o; o >>= 1) {
        sl += __shfl_down_sync(0xffffffffu, sl, o);
        sr += __shfl_down_sync(0xffffffffu, sr, o);
    }
    if (lane == 0) { el[w] = sl; er[w] = sr; }
}

__global__ void k_uv(const float* __restrict__ W3, const float* __restrict__ al3,
                     const float* __restrict__ ar3, float* uv) {
    int w = (blockIdx.x * blockDim.x + threadIdx.x) >> 5;
    int lane = threadIdx.x & 31;
    if (w >= 128) return;
    int h = w >> 6, k = w & 63;
    const float* Wr = W3 + (size_t)k * (2 * FIN) + h * FIN;
    const float* a = al3 + (size_t)h * FIN;
    const float* b = ar3 + (size_t)h * FIN;
    float su = 0.f, sv = 0.f;
    for (int f = lane; f < FIN; f += 32) { float ww = Wr[f]; su += ww * a[f]; sv += ww * b[f]; }
#pragma unroll
    for (int o = 16; o; o >>= 1) {
        su += __shfl_down_sync(0xffffffffu, su, o);
        sv += __shfl_down_sync(0xffffffffu, sv, o);
    }
    if (lane == 0) { uv[h * 64 + k] = su; uv[128 + h * 64 + k] = sv; }
}

__global__ void k_elr3(const float* __restrict__ h2, const float* __restrict__ uv,
                       float* el, float* er) {
    int w = (blockIdx.x * blockDim.x + threadIdx.x) >> 5;
    int lane = threadIdx.x & 31;
    if (w >= NN * 2) return;
    int n = w >> 1, h = w & 1;
    const float* row = h2 + (size_t)n * 64;
    const float* u = uv + h * 64;
    const float* v = uv + 128 + h * 64;
    float sl = 0.f, sr = 0.f;
    for (int d = lane; d < 64; d += 32) { float x = row[d]; sl += x * u[d]; sr += x * v[d]; }
#pragma unroll
    for (int o = 16; o; o >>= 1) {
        sl += __shfl_down_sync(0xffffffffu, sl, o);
        sr += __shfl_down_sync(0xffffffffu, sr, o);
    }
    if (lane == 0) { el[w] = sl; er[w] = sr; }
}

// ================= CSR softmax denominators =================
__global__ void k_sum(const int* __restrict__ rowptr, const int* __restrict__ csrsrc,
                      const float* __restrict__ el, const float* __restrict__ er,
                      float* __restrict__ sinv) {
    int d = blockIdx.x * (blockDim.x >> 5) + (threadIdx.x >> 5);
    int lane = threadIdx.x & 31;
    if (d >= NN) return;
    int b = rowptr[d], e = rowptr[d + 1];
    float2 r = *(const float2*)&er[d * 2];
    float s0 = 0.f, s1 = 0.f;
    for (int i = b + lane; i < e; i += 32) {
        int s = csrsrc[i];
        float2 l = *(const float2*)&el[s * 2];
        float e0 = l.x + r.x; e0 = e0 > 0.f ? e0 : 0.2f * e0;
        float e1 = l.y + r.y; e1 = e1 > 0.f ? e1 : 0.2f * e1;
        s0 += __expf(e0); s1 += __expf(e1);
    }
#pragma unroll
    for (int o = 16; o; o >>= 1) {
        s0 += __shfl_down_sync(0xffffffffu, s0, o);
        s1 += __shfl_down_sync(0xffffffffu, s1, o);
    }
    if (lane == 0) { sinv[d * 2] = 1.f / s0; sinv[d * 2 + 1] = 1.f / s1; }
}

// ================= CSR gather aggregation =================
__global__ void __launch_bounds__(256)
k_agg1(const int* __restrict__ rowptr, const int* __restrict__ csrsrc,
       const float* __restrict__ el, const float* __restrict__ er,
       const float* __restrict__ sinv, const float* __restrict__ hp,
       const float* __restrict__ b1, bf16* __restrict__ ohi, bf16* __restrict__ olo) {
    int d = blockIdx.x;
    int t = threadIdx.x;
    __shared__ float2 sal[128];
    __shared__ int ssrc[128];
    int b = rowptr[d], en = rowptr[d + 1];
    float2 r = *(const float2*)&er[d * 2];
    float2 inv = *(const float2*)&sinv[d * 2];
    float acc = 0.f;
    int h = t >> 7;
    for (int c = b; c < en; c += 128) {
        int cnt = min(128, en - c);
        __syncthreads();
        if (t < cnt) {
            int s = csrsrc[c + t];
            float2 l = *(const float2*)&el[s * 2];
            float e0 = l.x + r.x; e0 = e0 > 0.f ? e0 : 0.2f * e0;
            float e1 = l.y + r.y; e1 = e1 > 0.f ? e1 : 0.2f * e1;
            sal[t] = make_float2(__expf(e0) * inv.x, __expf(e1) * inv.y);
            ssrc[t] = s;
        }
        __syncthreads();
#pragma unroll 4
        for (int i = 0; i < cnt; i++) {
            float a = h ? sal[i].y : sal[i].x;
            acc = fmaf(a, hp[(size_t)ssrc[i] * 256 + t], acc);
        }
    }
    float x = lrelu(acc + b1[t], 0.01f);
    split_bf16(x, &ohi[(size_t)d * 256 + t], &olo[(size_t)d * 256 + t]);
}

__global__ void __launch_bounds__(128)
k_agg2(const int* __restrict__ rowptr, const int* __restrict__ csrsrc,
       const float* __restrict__ el, const float* __restrict__ er,
       const float* __restrict__ sinv, const float* __restrict__ hp,
       const float* __restrict__ b2, float* __restrict__ h2,
       bf16* __restrict__ h2hi, bf16* __restrict__ h2lo) {
    int d = blockIdx.x;
    int t = threadIdx.x;
    __shared__ float2 sal[128];
    __shared__ int ssrc[128];
    __shared__ float o[128];
    int b = rowptr[d], en = rowptr[d + 1];
    float2 r = *(const float2*)&er[d * 2];
    float2 inv = *(const float2*)&sinv[d * 2];
    float acc = 0.f;
    int h = t >> 6;
    for (int c = b; c < en; c += 128) {
        int cnt = min(128, en - c);
        __syncthreads();
        if (t < cnt) {
            int s = csrsrc[c + t];
            float2 l = *(const float2*)&el[s * 2];
            float e0 = l.x + r.x; e0 = e0 > 0.f ? e0 : 0.2f * e0;
            float e1 = l.y + r.y; e1 = e1 > 0.f ? e1 : 0.2f * e1;
            sal[t] = make_float2(__expf(e0) * inv.x, __expf(e1) * inv.y);
            ssrc[t] = s;
        }
        __syncthreads();
#pragma unroll 4
        for (int i = 0; i < cnt; i++) {
            float a = h ? sal[i].y : sal[i].x;
            acc = fmaf(a, hp[(size_t)ssrc[i] * 128 + t], acc);
        }
    }
    o[t] = acc;
    __syncthreads();
    if (t < 64) {
        float x0 = lrelu(o[t] + b2[t], 0.01f);
        float x1 = lrelu(o[64 + t] + b2[64 + t], 0.01f);
        float v = 0.5f * (x0 + x1);
        h2[(size_t)d * 64 + t] = v;
        split_bf16(v, &h2hi[(size_t)d * 64 + t], &h2lo[(size_t)d * 64 + t]);
    }
}

__global__ void __launch_bounds__(128)
k_agg3(const int* __restrict__ rowptr, const int* __restrict__ csrsrc,
       const float* __restrict__ el, const float* __restrict__ er,
       const float* __restrict__ sinv, const float* __restrict__ h2,
       bf16* __restrict__ ahi, bf16* __restrict__ alo) {
    int d = blockIdx.x;
    int t = threadIdx.x;
    __shared__ float2 sal[128];
    __shared__ int ssrc[128];
    int b = rowptr[d], en = rowptr[d + 1];
    float2 r = *(const float2*)&er[d * 2];
    float2 inv = *(const float2*)&sinv[d * 2];
    float acc = 0.f;
    int h = t >> 6, dd = t & 63;
    for (int c = b; c < en; c += 128) {
        int cnt = min(128, en - c);
        __syncthreads();
        if (t < cnt) {
            int s = csrsrc[c + t];
            float2 l = *(const float2*)&el[s * 2];
            float e0 = l.x + r.x; e0 = e0 > 0.f ? e0 : 0.2f * e0;
            float e1 = l.y + r.y; e1 = e1 > 0.f ? e1 : 0.2f * e1;
            sal[t] = make_float2(__expf(e0) * inv.x, __expf(e1) * inv.y);
            ssrc[t] = s;
        }
        __syncthreads();
#pragma unroll 4
        for (int i = 0; i < cnt; i++) {
            float a = h ? sal[i].y : sal[i].x;
            acc = fmaf(a, h2[(size_t)ssrc[i] * 64 + dd], acc);
        }
    }
    size_t idx = ((size_t)h * NN + d) * 64 + dd;
    split_bf16(acc, &ahi[idx], &alo[idx]);
}

// ================= launch =================
extern "C" void kernel_launch(void* const* d_in, const int* in_sizes, int n_in,
                              void* d_out, int out_size) {
    const float* feat = (const float*)d_in[0];
    const int* src = (const int*)d_in[1];
    const int* dst = (const int*)d_in[2];
    const float* W1 = (const float*)d_in[3];
    const float* al1 = (const float*)d_in[4];
    const float* ar1 = (const float*)d_in[5];
    const float* b1 = (const float*)d_in[6];
    const float* W2 = (const float*)d_in[7];
    const float* al2 = (const float*)d_in[8];
    const float* ar2 = (const float*)d_in[9];
    const float* b2 = (const float*)d_in[10];
    const float* W3 = (const float*)d_in[11];
    const float* al3 = (const float*)d_in[12];
    const float* ar3 = (const float*)d_in[13];
    const float* b3 = (const float*)d_in[14];

    float* a_hat = (float*)d_out;
    float* x_hat = a_hat + (size_t)NN * NN;
    const int E = in_sizes[1];

    bf16 *feathi, *featlo, *w1thi, *w1tlo, *w2thi, *w2tlo, *w3thi, *w3tlo;
    bf16 *agg1hi, *agg1lo, *h2hi, *h2lo, *agg3hi, *agg3lo;
    float *h1p, *h2p, *h2, *el, *er, *sinv, *uv;
    int *deg, *cursor, *rowptr, *csrsrc;
    cudaGetSymbolAddress((void**)&feathi, g_feathi);
    cudaGetSymbolAddress((void**)&featlo, g_featlo);
    cudaGetSymbolAddress((void**)&w1thi, g_w1thi);
    cudaGetSymbolAddress((void**)&w1tlo, g_w1tlo);
    cudaGetSymbolAddress((void**)&w2thi, g_w2thi);
    cudaGetSymbolAddress((void**)&w2tlo, g_w2tlo);
    cudaGetSymbolAddress((void**)&w3thi, g_w3thi);
    cudaGetSymbolAddress((void**)&w3tlo, g_w3tlo);
    cudaGetSymbolAddress((void**)&h1p, g_h1p);
    cudaGetSymbolAddress((void**)&agg1hi, g_agg1hi);
    cudaGetSymbolAddress((void**)&agg1lo, g_agg1lo);
    cudaGetSymbolAddress((void**)&h2p, g_h2p);
    cudaGetSymbolAddress((void**)&h2, g_h2);
    cudaGetSymbolAddress((void**)&h2hi, g_h2hi);
    cudaGetSymbolAddress((void**)&h2lo, g_h2lo);
    cudaGetSymbolAddress((void**)&agg3hi, g_agg3hi);
    cudaGetSymbolAddress((void**)&agg3lo, g_agg3lo);
    cudaGetSymbolAddress((void**)&el, g_el);
    cudaGetSymbolAddress((void**)&er, g_er);
    cudaGetSymbolAddress((void**)&sinv, g_sinv);
    cudaGetSymbolAddress((void**)&uv, g_uv);
    cudaGetSymbolAddress((void**)&deg, g_deg);
    cudaGetSymbolAddress((void**)&cursor, g_cursor);
    cudaGetSymbolAddress((void**)&rowptr, g_rowptr);
    cudaGetSymbolAddress((void**)&csrsrc, g_csrsrc);

    cudaFuncSetAttribute(ahat_hmma, cudaFuncAttributeMaxDynamicSharedMemorySize, AHAT_SMEM);
    cudaFuncSetAttribute(hmma_gemm, cudaFuncAttributeMaxDynamicSharedMemorySize, HG_SMEM);
    cudaFuncSetAttribute(dec_hmma, cudaFuncAttributeMaxDynamicSharedMemorySize, DEC_SMEM);

    float *el1 = el, *el2 = el + NN * 2, *el3 = el + 2 * NN * 2;
    float *er1 = er, *er2 = er + NN * 2, *er3 = er + 2 * NN * 2;
    float *s1 = sinv, *s2 = sinv + NN * 2, *s3 = sinv + 2 * NN * 2;

    const int eb = (E + 255) / 256;

    // ---- CSR build ----
    k_zerodeg<<<(NN + 255) / 256, 256>>>(deg);
    k_deg<<<eb, 256>>>(dst, deg, E);
    k_scan<<<1, 256>>>(deg, rowptr, cursor);
    k_scatter<<<eb, 256>>>(src, dst, cursor, csrsrc, E);

    // ---- pack (split + transpose) ----
    k_pack_feat<<<NN, 256>>>(feat, feathi, featlo);
    k_pack_w1t<<<256, 256>>>(W1, w1thi, w1tlo);
    k_pack_w2t<<<128, 256>>>(W2, w2thi, w2tlo);
    k_pack_w3t<<<NDEC, 64>>>(W3, w3thi, w3tlo);

    // ---- layer 1: h1p = feat @ W1 (bf16-split HMMA) ----
    {
        dim3 grid(2, 64);
        hmma_gemm<<<grid, 256, HG_SMEM>>>(feathi, featlo, w1thi, w1tlo, h1p, FINB, FINB, FINB, 256);
    }
    k_elr<<<(NN * 2 * 32 + 255) / 256, 256>>>(h1p, al1, ar1, el1, er1, 128);
    k_sum<<<NN / 8, 256>>>(rowptr, csrsrc, el1, er1, s1);
    k_agg1<<<NN, 256>>>(rowptr, csrsrc, el1, er1, s1, h1p, b1, agg1hi, agg1lo);

    // ---- layer 2: h2p = agg1 @ W2 (HMMA) ----
    {
        dim3 grid(1, 64);
        hmma_gemm<<<grid, 256, HG_SMEM>>>(agg1hi, agg1lo, w2thi, w2tlo, h2p, 256, 256, 256, 128);
    }
    k_elr<<<(NN * 2 * 32 + 255) / 256, 256>>>(h2p, al2, ar2, el2, er2, 64);
    k_sum<<<NN / 8, 256>>>(rowptr, csrsrc, el2, er2, s2);
    k_agg2<<<NN, 128>>>(rowptr, csrsrc, el2, er2, s2, h2p, b2, h2, h2hi, h2lo);

    // ---- structure decoder: a_hat = h2 @ h2^T (HMMA) ----
    {
        dim3 grid(NN / 128, NN / 128);
        ahat_hmma<<<grid, 256, AHAT_SMEM>>>(h2hi, h2lo, a_hat);
    }

    // ---- attribute decoder ----
    k_uv<<<16, 256>>>(W3, al3, ar3, uv);
    k_elr3<<<(NN * 2 * 32 + 255) / 256, 256>>>(h2, uv, el3, er3);
    k_sum<<<NN / 8, 256>>>(rowptr, csrsrc, el3, er3, s3);
    k_agg3<<<NN, 128>>>(rowptr, csrsrc, el3, er3, s3, h2, agg3hi, agg3lo);
    {
        dim3 grid(NDEC / 64, NN / 128);
        dec_hmma<<<grid, 256, DEC_SMEM>>>(agg3hi, agg3lo, w3thi, w3tlo, b3, x_hat);
    }
}

// round 7
// speedup vs baseline: 3.6504x; 1.0772x over previous
#include <cuda_runtime.h>
#include <cuda_bf16.h>
#include <cstdint>

#define NN 8192
#define FIN 1433
#define FINB 1472      // FIN padded to multiple of 64
#define NDEC 1536      // decoder N padded to multiple of 64
#define MAXE (1 << 20)

typedef unsigned long long u64t;
typedef __nv_bfloat16 bf16;

// ---------------- scratch (device globals) ----------------
__device__ bf16 g_feathi[NN * FINB];
__device__ bf16 g_featlo[NN * FINB];
__device__ bf16 g_w1thi[256 * FINB];
__device__ bf16 g_w1tlo[256 * FINB];
__device__ bf16 g_w2thi[128 * 256];
__device__ bf16 g_w2tlo[128 * 256];
__device__ bf16 g_w3thi[2 * NDEC * 64];
__device__ bf16 g_w3tlo[2 * NDEC * 64];
__device__ float g_h1p[NN * 256];
__device__ bf16 g_agg1hi[NN * 256];
__device__ bf16 g_agg1lo[NN * 256];
__device__ float g_h2p[NN * 128];
__device__ float g_h2[NN * 64];
__device__ bf16 g_h2hi[NN * 64];
__device__ bf16 g_h2lo[NN * 64];
__device__ bf16 g_agg3hi[2 * NN * 64];
__device__ bf16 g_agg3lo[2 * NN * 64];
__device__ float g_el[3 * NN * 2];
__device__ float g_er[3 * NN * 2];
__device__ float g_sinv[3 * NN * 2];
__device__ float g_uv[2 * 64 * 2];
__device__ int g_deg[NN];
__device__ int g_cursor[NN];
__device__ int g_rowptr[NN + 1];
__device__ int g_csrsrc[MAXE];

__device__ __forceinline__ float lrelu(float x, float a) { return x > 0.f ? x : a * x; }

__device__ __forceinline__ uint32_t smem_u32(const void* p) {
    uint32_t a;
    asm("{ .reg .u64 t; cvta.to.shared.u64 t, %1; cvt.u32.u64 %0, t; }" : "=r"(a) : "l"(p));
    return a;
}
__device__ __forceinline__ void ldm_x4(uint32_t* r, uint32_t addr) {
    asm volatile("ldmatrix.sync.aligned.m8n8.x4.shared.b16 {%0,%1,%2,%3}, [%4];"
                 : "=r"(r[0]), "=r"(r[1]), "=r"(r[2]), "=r"(r[3]) : "r"(addr));
}
__device__ __forceinline__ void mma_bf16(float* c, const uint32_t* a, uint32_t b0, uint32_t b1) {
    asm volatile(
        "mma.sync.aligned.m16n8k16.row.col.f32.bf16.bf16.f32 "
        "{%0,%1,%2,%3}, {%4,%5,%6,%7}, {%8,%9}, {%0,%1,%2,%3};"
        : "+f"(c[0]), "+f"(c[1]), "+f"(c[2]), "+f"(c[3])
        : "r"(a[0]), "r"(a[1]), "r"(a[2]), "r"(a[3]), "r"(b0), "r"(b1));
}
__device__ __forceinline__ void split_bf16(float v, bf16* hi, bf16* lo) {
    bf16 h = __float2bfloat16(v);
    *hi = h;
    *lo = __float2bfloat16(v - __bfloat162float(h));
}

#define APITCH 72  // bf16 per smem row (144B) — conflict-free ldmatrix

// ================= generic bf16-split HMMA GEMM =================
#define HG_SMEM (4 * 128 * APITCH * 2)  // 73728 B

__global__ void __launch_bounds__(256)
hmma_gemm(const bf16* __restrict__ Ahi, const bf16* __restrict__ Alo,
          const bf16* __restrict__ Bhi, const bf16* __restrict__ Blo,
          float* __restrict__ C, int K, int lda, int ldb, int ldc) {
    extern __shared__ char smem[];
    bf16* sAhi = (bf16*)smem;
    bf16* sAlo = (bf16*)(smem + 18432);
    bf16* sBhi = (bf16*)(smem + 36864);
    bf16* sBlo = (bf16*)(smem + 55296);
    const int tid = threadIdx.x, wid = tid >> 5, lane = tid & 31;
    const int rowBase = blockIdx.y * 128, colBase = blockIdx.x * 128;
    const int wm = (wid & 3) * 32, wn = (wid >> 2) * 64;
    const int lrow = lane & 15, lch = lane >> 4;

    float acc[2][8][4];
#pragma unroll
    for (int i = 0; i < 2; i++)
#pragma unroll
        for (int j = 0; j < 8; j++)
#pragma unroll
            for (int q = 0; q < 4; q++) acc[i][j][q] = 0.f;

    const uint32_t sbAhi = smem_u32(sAhi), sbAlo = smem_u32(sAlo);
    const uint32_t sbBhi = smem_u32(sBhi), sbBlo = smem_u32(sBlo);

    for (int kc = 0; kc < K; kc += 64) {
        for (int idx = tid; idx < 1024; idx += 256) {
            int row = idx >> 3, ch = idx & 7;
            int off = row * APITCH + ch * 8;
            *(uint4*)(sAhi + off) = *(const uint4*)(Ahi + (size_t)(rowBase + row) * lda + kc + ch * 8);
            *(uint4*)(sAlo + off) = *(const uint4*)(Alo + (size_t)(rowBase + row) * lda + kc + ch * 8);
            *(uint4*)(sBhi + off) = *(const uint4*)(Bhi + (size_t)(colBase + row) * ldb + kc + ch * 8);
            *(uint4*)(sBlo + off) = *(const uint4*)(Blo + (size_t)(colBase + row) * ldb + kc + ch * 8);
        }
        __syncthreads();
#pragma unroll
        for (int ks = 0; ks < 4; ks++) {
            uint32_t afh[2][4], afl[2][4];
#pragma unroll
            for (int i = 0; i < 2; i++) {
                uint32_t ao = ((wm + i * 16 + lrow) * APITCH) * 2 + (ks * 2 + lch) * 16;
                ldm_x4(afh[i], sbAhi + ao);
                ldm_x4(afl[i], sbAlo + ao);
            }
            uint32_t bfh[8][2], bfl[8][2];
#pragma unroll
            for (int jj = 0; jj < 4; jj++) {
                uint32_t bo = ((wn + jj * 16 + lrow) * APITCH) * 2 + (ks * 2 + lch) * 16;
                uint32_t r[4];
                ldm_x4(r, sbBhi + bo);
                bfh[2 * jj][0] = r[0]; bfh[2 * jj][1] = r[2];
                bfh[2 * jj + 1][0] = r[1]; bfh[2 * jj + 1][1] = r[3];
                ldm_x4(r, sbBlo + bo);
                bfl[2 * jj][0] = r[0]; bfl[2 * jj][1] = r[2];
                bfl[2 * jj + 1][0] = r[1]; bfl[2 * jj + 1][1] = r[3];
            }
#pragma unroll
            for (int i = 0; i < 2; i++)
#pragma unroll
                for (int j = 0; j < 8; j++) {
                    mma_bf16(acc[i][j], afh[i], bfh[j][0], bfh[j][1]);
                    mma_bf16(acc[i][j], afh[i], bfl[j][0], bfl[j][1]);
                    mma_bf16(acc[i][j], afl[i], bfh[j][0], bfh[j][1]);
                }
        }
        __syncthreads();
    }

    const int rr = lane >> 2, cc = (lane & 3) * 2;
#pragma unroll
    for (int i = 0; i < 2; i++) {
        int gr = rowBase + wm + i * 16 + rr;
        float* out0 = C + (size_t)gr * ldc + colBase + wn + cc;
        float* out1 = out0 + 8 * ldc;
#pragma unroll
        for (int j = 0; j < 8; j++) {
            *(float2*)(out0 + j * 8) = make_float2(acc[i][j][0], acc[i][j][1]);
            *(float2*)(out1 + j * 8) = make_float2(acc[i][j][2], acc[i][j][3]);
        }
    }
}

// ================= a_hat HMMA (128x128, K=64) =================
#define AHAT_TILE_B (128 * APITCH * 2)
#define AHAT_SMEM (4 * AHAT_TILE_B)

__global__ void __launch_bounds__(256)
ahat_hmma(const bf16* __restrict__ hi, const bf16* __restrict__ lo, float* __restrict__ C) {
    extern __shared__ char smem[];
    bf16* sAhi = (bf16*)(smem);
    bf16* sAlo = (bf16*)(smem + AHAT_TILE_B);
    bf16* sBhi = (bf16*)(smem + 2 * AHAT_TILE_B);
    bf16* sBlo = (bf16*)(smem + 3 * AHAT_TILE_B);
    const int tid = threadIdx.x, wid = tid >> 5, lane = tid & 31;
    const int rowBase = blockIdx.y * 128, colBase = blockIdx.x * 128;

    for (int idx = tid; idx < 128 * 8; idx += 256) {
        int row = idx >> 3, ch = idx & 7;
        int off = row * APITCH + ch * 8;
        *(uint4*)(sAhi + off) = *((const uint4*)(hi + (size_t)(rowBase + row) * 64) + ch);
        *(uint4*)(sAlo + off) = *((const uint4*)(lo + (size_t)(rowBase + row) * 64) + ch);
        *(uint4*)(sBhi + off) = *((const uint4*)(hi + (size_t)(colBase + row) * 64) + ch);
        *(uint4*)(sBlo + off) = *((const uint4*)(lo + (size_t)(colBase + row) * 64) + ch);
    }
    __syncthreads();

    const int wm = (wid & 3) * 32, wn = (wid >> 2) * 64;
    float acc[2][8][4];
#pragma unroll
    for (int i = 0; i < 2; i++)
#pragma unroll
        for (int j = 0; j < 8; j++)
#pragma unroll
            for (int q = 0; q < 4; q++) acc[i][j][q] = 0.f;

    const int lrow = lane & 15, lch = lane >> 4;
    const uint32_t sbAhi = smem_u32(sAhi), sbAlo = smem_u32(sAlo);
    const uint32_t sbBhi = smem_u32(sBhi), sbBlo = smem_u32(sBlo);

#pragma unroll
    for (int pass = 0; pass < 3; pass++) {
        const uint32_t aBase = (pass == 2) ? sbAlo : sbAhi;
        const uint32_t bBase = (pass == 1) ? sbBlo : sbBhi;
#pragma unroll
        for (int ks = 0; ks < 4; ks++) {
            uint32_t af[2][4];
#pragma unroll
            for (int i = 0; i < 2; i++)
                ldm_x4(af[i], aBase + ((wm + i * 16 + lrow) * APITCH) * 2 + (ks * 2 + lch) * 16);
            uint32_t bf[8][2];
#pragma unroll
            for (int jj = 0; jj < 4; jj++) {
                uint32_t r[4];
                ldm_x4(r, bBase + ((wn + jj * 16 + lrow) * APITCH) * 2 + (ks * 2 + lch) * 16);
                bf[2 * jj][0] = r[0]; bf[2 * jj][1] = r[2];
                bf[2 * jj + 1][0] = r[1]; bf[2 * jj + 1][1] = r[3];
            }
#pragma unroll
            for (int i = 0; i < 2; i++)
#pragma unroll
                for (int j = 0; j < 8; j++)
                    mma_bf16(acc[i][j], af[i], bf[j][0], bf[j][1]);
        }
    }

    const int rr = lane >> 2, cc = (lane & 3) * 2;
#pragma unroll
    for (int i = 0; i < 2; i++) {
        int gr = rowBase + wm + i * 16 + rr;
        float* out0 = C + (size_t)gr * NN + colBase + wn + cc;
        float* out1 = out0 + 8 * NN;
#pragma unroll
        for (int j = 0; j < 8; j++) {
            *(float2*)(out0 + j * 8) = make_float2(acc[i][j][0], acc[i][j][1]);
            *(float2*)(out1 + j * 8) = make_float2(acc[i][j][2], acc[i][j][3]);
        }
    }
}

// ================= fused decoder HMMA (2 heads + bias + lrelu + mean) =================
#define DEC_SMEM (2 * 128 * APITCH * 2 + 2 * 64 * APITCH * 2)  // 55296 B

__global__ void __launch_bounds__(256)
dec_hmma(const bf16* __restrict__ Ahi, const bf16* __restrict__ Alo,
         const bf16* __restrict__ Bhi, const bf16* __restrict__ Blo,
         const float* __restrict__ b3, float* __restrict__ xhat) {
    extern __shared__ char smem[];
    bf16* sAhi = (bf16*)smem;
    bf16* sAlo = (bf16*)(smem + 18432);
    bf16* sBhi = (bf16*)(smem + 36864);
    bf16* sBlo = (bf16*)(smem + 36864 + 9216);
    const int tid = threadIdx.x, wid = tid >> 5, lane = tid & 31;
    const int rowBase = blockIdx.y * 128, colBase = blockIdx.x * 64;
    const int wm = (wid & 3) * 32, wn = (wid >> 2) * 32;
    const int lrow = lane & 15, lch = lane >> 4;

    float acc[2][2][4][4];
#pragma unroll
    for (int h = 0; h < 2; h++)
#pragma unroll
        for (int i = 0; i < 2; i++)
#pragma unroll
            for (int j = 0; j < 4; j++)
#pragma unroll
                for (int q = 0; q < 4; q++) acc[h][i][j][q] = 0.f;

    const uint32_t sbAhi = smem_u32(sAhi), sbAlo = smem_u32(sAlo);
    const uint32_t sbBhi = smem_u32(sBhi), sbBlo = smem_u32(sBlo);

#pragma unroll
    for (int h = 0; h < 2; h++) {
        const bf16* ahp = Ahi + (size_t)h * NN * 64;
        const bf16* alp = Alo + (size_t)h * NN * 64;
        const bf16* bhp = Bhi + (size_t)h * NDEC * 64;
        const bf16* blp = Blo + (size_t)h * NDEC * 64;
        __syncthreads();
        for (int idx = tid; idx < 1024; idx += 256) {
            int row = idx >> 3, ch = idx & 7;
            int off = row * APITCH + ch * 8;
            *(uint4*)(sAhi + off) = *(const uint4*)(ahp + (size_t)(rowBase + row) * 64 + ch * 8);
            *(uint4*)(sAlo + off) = *(const uint4*)(alp + (size_t)(rowBase + row) * 64 + ch * 8);
        }
        for (int idx = tid; idx < 512; idx += 256) {
            int row = idx >> 3, ch = idx & 7;
            int off = row * APITCH + ch * 8;
            *(uint4*)(sBhi + off) = *(const uint4*)(bhp + (size_t)(colBase + row) * 64 + ch * 8);
            *(uint4*)(sBlo + off) = *(const uint4*)(blp + (size_t)(colBase + row) * 64 + ch * 8);
        }
        __syncthreads();
#pragma unroll
        for (int ks = 0; ks < 4; ks++) {
            uint32_t afh[2][4], afl[2][4];
#pragma unroll
            for (int i = 0; i < 2; i++) {
                uint32_t ao = ((wm + i * 16 + lrow) * APITCH) * 2 + (ks * 2 + lch) * 16;
                ldm_x4(afh[i], sbAhi + ao);
                ldm_x4(afl[i], sbAlo + ao);
            }
            uint32_t bfh[4][2], bfl[4][2];
#pragma unroll
            for (int jj = 0; jj < 2; jj++) {
                uint32_t bo = ((wn + jj * 16 + lrow) * APITCH) * 2 + (ks * 2 + lch) * 16;
                uint32_t r[4];
                ldm_x4(r, sbBhi + bo);
                bfh[2 * jj][0] = r[0]; bfh[2 * jj][1] = r[2];
                bfh[2 * jj + 1][0] = r[1]; bfh[2 * jj + 1][1] = r[3];
                ldm_x4(r, sbBlo + bo);
                bfl[2 * jj][0] = r[0]; bfl[2 * jj][1] = r[2];
                bfl[2 * jj + 1][0] = r[1]; bfl[2 * jj + 1][1] = r[3];
            }
#pragma unroll
            for (int i = 0; i < 2; i++)
#pragma unroll
                for (int j = 0; j < 4; j++) {
                    mma_bf16(acc[h][i][j], afh[i], bfh[j][0], bfh[j][1]);
                    mma_bf16(acc[h][i][j], afh[i], bfl[j][0], bfl[j][1]);
                    mma_bf16(acc[h][i][j], afl[i], bfh[j][0], bfh[j][1]);
                }
        }
    }

    const int rr = lane >> 2, cc = (lane & 3) * 2;
#pragma unroll
    for (int i = 0; i < 2; i++) {
#pragma unroll
        for (int j = 0; j < 4; j++) {
#pragma unroll
            for (int half = 0; half < 2; half++) {
                int gr = rowBase + wm + i * 16 + rr + half * 8;
                int gn = colBase + wn + j * 8 + cc;
                if (gn < FIN) {
                    float v0 = acc[0][i][j][half * 2], v1 = acc[1][i][j][half * 2];
                    xhat[(size_t)gr * FIN + gn] =
                        0.5f * (lrelu(v0 + b3[gn], 0.01f) + lrelu(v1 + b3[FIN + gn], 0.01f));
                }
                if (gn + 1 < FIN) {
                    float v0 = acc[0][i][j][half * 2 + 1], v1 = acc[1][i][j][half * 2 + 1];
                    xhat[(size_t)gr * FIN + gn + 1] =
                        0.5f * (lrelu(v0 + b3[gn + 1], 0.01f) + lrelu(v1 + b3[FIN + gn + 1], 0.01f));
                }
            }
        }
    }
}

// ================= CSR build =================
__global__ void k_zerodeg(int* deg) {
    int i = blockIdx.x * blockDim.x + threadIdx.x;
    if (i < NN) deg[i] = 0;
}
__global__ void k_deg(const int* __restrict__ dst, int* deg, int E) {
    int e = blockIdx.x * blockDim.x + threadIdx.x;
    if (e < E) atomicAdd(&deg[dst[e]], 1);
}
__global__ void k_scan(const int* __restrict__ deg, int* rowptr, int* cursor) {
    __shared__ int partx[257];
    int t = threadIdx.x;
    int base = t * 32;
    int loc[32];
    int s = 0;
#pragma unroll
    for (int i = 0; i < 32; i++) { loc[i] = s; s += deg[base + i]; }
    __shared__ int part[256];
    part[t] = s;
    __syncthreads();
    if (t == 0) {
        int acc = 0;
        for (int i = 0; i < 256; i++) { partx[i] = acc; acc += part[i]; }
        partx[256] = acc;
    }
    __syncthreads();
    int off = partx[t];
#pragma unroll
    for (int i = 0; i < 32; i++) {
        int v = off + loc[i];
        rowptr[base + i] = v;
        cursor[base + i] = v;
    }
    if (t == 0) rowptr[NN] = partx[256];
}
__global__ void k_scatter(const int* __restrict__ src, const int* __restrict__ dst,
                          int* cursor, int* csrsrc, int E) {
    int e = blockIdx.x * blockDim.x + threadIdx.x;
    if (e >= E) return;
    int d = dst[e];
    int idx = atomicAdd(&cursor[d], 1);
    csrsrc[idx] = src[e];
}

// ================= pack kernels (split + transpose) =================
__global__ void k_pack_feat(const float* __restrict__ feat, bf16* __restrict__ fhi,
                            bf16* __restrict__ flo) {
    int n = blockIdx.x;
    for (int f = threadIdx.x; f < FINB; f += blockDim.x) {
        float v = (f < FIN) ? feat[(size_t)n * FIN + f] : 0.f;
        split_bf16(v, &fhi[(size_t)n * FINB + f], &flo[(size_t)n * FINB + f]);
    }
}
__global__ void k_pack_w1t(const float* __restrict__ W1, bf16* __restrict__ whi,
                           bf16* __restrict__ wlo) {
    int n = blockIdx.x;  // 256
    for (int k = threadIdx.x; k < FINB; k += blockDim.x) {
        float v = (k < FIN) ? W1[(size_t)k * 256 + n] : 0.f;
        split_bf16(v, &whi[(size_t)n * FINB + k], &wlo[(size_t)n * FINB + k]);
    }
}
__global__ void k_pack_w2t(const float* __restrict__ W2, bf16* __restrict__ whi,
                           bf16* __restrict__ wlo) {
    int n = blockIdx.x;  // 128
    for (int k = threadIdx.x; k < 256; k += blockDim.x) {
        float v = W2[(size_t)k * 128 + n];
        split_bf16(v, &whi[(size_t)n * 256 + k], &wlo[(size_t)n * 256 + k]);
    }
}
__global__ void k_pack_w3t(const float* __restrict__ W3, bf16* __restrict__ whi,
                           bf16* __restrict__ wlo) {
    int f = blockIdx.x;  // NDEC rows
    int k = threadIdx.x; // 64
#pragma unroll
    for (int h = 0; h < 2; h++) {
        float v = (f < FIN) ? W3[(size_t)k * (2 * FIN) + h * FIN + f] : 0.f;
        split_bf16(v, &whi[((size_t)h * NDEC + f) * 64 + k], &wlo[((size_t)h * NDEC + f) * 64 + k]);
    }
}

// ================= attention logits =================
__global__ void k_elr(const float* __restrict__ hp, const float* __restrict__ al,
                      const float* __restrict__ ar, float* el, float* er, int D) {
    int w = (blockIdx.x * blockDim.x + threadIdx.x) >> 5;
    int lane = threadIdx.x & 31;
    if (w >= NN * 2) return;
    int n = w >> 1, h = w & 1;
    const float* row = hp + (size_t)n * (2 * D) + h * D;
    const float* a = al + h * D;
    const float* b = ar + h * D;
    float sl = 0.f, sr = 0.f;
    for (int d = lane; d < D; d += 32) { float x = row[d]; sl += x * a[d]; sr += x * b[d]; }
#pragma unroll
    for (int o = 16; o; o >>= 1) {
        sl += __shfl_down_sync(0xffffffffu, sl, o);
        sr += __shfl_down_sync(0xffffffffu, sr, o);
    }
    if (lane == 0) { el[w] = sl; er[w] = sr; }
}

__global__ void k_uv(const float* __restrict__ W3, const float* __restrict__ al3,
                     const float* __restrict__ ar3, float* uv) {
    int w = (blockIdx.x * blockDim.x + threadIdx.x) >> 5;
    int lane = threadIdx.x & 31;
    if (w >= 128) return;
    int h = w >> 6, k = w & 63;
    const float* Wr = W3 + (size_t)k * (2 * FIN) + h * FIN;
    const float* a = al3 + (size_t)h * FIN;
    const float* b = ar3 + (size_t)h * FIN;
    float su = 0.f, sv = 0.f;
    for (int f = lane; f < FIN; f += 32) { float ww = Wr[f]; su += ww * a[f]; sv += ww * b[f]; }
#pragma unroll
    for (int o = 16; o; o >>= 1) {
        su += __shfl_down_sync(0xffffffffu, su, o);
        sv += __shfl_down_sync(0xffffffffu, sv, o);
    }
    if (lane == 0) { uv[h * 64 + k] = su; uv[128 + h * 64 + k] = sv; }
}

__global__ void k_elr3(const float* __restrict__ h2, const float* __restrict__ uv,
                       float* el, float* er) {
    int w = (blockIdx.x * blockDim.x + threadIdx.x) >> 5;
    int lane = threadIdx.x & 31;
    if (w >= NN * 2) return;
    int n = w >> 1, h = w & 1;
    const float* row = h2 + (size_t)n * 64;
    const float* u = uv + h * 64;
    const float* v = uv + 128 + h * 64;
    float sl = 0.f, sr = 0.f;
    for (int d = lane; d < 64; d += 32) { float x = row[d]; sl += x * u[d]; sr += x * v[d]; }
#pragma unroll
    for (int o = 16; o; o >>= 1) {
        sl += __shfl_down_sync(0xffffffffu, sl, o);
        sr += __shfl_down_sync(0xffffffffu, sr, o);
    }
    if (lane == 0) { el[w] = sl; er[w] = sr; }
}

// ================= CSR softmax denominators =================
__global__ void k_sum(const int* __restrict__ rowptr, const int* __restrict__ csrsrc,
                      const float* __restrict__ el, const float* __restrict__ er,
                      float* __restrict__ sinv) {
    int d = blockIdx.x * (blockDim.x >> 5) + (threadIdx.x >> 5);
    int lane = threadIdx.x & 31;
    if (d >= NN) return;
    int b = rowptr[d], e = rowptr[d + 1];
    float2 r = *(const float2*)&er[d * 2];
    float s0 = 0.f, s1 = 0.f;
    for (int i = b + lane; i < e; i += 32) {
        int s = csrsrc[i];
        float2 l = *(const float2*)&el[s * 2];
        float e0 = l.x + r.x; e0 = e0 > 0.f ? e0 : 0.2f * e0;
        float e1 = l.y + r.y; e1 = e1 > 0.f ? e1 : 0.2f * e1;
        s0 += __expf(e0); s1 += __expf(e1);
    }
#pragma unroll
    for (int o = 16; o; o >>= 1) {
        s0 += __shfl_down_sync(0xffffffffu, s0, o);
        s1 += __shfl_down_sync(0xffffffffu, s1, o);
    }
    if (lane == 0) { sinv[d * 2] = 1.f / s0; sinv[d * 2 + 1] = 1.f / s1; }
}

// ================= CSR gather aggregation =================
__global__ void __launch_bounds__(256)
k_agg1(const int* __restrict__ rowptr, const int* __restrict__ csrsrc,
       const float* __restrict__ el, const float* __restrict__ er,
       const float* __restrict__ sinv, const float* __restrict__ hp,
       const float* __restrict__ b1, bf16* __restrict__ ohi, bf16* __restrict__ olo) {
    int d = blockIdx.x;
    int t = threadIdx.x;
    __shared__ float2 sal[128];
    __shared__ int ssrc[128];
    int b = rowptr[d], en = rowptr[d + 1];
    float2 r = *(const float2*)&er[d * 2];
    float2 inv = *(const float2*)&sinv[d * 2];
    float acc = 0.f;
    int h = t >> 7;
    for (int c = b; c < en; c += 128) {
        int cnt = min(128, en - c);
        __syncthreads();
        if (t < cnt) {
            int s = csrsrc[c + t];
            float2 l = *(const float2*)&el[s * 2];
            float e0 = l.x + r.x; e0 = e0 > 0.f ? e0 : 0.2f * e0;
            float e1 = l.y + r.y; e1 = e1 > 0.f ? e1 : 0.2f * e1;
            sal[t] = make_float2(__expf(e0) * inv.x, __expf(e1) * inv.y);
            ssrc[t] = s;
        }
        __syncthreads();
#pragma unroll 4
        for (int i = 0; i < cnt; i++) {
            float a = h ? sal[i].y : sal[i].x;
            acc = fmaf(a, hp[(size_t)ssrc[i] * 256 + t], acc);
        }
    }
    float x = lrelu(acc + b1[t], 0.01f);
    split_bf16(x, &ohi[(size_t)d * 256 + t], &olo[(size_t)d * 256 + t]);
}

__global__ void __launch_bounds__(128)
k_agg2(const int* __restrict__ rowptr, const int* __restrict__ csrsrc,
       const float* __restrict__ el, const float* __restrict__ er,
       const float* __restrict__ sinv, const float* __restrict__ hp,
       const float* __restrict__ b2, float* __restrict__ h2,
       bf16* __restrict__ h2hi, bf16* __restrict__ h2lo) {
    int d = blockIdx.x;
    int t = threadIdx.x;
    __shared__ float2 sal[128];
    __shared__ int ssrc[128];
    __shared__ float o[128];
    int b = rowptr[d], en = rowptr[d + 1];
    float2 r = *(const float2*)&er[d * 2];
    float2 inv = *(const float2*)&sinv[d * 2];
    float acc = 0.f;
    int h = t >> 6;
    for (int c = b; c < en; c += 128) {
        int cnt = min(128, en - c);
        __syncthreads();
        if (t < cnt) {
            int s = csrsrc[c + t];
            float2 l = *(const float2*)&el[s * 2];
            float e0 = l.x + r.x; e0 = e0 > 0.f ? e0 : 0.2f * e0;
            float e1 = l.y + r.y; e1 = e1 > 0.f ? e1 : 0.2f * e1;
            sal[t] = make_float2(__expf(e0) * inv.x, __expf(e1) * inv.y);
            ssrc[t] = s;
        }
        __syncthreads();
#pragma unroll 4
        for (int i = 0; i < cnt; i++) {
            float a = h ? sal[i].y : sal[i].x;
            acc = fmaf(a, hp[(size_t)ssrc[i] * 128 + t], acc);
        }
    }
    o[t] = acc;
    __syncthreads();
    if (t < 64) {
        float x0 = lrelu(o[t] + b2[t], 0.01f);
        float x1 = lrelu(o[64 + t] + b2[64 + t], 0.01f);
        float v = 0.5f * (x0 + x1);
        h2[(size_t)d * 64 + t] = v;
        split_bf16(v, &h2hi[(size_t)d * 64 + t], &h2lo[(size_t)d * 64 + t]);
    }
}

__global__ void __launch_bounds__(128)
k_agg3(const int* __restrict__ rowptr, const int* __restrict__ csrsrc,
       const float* __restrict__ el, const float* __restrict__ er,
       const float* __restrict__ sinv, const float* __restrict__ h2,
       bf16* __restrict__ ahi, bf16* __restrict__ alo) {
    int d = blockIdx.x;
    int t = threadIdx.x;
    __shared__ float2 sal[128];
    __shared__ int ssrc[128];
    int b = rowptr[d], en = rowptr[d + 1];
    float2 r = *(const float2*)&er[d * 2];
    float2 inv = *(const float2*)&sinv[d * 2];
    float acc = 0.f;
    int h = t >> 6, dd = t & 63;
    for (int c = b; c < en; c += 128) {
        int cnt = min(128, en - c);
        __syncthreads();
        if (t < cnt) {
            int s = csrsrc[c + t];
            float2 l = *(const float2*)&el[s * 2];
            float e0 = l.x + r.x; e0 = e0 > 0.f ? e0 : 0.2f * e0;
            float e1 = l.y + r.y; e1 = e1 > 0.f ? e1 : 0.2f * e1;
            sal[t] = make_float2(__expf(e0) * inv.x, __expf(e1) * inv.y);
            ssrc[t] = s;
        }
        __syncthreads();
#pragma unroll 4
        for (int i = 0; i < cnt; i++) {
            float a = h ? sal[i].y : sal[i].x;
            acc = fmaf(a, h2[(size_t)ssrc[i] * 64 + dd], acc);
        }
    }
    size_t idx = ((size_t)h * NN + d) * 64 + dd;
    split_bf16(acc, &ahi[idx], &alo[idx]);
}

// ================= launch =================
extern "C" void kernel_launch(void* const* d_in, const int* in_sizes, int n_in,
                              void* d_out, int out_size) {
    const float* feat = (const float*)d_in[0];
    const int* src = (const int*)d_in[1];
    const int* dst = (const int*)d_in[2];
    const float* W1 = (const float*)d_in[3];
    const float* al1 = (const float*)d_in[4];
    const float* ar1 = (const float*)d_in[5];
    const float* b1 = (const float*)d_in[6];
    const float* W2 = (const float*)d_in[7];
    const float* al2 = (const float*)d_in[8];
    const float* ar2 = (const float*)d_in[9];
    const float* b2 = (const float*)d_in[10];
    const float* W3 = (const float*)d_in[11];
    const float* al3 = (const float*)d_in[12];
    const float* ar3 = (const float*)d_in[13];
    const float* b3 = (const float*)d_in[14];

    float* a_hat = (float*)d_out;
    float* x_hat = a_hat + (size_t)NN * NN;
    const int E = in_sizes[1];

    bf16 *feathi, *featlo, *w1thi, *w1tlo, *w2thi, *w2tlo, *w3thi, *w3tlo;
    bf16 *agg1hi, *agg1lo, *h2hi, *h2lo, *agg3hi, *agg3lo;
    float *h1p, *h2p, *h2, *el, *er, *sinv, *uv;
    int *deg, *cursor, *rowptr, *csrsrc;
    cudaGetSymbolAddress((void**)&feathi, g_feathi);
    cudaGetSymbolAddress((void**)&featlo, g_featlo);
    cudaGetSymbolAddress((void**)&w1thi, g_w1thi);
    cudaGetSymbolAddress((void**)&w1tlo, g_w1tlo);
    cudaGetSymbolAddress((void**)&w2thi, g_w2thi);
    cudaGetSymbolAddress((void**)&w2tlo, g_w2tlo);
    cudaGetSymbolAddress((void**)&w3thi, g_w3thi);
    cudaGetSymbolAddress((void**)&w3tlo, g_w3tlo);
    cudaGetSymbolAddress((void**)&h1p, g_h1p);
    cudaGetSymbolAddress((void**)&agg1hi, g_agg1hi);
    cudaGetSymbolAddress((void**)&agg1lo, g_agg1lo);
    cudaGetSymbolAddress((void**)&h2p, g_h2p);
    cudaGetSymbolAddress((void**)&h2, g_h2);
    cudaGetSymbolAddress((void**)&h2hi, g_h2hi);
    cudaGetSymbolAddress((void**)&h2lo, g_h2lo);
    cudaGetSymbolAddress((void**)&agg3hi, g_agg3hi);
    cudaGetSymbolAddress((void**)&agg3lo, g_agg3lo);
    cudaGetSymbolAddress((void**)&el, g_el);
    cudaGetSymbolAddress((void**)&er, g_er);
    cudaGetSymbolAddress((void**)&sinv, g_sinv);
    cudaGetSymbolAddress((void**)&uv, g_uv);
    cudaGetSymbolAddress((void**)&deg, g_deg);
    cudaGetSymbolAddress((void**)&cursor, g_cursor);
    cudaGetSymbolAddress((void**)&rowptr, g_rowptr);
    cudaGetSymbolAddress((void**)&csrsrc, g_csrsrc);

    cudaFuncSetAttribute(ahat_hmma, cudaFuncAttributeMaxDynamicSharedMemorySize, AHAT_SMEM);
    cudaFuncSetAttribute(hmma_gemm, cudaFuncAttributeMaxDynamicSharedMemorySize, HG_SMEM);
    cudaFuncSetAttribute(dec_hmma, cudaFuncAttributeMaxDynamicSharedMemorySize, DEC_SMEM);

    // one-time stream/event setup (first call is the uncaptured correctness run)
    static cudaStream_t s1 = nullptr, s2 = nullptr;
    static cudaEvent_t evRoot, evCSR, evW, evH2, evAhat;
    if (s1 == nullptr) {
        cudaStreamCreateWithFlags(&s1, cudaStreamNonBlocking);
        cudaStreamCreateWithFlags(&s2, cudaStreamNonBlocking);
        cudaEventCreateWithFlags(&evRoot, cudaEventDisableTiming);
        cudaEventCreateWithFlags(&evCSR, cudaEventDisableTiming);
        cudaEventCreateWithFlags(&evW, cudaEventDisableTiming);
        cudaEventCreateWithFlags(&evH2, cudaEventDisableTiming);
        cudaEventCreateWithFlags(&evAhat, cudaEventDisableTiming);
    }

    float *el1 = el, *el2 = el + NN * 2, *el3 = el + 2 * NN * 2;
    float *er1 = er, *er2 = er + NN * 2, *er3 = er + 2 * NN * 2;
    float *sv1 = sinv, *sv2 = sinv + NN * 2, *sv3 = sinv + 2 * NN * 2;

    const int eb = (E + 255) / 256;

    // fork s1/s2 from the captured origin stream
    cudaEventRecord(evRoot, 0);
    cudaStreamWaitEvent(s1, evRoot, 0);
    cudaStreamWaitEvent(s2, evRoot, 0);

    // ---- s1: CSR build (needed first at k_sum1) ----
    k_zerodeg<<<(NN + 255) / 256, 256, 0, s1>>>(deg);
    k_deg<<<eb, 256, 0, s1>>>(dst, deg, E);
    k_scan<<<1, 256, 0, s1>>>(deg, rowptr, cursor);
    k_scatter<<<eb, 256, 0, s1>>>(src, dst, cursor, csrsrc, E);
    cudaEventRecord(evCSR, s1);

    // ---- s2: weight packs + decoder attention projection ----
    k_pack_w2t<<<128, 256, 0, s2>>>(W2, w2thi, w2tlo);
    k_pack_w3t<<<NDEC, 64, 0, s2>>>(W3, w3thi, w3tlo);
    k_uv<<<16, 256, 0, s2>>>(W3, al3, ar3, uv);
    cudaEventRecord(evW, s2);

    // ---- main stream: layer 1 ----
    k_pack_feat<<<NN, 256>>>(feat, feathi, featlo);
    k_pack_w1t<<<256, 256>>>(W1, w1thi, w1tlo);
    {
        dim3 grid(2, 64);
        hmma_gemm<<<grid, 256, HG_SMEM>>>(feathi, featlo, w1thi, w1tlo, h1p, FINB, FINB, FINB, 256);
    }
    k_elr<<<(NN * 2 * 32 + 255) / 256, 256>>>(h1p, al1, ar1, el1, er1, 128);
    cudaStreamWaitEvent(0, evCSR, 0);
    k_sum<<<NN / 8, 256>>>(rowptr, csrsrc, el1, er1, sv1);
    k_agg1<<<NN, 256>>>(rowptr, csrsrc, el1, er1, sv1, h1p, b1, agg1hi, agg1lo);

    // ---- layer 2 ----
    cudaStreamWaitEvent(0, evW, 0);
    {
        dim3 grid(1, 64);
        hmma_gemm<<<grid, 256, HG_SMEM>>>(agg1hi, agg1lo, w2thi, w2tlo, h2p, 256, 256, 256, 128);
    }
    k_elr<<<(NN * 2 * 32 + 255) / 256, 256>>>(h2p, al2, ar2, el2, er2, 64);
    k_sum<<<NN / 8, 256>>>(rowptr, csrsrc, el2, er2, sv2);
    k_agg2<<<NN, 128>>>(rowptr, csrsrc, el2, er2, sv2, h2p, b2, h2, h2hi, h2lo);
    cudaEventRecord(evH2, 0);

    // ---- s1: structure decoder a_hat (overlaps with attribute decoder below) ----
    cudaStreamWaitEvent(s1, evH2, 0);
    {
        dim3 grid(NN / 128, NN / 128);
        ahat_hmma<<<grid, 256, AHAT_SMEM, s1>>>(h2hi, h2lo, a_hat);
    }
    cudaEventRecord(evAhat, s1);

    // ---- main stream: attribute decoder ----
    k_elr3<<<(NN * 2 * 32 + 255) / 256, 256>>>(h2, uv, el3, er3);
    k_sum<<<NN / 8, 256>>>(rowptr, csrsrc, el3, er3, sv3);
    k_agg3<<<NN, 128>>>(rowptr, csrsrc, el3, er3, sv3, h2, agg3hi, agg3lo);
    {
        dim3 grid(NDEC / 64, NN / 128);
        dec_hmma<<<grid, 256, DEC_SMEM>>>(agg3hi, agg3lo, w3thi, w3tlo, b3, x_hat);
    }

    // join
    cudaStreamWaitEvent(0, evAhat, 0);
}

// round 8
// speedup vs baseline: 4.2046x; 1.1518x over previous
#include <cuda_runtime.h>
#include <cuda_bf16.h>
#include <cstdint>

#define NN 8192
#define FIN 1433
#define FINB 1472      // FIN padded to multiple of 64
#define NDEC 1536      // decoder N padded to multiple of 64
#define MAXE (1 << 20)

typedef unsigned long long u64t;
typedef __nv_bfloat16 bf16;

// ---------------- scratch (device globals) ----------------
__device__ bf16 g_feathi[NN * FINB];
__device__ bf16 g_featlo[NN * FINB];
__device__ bf16 g_w1thi[256 * FINB];
__device__ bf16 g_w1tlo[256 * FINB];
__device__ bf16 g_w2thi[128 * 256];
__device__ bf16 g_w2tlo[128 * 256];
__device__ bf16 g_w3thi[2 * NDEC * 64];
__device__ bf16 g_w3tlo[2 * NDEC * 64];
__device__ float g_h1p[NN * 256];
__device__ bf16 g_agg1hi[NN * 256];
__device__ bf16 g_agg1lo[NN * 256];
__device__ float g_h2p[NN * 128];
__device__ float g_h2[NN * 64];
__device__ bf16 g_h2hi[NN * 64];
__device__ bf16 g_h2lo[NN * 64];
__device__ bf16 g_agg3hi[2 * NN * 64];
__device__ bf16 g_agg3lo[2 * NN * 64];
__device__ float g_el[3 * NN * 2];
__device__ float g_er[3 * NN * 2];
__device__ float g_uv[2 * 64 * 2];
__device__ int g_deg[NN];
__device__ int g_cursor[NN];
__device__ int g_rowptr[NN + 1];
__device__ int g_csrsrc[MAXE];

__device__ __forceinline__ float lrelu(float x, float a) { return x > 0.f ? x : a * x; }

__device__ __forceinline__ uint32_t smem_u32(const void* p) {
    uint32_t a;
    asm("{ .reg .u64 t; cvta.to.shared.u64 t, %1; cvt.u32.u64 %0, t; }" : "=r"(a) : "l"(p));
    return a;
}
__device__ __forceinline__ void ldm_x4(uint32_t* r, uint32_t addr) {
    asm volatile("ldmatrix.sync.aligned.m8n8.x4.shared.b16 {%0,%1,%2,%3}, [%4];"
                 : "=r"(r[0]), "=r"(r[1]), "=r"(r[2]), "=r"(r[3]) : "r"(addr));
}
__device__ __forceinline__ void mma_bf16(float* c, const uint32_t* a, uint32_t b0, uint32_t b1) {
    asm volatile(
        "mma.sync.aligned.m16n8k16.row.col.f32.bf16.bf16.f32 "
        "{%0,%1,%2,%3}, {%4,%5,%6,%7}, {%8,%9}, {%0,%1,%2,%3};"
        : "+f"(c[0]), "+f"(c[1]), "+f"(c[2]), "+f"(c[3])
        : "r"(a[0]), "r"(a[1]), "r"(a[2]), "r"(a[3]), "r"(b0), "r"(b1));
}
__device__ __forceinline__ void split_bf16(float v, bf16* hi, bf16* lo) {
    bf16 h = __float2bfloat16(v);
    *hi = h;
    *lo = __float2bfloat16(v - __bfloat162float(h));
}
__device__ __forceinline__ void cp16(uint32_t dst, const void* src) {
    asm volatile("cp.async.cg.shared.global [%0], [%1], 16;" :: "r"(dst), "l"(src));
}

#define APITCH 72  // bf16 per smem row (144B) — conflict-free ldmatrix
#define TILEB 18432  // one 128xAPITCH bf16 tile in bytes

// ================= generic bf16-split HMMA GEMM, cp.async double-buffered =================
#define HG_SMEM (8 * TILEB)  // 147456 B (two buffer sets of 4 tiles)

__global__ void __launch_bounds__(256)
hmma_gemm(const bf16* __restrict__ Ahi, const bf16* __restrict__ Alo,
          const bf16* __restrict__ Bhi, const bf16* __restrict__ Blo,
          float* __restrict__ C, int K, int lda, int ldb, int ldc) {
    extern __shared__ char smem[];
    const uint32_t sb = smem_u32(smem);
    const int tid = threadIdx.x, wid = tid >> 5, lane = tid & 31;
    const int rowBase = blockIdx.y * 128, colBase = blockIdx.x * 128;
    const int wm = (wid & 3) * 32, wn = (wid >> 2) * 64;
    const int lrow = lane & 15, lch = lane >> 4;
    const int nk = K >> 6;

    float acc[2][8][4];
#pragma unroll
    for (int i = 0; i < 2; i++)
#pragma unroll
        for (int j = 0; j < 8; j++)
#pragma unroll
            for (int q = 0; q < 4; q++) acc[i][j][q] = 0.f;

    auto stage = [&](int buf, int kc) {
        uint32_t base = sb + buf * (4 * TILEB);
        for (int idx = tid; idx < 1024; idx += 256) {
            int row = idx >> 3, ch = idx & 7;
            uint32_t off = (uint32_t)(row * APITCH + ch * 8) * 2;
            cp16(base + off, Ahi + (size_t)(rowBase + row) * lda + kc + ch * 8);
            cp16(base + TILEB + off, Alo + (size_t)(rowBase + row) * lda + kc + ch * 8);
            cp16(base + 2 * TILEB + off, Bhi + (size_t)(colBase + row) * ldb + kc + ch * 8);
            cp16(base + 3 * TILEB + off, Blo + (size_t)(colBase + row) * ldb + kc + ch * 8);
        }
        asm volatile("cp.async.commit_group;" ::: "memory");
    };

    stage(0, 0);
    for (int t = 0; t < nk; ++t) {
        asm volatile("cp.async.wait_group 0;" ::: "memory");
        __syncthreads();
        if (t + 1 < nk) stage((t + 1) & 1, (t + 1) * 64);
        const uint32_t base = sb + (t & 1) * (4 * TILEB);
        const uint32_t bAhi = base, bAlo = base + TILEB;
        const uint32_t bBhi = base + 2 * TILEB, bBlo = base + 3 * TILEB;
#pragma unroll
        for (int ks = 0; ks < 4; ks++) {
            uint32_t afh[2][4], afl[2][4];
#pragma unroll
            for (int i = 0; i < 2; i++) {
                uint32_t ao = ((wm + i * 16 + lrow) * APITCH) * 2 + (ks * 2 + lch) * 16;
                ldm_x4(afh[i], bAhi + ao);
                ldm_x4(afl[i], bAlo + ao);
            }
            uint32_t bfh[8][2], bfl[8][2];
#pragma unroll
            for (int jj = 0; jj < 4; jj++) {
                uint32_t bo = ((wn + jj * 16 + lrow) * APITCH) * 2 + (ks * 2 + lch) * 16;
                uint32_t r[4];
                ldm_x4(r, bBhi + bo);
                bfh[2 * jj][0] = r[0]; bfh[2 * jj][1] = r[2];
                bfh[2 * jj + 1][0] = r[1]; bfh[2 * jj + 1][1] = r[3];
                ldm_x4(r, bBlo + bo);
                bfl[2 * jj][0] = r[0]; bfl[2 * jj][1] = r[2];
                bfl[2 * jj + 1][0] = r[1]; bfl[2 * jj + 1][1] = r[3];
            }
#pragma unroll
            for (int i = 0; i < 2; i++)
#pragma unroll
                for (int j = 0; j < 8; j++) {
                    mma_bf16(acc[i][j], afh[i], bfh[j][0], bfh[j][1]);
                    mma_bf16(acc[i][j], afh[i], bfl[j][0], bfl[j][1]);
                    mma_bf16(acc[i][j], afl[i], bfh[j][0], bfh[j][1]);
                }
        }
        __syncthreads();
    }

    const int rr = lane >> 2, cc = (lane & 3) * 2;
#pragma unroll
    for (int i = 0; i < 2; i++) {
        int gr = rowBase + wm + i * 16 + rr;
        float* out0 = C + (size_t)gr * ldc + colBase + wn + cc;
        float* out1 = out0 + 8 * ldc;
#pragma unroll
        for (int j = 0; j < 8; j++) {
            *(float2*)(out0 + j * 8) = make_float2(acc[i][j][0], acc[i][j][1]);
            *(float2*)(out1 + j * 8) = make_float2(acc[i][j][2], acc[i][j][3]);
        }
    }
}

// ================= a_hat HMMA (128x128, K=64) =================
#define AHAT_SMEM (4 * TILEB)

__global__ void __launch_bounds__(256)
ahat_hmma(const bf16* __restrict__ hi, const bf16* __restrict__ lo, float* __restrict__ C) {
    extern __shared__ char smem[];
    bf16* sAhi = (bf16*)(smem);
    bf16* sAlo = (bf16*)(smem + TILEB);
    bf16* sBhi = (bf16*)(smem + 2 * TILEB);
    bf16* sBlo = (bf16*)(smem + 3 * TILEB);
    const int tid = threadIdx.x, wid = tid >> 5, lane = tid & 31;
    const int rowBase = blockIdx.y * 128, colBase = blockIdx.x * 128;

    for (int idx = tid; idx < 128 * 8; idx += 256) {
        int row = idx >> 3, ch = idx & 7;
        int off = row * APITCH + ch * 8;
        *(uint4*)(sAhi + off) = *((const uint4*)(hi + (size_t)(rowBase + row) * 64) + ch);
        *(uint4*)(sAlo + off) = *((const uint4*)(lo + (size_t)(rowBase + row) * 64) + ch);
        *(uint4*)(sBhi + off) = *((const uint4*)(hi + (size_t)(colBase + row) * 64) + ch);
        *(uint4*)(sBlo + off) = *((const uint4*)(lo + (size_t)(colBase + row) * 64) + ch);
    }
    __syncthreads();

    const int wm = (wid & 3) * 32, wn = (wid >> 2) * 64;
    float acc[2][8][4];
#pragma unroll
    for (int i = 0; i < 2; i++)
#pragma unroll
        for (int j = 0; j < 8; j++)
#pragma unroll
            for (int q = 0; q < 4; q++) acc[i][j][q] = 0.f;

    const int lrow = lane & 15, lch = lane >> 4;
    const uint32_t sbAhi = smem_u32(sAhi), sbAlo = smem_u32(sAlo);
    const uint32_t sbBhi = smem_u32(sBhi), sbBlo = smem_u32(sBlo);

#pragma unroll
    for (int pass = 0; pass < 3; pass++) {
        const uint32_t aBase = (pass == 2) ? sbAlo : sbAhi;
        const uint32_t bBase = (pass == 1) ? sbBlo : sbBhi;
#pragma unroll
        for (int ks = 0; ks < 4; ks++) {
            uint32_t af[2][4];
#pragma unroll
            for (int i = 0; i < 2; i++)
                ldm_x4(af[i], aBase + ((wm + i * 16 + lrow) * APITCH) * 2 + (ks * 2 + lch) * 16);
            uint32_t bf[8][2];
#pragma unroll
            for (int jj = 0; jj < 4; jj++) {
                uint32_t r[4];
                ldm_x4(r, bBase + ((wn + jj * 16 + lrow) * APITCH) * 2 + (ks * 2 + lch) * 16);
                bf[2 * jj][0] = r[0]; bf[2 * jj][1] = r[2];
                bf[2 * jj + 1][0] = r[1]; bf[2 * jj + 1][1] = r[3];
            }
#pragma unroll
            for (int i = 0; i < 2; i++)
#pragma unroll
                for (int j = 0; j < 8; j++)
                    mma_bf16(acc[i][j], af[i], bf[j][0], bf[j][1]);
        }
    }

    const int rr = lane >> 2, cc = (lane & 3) * 2;
#pragma unroll
    for (int i = 0; i < 2; i++) {
        int gr = rowBase + wm + i * 16 + rr;
        float* out0 = C + (size_t)gr * NN + colBase + wn + cc;
        float* out1 = out0 + 8 * NN;
#pragma unroll
        for (int j = 0; j < 8; j++) {
            *(float2*)(out0 + j * 8) = make_float2(acc[i][j][0], acc[i][j][1]);
            *(float2*)(out1 + j * 8) = make_float2(acc[i][j][2], acc[i][j][3]);
        }
    }
}

// ================= fused decoder HMMA (2 heads + bias + lrelu + mean) =================
#define DEC_SMEM (2 * TILEB + TILEB)  // A hi/lo 128-row + B hi/lo 64-row

__global__ void __launch_bounds__(256)
dec_hmma(const bf16* __restrict__ Ahi, const bf16* __restrict__ Alo,
         const bf16* __restrict__ Bhi, const bf16* __restrict__ Blo,
         const float* __restrict__ b3, float* __restrict__ xhat) {
    extern __shared__ char smem[];
    bf16* sAhi = (bf16*)smem;
    bf16* sAlo = (bf16*)(smem + TILEB);
    bf16* sBhi = (bf16*)(smem + 2 * TILEB);
    bf16* sBlo = (bf16*)(smem + 2 * TILEB + TILEB / 2);
    const int tid = threadIdx.x, wid = tid >> 5, lane = tid & 31;
    const int rowBase = blockIdx.y * 128, colBase = blockIdx.x * 64;
    const int wm = (wid & 3) * 32, wn = (wid >> 2) * 32;
    const int lrow = lane & 15, lch = lane >> 4;

    float acc[2][2][4][4];
#pragma unroll
    for (int h = 0; h < 2; h++)
#pragma unroll
        for (int i = 0; i < 2; i++)
#pragma unroll
            for (int j = 0; j < 4; j++)
#pragma unroll
                for (int q = 0; q < 4; q++) acc[h][i][j][q] = 0.f;

    const uint32_t sbAhi = smem_u32(sAhi), sbAlo = smem_u32(sAlo);
    const uint32_t sbBhi = smem_u32(sBhi), sbBlo = smem_u32(sBlo);

#pragma unroll
    for (int h = 0; h < 2; h++) {
        const bf16* ahp = Ahi + (size_t)h * NN * 64;
        const bf16* alp = Alo + (size_t)h * NN * 64;
        const bf16* bhp = Bhi + (size_t)h * NDEC * 64;
        const bf16* blp = Blo + (size_t)h * NDEC * 64;
        __syncthreads();
        for (int idx = tid; idx < 1024; idx += 256) {
            int row = idx >> 3, ch = idx & 7;
            int off = row * APITCH + ch * 8;
            *(uint4*)(sAhi + off) = *(const uint4*)(ahp + (size_t)(rowBase + row) * 64 + ch * 8);
            *(uint4*)(sAlo + off) = *(const uint4*)(alp + (size_t)(rowBase + row) * 64 + ch * 8);
        }
        for (int idx = tid; idx < 512; idx += 256) {
            int row = idx >> 3, ch = idx & 7;
            int off = row * APITCH + ch * 8;
            *(uint4*)(sBhi + off) = *(const uint4*)(bhp + (size_t)(colBase + row) * 64 + ch * 8);
            *(uint4*)(sBlo + off) = *(const uint4*)(blp + (size_t)(colBase + row) * 64 + ch * 8);
        }
        __syncthreads();
#pragma unroll
        for (int ks = 0; ks < 4; ks++) {
            uint32_t afh[2][4], afl[2][4];
#pragma unroll
            for (int i = 0; i < 2; i++) {
                uint32_t ao = ((wm + i * 16 + lrow) * APITCH) * 2 + (ks * 2 + lch) * 16;
                ldm_x4(afh[i], sbAhi + ao);
                ldm_x4(afl[i], sbAlo + ao);
            }
            uint32_t bfh[4][2], bfl[4][2];
#pragma unroll
            for (int jj = 0; jj < 2; jj++) {
                uint32_t bo = ((wn + jj * 16 + lrow) * APITCH) * 2 + (ks * 2 + lch) * 16;
                uint32_t r[4];
                ldm_x4(r, sbBhi + bo);
                bfh[2 * jj][0] = r[0]; bfh[2 * jj][1] = r[2];
                bfh[2 * jj + 1][0] = r[1]; bfh[2 * jj + 1][1] = r[3];
                ldm_x4(r, sbBlo + bo);
                bfl[2 * jj][0] = r[0]; bfl[2 * jj][1] = r[2];
                bfl[2 * jj + 1][0] = r[1]; bfl[2 * jj + 1][1] = r[3];
            }
#pragma unroll
            for (int i = 0; i < 2; i++)
#pragma unroll
                for (int j = 0; j < 4; j++) {
                    mma_bf16(acc[h][i][j], afh[i], bfh[j][0], bfh[j][1]);
                    mma_bf16(acc[h][i][j], afh[i], bfl[j][0], bfl[j][1]);
                    mma_bf16(acc[h][i][j], afl[i], bfh[j][0], bfh[j][1]);
                }
        }
    }

    const int rr = lane >> 2, cc = (lane & 3) * 2;
#pragma unroll
    for (int i = 0; i < 2; i++) {
#pragma unroll
        for (int j = 0; j < 4; j++) {
#pragma unroll
            for (int half = 0; half < 2; half++) {
                int gr = rowBase + wm + i * 16 + rr + half * 8;
                int gn = colBase + wn + j * 8 + cc;
                if (gn < FIN) {
                    float v0 = acc[0][i][j][half * 2], v1 = acc[1][i][j][half * 2];
                    xhat[(size_t)gr * FIN + gn] =
                        0.5f * (lrelu(v0 + b3[gn], 0.01f) + lrelu(v1 + b3[FIN + gn], 0.01f));
                }
                if (gn + 1 < FIN) {
                    float v0 = acc[0][i][j][half * 2 + 1], v1 = acc[1][i][j][half * 2 + 1];
                    xhat[(size_t)gr * FIN + gn + 1] =
                        0.5f * (lrelu(v0 + b3[gn + 1], 0.01f) + lrelu(v1 + b3[FIN + gn + 1], 0.01f));
                }
            }
        }
    }
}

// ================= CSR build =================
__global__ void k_zerodeg(int* deg) {
    int i = blockIdx.x * blockDim.x + threadIdx.x;
    if (i < NN) deg[i] = 0;
}
__global__ void k_deg(const int* __restrict__ dst, int* deg, int E) {
    int e = blockIdx.x * blockDim.x + threadIdx.x;
    if (e < E) atomicAdd(&deg[dst[e]], 1);
}
__global__ void k_scan(const int* __restrict__ deg, int* rowptr, int* cursor) {
    __shared__ int partx[257];
    int t = threadIdx.x;
    int base = t * 32;
    int loc[32];
    int s = 0;
#pragma unroll
    for (int i = 0; i < 32; i++) { loc[i] = s; s += deg[base + i]; }
    __shared__ int part[256];
    part[t] = s;
    __syncthreads();
    if (t == 0) {
        int acc = 0;
        for (int i = 0; i < 256; i++) { partx[i] = acc; acc += part[i]; }
        partx[256] = acc;
    }
    __syncthreads();
    int off = partx[t];
#pragma unroll
    for (int i = 0; i < 32; i++) {
        int v = off + loc[i];
        rowptr[base + i] = v;
        cursor[base + i] = v;
    }
    if (t == 0) rowptr[NN] = partx[256];
}
__global__ void k_scatter(const int* __restrict__ src, const int* __restrict__ dst,
                          int* cursor, int* csrsrc, int E) {
    int e = blockIdx.x * blockDim.x + threadIdx.x;
    if (e >= E) return;
    int d = dst[e];
    int idx = atomicAdd(&cursor[d], 1);
    csrsrc[idx] = src[e];
}

// ================= pack kernels (split + transpose) =================
__global__ void k_pack_feat(const float* __restrict__ feat, bf16* __restrict__ fhi,
                            bf16* __restrict__ flo) {
    int n = blockIdx.x;
    for (int f = threadIdx.x; f < FINB; f += blockDim.x) {
        float v = (f < FIN) ? feat[(size_t)n * FIN + f] : 0.f;
        split_bf16(v, &fhi[(size_t)n * FINB + f], &flo[(size_t)n * FINB + f]);
    }
}
__global__ void k_pack_w1t(const float* __restrict__ W1, bf16* __restrict__ whi,
                           bf16* __restrict__ wlo) {
    int n = blockIdx.x;  // 256
    for (int k = threadIdx.x; k < FINB; k += blockDim.x) {
        float v = (k < FIN) ? W1[(size_t)k * 256 + n] : 0.f;
        split_bf16(v, &whi[(size_t)n * FINB + k], &wlo[(size_t)n * FINB + k]);
    }
}
__global__ void k_pack_w2t(const float* __restrict__ W2, bf16* __restrict__ whi,
                           bf16* __restrict__ wlo) {
    int n = blockIdx.x;  // 128
    for (int k = threadIdx.x; k < 256; k += blockDim.x) {
        float v = W2[(size_t)k * 128 + n];
        split_bf16(v, &whi[(size_t)n * 256 + k], &wlo[(size_t)n * 256 + k]);
    }
}
__global__ void k_pack_w3t(const float* __restrict__ W3, bf16* __restrict__ whi,
                           bf16* __restrict__ wlo) {
    int f = blockIdx.x;  // NDEC rows
    int k = threadIdx.x; // 64
#pragma unroll
    for (int h = 0; h < 2; h++) {
        float v = (f < FIN) ? W3[(size_t)k * (2 * FIN) + h * FIN + f] : 0.f;
        split_bf16(v, &whi[((size_t)h * NDEC + f) * 64 + k], &wlo[((size_t)h * NDEC + f) * 64 + k]);
    }
}

// ================= attention logits =================
__global__ void k_elr(const float* __restrict__ hp, const float* __restrict__ al,
                      const float* __restrict__ ar, float* el, float* er, int D) {
    int w = (blockIdx.x * blockDim.x + threadIdx.x) >> 5;
    int lane = threadIdx.x & 31;
    if (w >= NN * 2) return;
    int n = w >> 1, h = w & 1;
    const float* row = hp + (size_t)n * (2 * D) + h * D;
    const float* a = al + h * D;
    const float* b = ar + h * D;
    float sl = 0.f, sr = 0.f;
    for (int d = lane; d < D; d += 32) { float x = row[d]; sl += x * a[d]; sr += x * b[d]; }
#pragma unroll
    for (int o = 16; o; o >>= 1) {
        sl += __shfl_down_sync(0xffffffffu, sl, o);
        sr += __shfl_down_sync(0xffffffffu, sr, o);
    }
    if (lane == 0) { el[w] = sl; er[w] = sr; }
}

__global__ void k_uv(const float* __restrict__ W3, const float* __restrict__ al3,
                     const float* __restrict__ ar3, float* uv) {
    int w = (blockIdx.x * blockDim.x + threadIdx.x) >> 5;
    int lane = threadIdx.x & 31;
    if (w >= 128) return;
    int h = w >> 6, k = w & 63;
    const float* Wr = W3 + (size_t)k * (2 * FIN) + h * FIN;
    const float* a = al3 + (size_t)h * FIN;
    const float* b = ar3 + (size_t)h * FIN;
    float su = 0.f, sv = 0.f;
    for (int f = lane; f < FIN; f += 32) { float ww = Wr[f]; su += ww * a[f]; sv += ww * b[f]; }
#pragma unroll
    for (int o = 16; o; o >>= 1) {
        su += __shfl_down_sync(0xffffffffu, su, o);
        sv += __shfl_down_sync(0xffffffffu, sv, o);
    }
    if (lane == 0) { uv[h * 64 + k] = su; uv[128 + h * 64 + k] = sv; }
}

__global__ void k_elr3(const float* __restrict__ h2, const float* __restrict__ uv,
                       float* el, float* er) {
    int w = (blockIdx.x * blockDim.x + threadIdx.x) >> 5;
    int lane = threadIdx.x & 31;
    if (w >= NN * 2) return;
    int n = w >> 1, h = w & 1;
    const float* row = h2 + (size_t)n * 64;
    const float* u = uv + h * 64;
    const float* v = uv + 128 + h * 64;
    float sl = 0.f, sr = 0.f;
    for (int d = lane; d < 64; d += 32) { float x = row[d]; sl += x * u[d]; sr += x * v[d]; }
#pragma unroll
    for (int o = 16; o; o >>= 1) {
        sl += __shfl_down_sync(0xffffffffu, sl, o);
        sr += __shfl_down_sync(0xffffffffu, sr, o);
    }
    if (lane == 0) { el[w] = sl; er[w] = sr; }
}

// ================= block softmax-sum helper (fused into agg kernels) =================
// computes 1/sum of exp(lrelu(el[src]+er[d])) over this dst's edges; NT = blockDim
template <int NT>
__device__ __forceinline__ float2 block_inv_sum(const int* csrsrc, int b, int en,
                                                const float* el, float2 r,
                                                float* red, float2* out_sh) {
    int t = threadIdx.x, lane = t & 31, wid = t >> 5;
    float p0 = 0.f, p1 = 0.f;
    for (int i = b + t; i < en; i += NT) {
        int s = csrsrc[i];
        float2 l = *(const float2*)&el[s * 2];
        float e0 = l.x + r.x; e0 = e0 > 0.f ? e0 : 0.2f * e0;
        float e1 = l.y + r.y; e1 = e1 > 0.f ? e1 : 0.2f * e1;
        p0 += __expf(e0); p1 += __expf(e1);
    }
#pragma unroll
    for (int o = 16; o; o >>= 1) {
        p0 += __shfl_down_sync(0xffffffffu, p0, o);
        p1 += __shfl_down_sync(0xffffffffu, p1, o);
    }
    if (lane == 0) { red[wid * 2] = p0; red[wid * 2 + 1] = p1; }
    __syncthreads();
    if (t == 0) {
        float s0 = 0.f, s1 = 0.f;
        for (int w = 0; w < NT / 32; w++) { s0 += red[w * 2]; s1 += red[w * 2 + 1]; }
        *out_sh = make_float2(1.f / s0, 1.f / s1);
    }
    __syncthreads();
    return *out_sh;
}

// ================= CSR gather aggregation (sum fused) =================
__global__ void __launch_bounds__(256)
k_agg1(const int* __restrict__ rowptr, const int* __restrict__ csrsrc,
       const float* __restrict__ el, const float* __restrict__ er,
       const float* __restrict__ hp, const float* __restrict__ b1,
       bf16* __restrict__ ohi, bf16* __restrict__ olo) {
    int d = blockIdx.x;
    int t = threadIdx.x;
    __shared__ float2 sal[128];
    __shared__ int ssrc[128];
    __shared__ float red[16];
    __shared__ float2 inv_sh;
    int b = rowptr[d], en = rowptr[d + 1];
    float2 r = *(const float2*)&er[d * 2];
    float2 inv = block_inv_sum<256>(csrsrc, b, en, el, r, red, &inv_sh);
    float acc = 0.f;
    int h = t >> 7;
    for (int c = b; c < en; c += 128) {
        int cnt = min(128, en - c);
        __syncthreads();
        if (t < cnt) {
            int s = csrsrc[c + t];
            float2 l = *(const float2*)&el[s * 2];
            float e0 = l.x + r.x; e0 = e0 > 0.f ? e0 : 0.2f * e0;
            float e1 = l.y + r.y; e1 = e1 > 0.f ? e1 : 0.2f * e1;
            sal[t] = make_float2(__expf(e0) * inv.x, __expf(e1) * inv.y);
            ssrc[t] = s;
        }
        __syncthreads();
#pragma unroll 4
        for (int i = 0; i < cnt; i++) {
            float a = h ? sal[i].y : sal[i].x;
            acc = fmaf(a, hp[(size_t)ssrc[i] * 256 + t], acc);
        }
    }
    float x = lrelu(acc + b1[t], 0.01f);
    split_bf16(x, &ohi[(size_t)d * 256 + t], &olo[(size_t)d * 256 + t]);
}

__global__ void __launch_bounds__(128)
k_agg2(const int* __restrict__ rowptr, const int* __restrict__ csrsrc,
       const float* __restrict__ el, const float* __restrict__ er,
       const float* __restrict__ hp, const float* __restrict__ b2,
       float* __restrict__ h2, bf16* __restrict__ h2hi, bf16* __restrict__ h2lo) {
    int d = blockIdx.x;
    int t = threadIdx.x;
    __shared__ float2 sal[128];
    __shared__ int ssrc[128];
    __shared__ float o[128];
    __shared__ float red[8];
    __shared__ float2 inv_sh;
    int b = rowptr[d], en = rowptr[d + 1];
    float2 r = *(const float2*)&er[d * 2];
    float2 inv = block_inv_sum<128>(csrsrc, b, en, el, r, red, &inv_sh);
    float acc = 0.f;
    int h = t >> 6;
    for (int c = b; c < en; c += 128) {
        int cnt = min(128, en - c);
        __syncthreads();
        if (t < cnt) {
            int s = csrsrc[c + t];
            float2 l = *(const float2*)&el[s * 2];
            float e0 = l.x + r.x; e0 = e0 > 0.f ? e0 : 0.2f * e0;
            float e1 = l.y + r.y; e1 = e1 > 0.f ? e1 : 0.2f * e1;
            sal[t] = make_float2(__expf(e0) * inv.x, __expf(e1) * inv.y);
            ssrc[t] = s;
        }
        __syncthreads();
#pragma unroll 4
        for (int i = 0; i < cnt; i++) {
            float a = h ? sal[i].y : sal[i].x;
            acc = fmaf(a, hp[(size_t)ssrc[i] * 128 + t], acc);
        }
    }
    o[t] = acc;
    __syncthreads();
    if (t < 64) {
        float x0 = lrelu(o[t] + b2[t], 0.01f);
        float x1 = lrelu(o[64 + t] + b2[64 + t], 0.01f);
        float v = 0.5f * (x0 + x1);
        h2[(size_t)d * 64 + t] = v;
        split_bf16(v, &h2hi[(size_t)d * 64 + t], &h2lo[(size_t)d * 64 + t]);
    }
}

__global__ void __launch_bounds__(128)
k_agg3(const int* __restrict__ rowptr, const int* __restrict__ csrsrc,
       const float* __restrict__ el, const float* __restrict__ er,
       const float* __restrict__ h2, bf16* __restrict__ ahi, bf16* __restrict__ alo) {
    int d = blockIdx.x;
    int t = threadIdx.x;
    __shared__ float2 sal[128];
    __shared__ int ssrc[128];
    __shared__ float red[8];
    __shared__ float2 inv_sh;
    int b = rowptr[d], en = rowptr[d + 1];
    float2 r = *(const float2*)&er[d * 2];
    float2 inv = block_inv_sum<128>(csrsrc, b, en, el, r, red, &inv_sh);
    float acc = 0.f;
    int h = t >> 6, dd = t & 63;
    for (int c = b; c < en; c += 128) {
        int cnt = min(128, en - c);
        __syncthreads();
        if (t < cnt) {
            int s = csrsrc[c + t];
            float2 l = *(const float2*)&el[s * 2];
            float e0 = l.x + r.x; e0 = e0 > 0.f ? e0 : 0.2f * e0;
            float e1 = l.y + r.y; e1 = e1 > 0.f ? e1 : 0.2f * e1;
            sal[t] = make_float2(__expf(e0) * inv.x, __expf(e1) * inv.y);
            ssrc[t] = s;
        }
        __syncthreads();
#pragma unroll 4
        for (int i = 0; i < cnt; i++) {
            float a = h ? sal[i].y : sal[i].x;
            acc = fmaf(a, h2[(size_t)ssrc[i] * 64 + dd], acc);
        }
    }
    size_t idx = ((size_t)h * NN + d) * 64 + dd;
    split_bf16(acc, &ahi[idx], &alo[idx]);
}

// ================= launch =================
extern "C" void kernel_launch(void* const* d_in, const int* in_sizes, int n_in,
                              void* d_out, int out_size) {
    const float* feat = (const float*)d_in[0];
    const int* src = (const int*)d_in[1];
    const int* dst = (const int*)d_in[2];
    const float* W1 = (const float*)d_in[3];
    const float* al1 = (const float*)d_in[4];
    const float* ar1 = (const float*)d_in[5];
    const float* b1 = (const float*)d_in[6];
    const float* W2 = (const float*)d_in[7];
    const float* al2 = (const float*)d_in[8];
    const float* ar2 = (const float*)d_in[9];
    const float* b2 = (const float*)d_in[10];
    const float* W3 = (const float*)d_in[11];
    const float* al3 = (const float*)d_in[12];
    const float* ar3 = (const float*)d_in[13];
    const float* b3 = (const float*)d_in[14];

    float* a_hat = (float*)d_out;
    float* x_hat = a_hat + (size_t)NN * NN;
    const int E = in_sizes[1];

    bf16 *feathi, *featlo, *w1thi, *w1tlo, *w2thi, *w2tlo, *w3thi, *w3tlo;
    bf16 *agg1hi, *agg1lo, *h2hi, *h2lo, *agg3hi, *agg3lo;
    float *h1p, *h2p, *h2, *el, *er, *uv;
    int *deg, *cursor, *rowptr, *csrsrc;
    cudaGetSymbolAddress((void**)&feathi, g_feathi);
    cudaGetSymbolAddress((void**)&featlo, g_featlo);
    cudaGetSymbolAddress((void**)&w1thi, g_w1thi);
    cudaGetSymbolAddress((void**)&w1tlo, g_w1tlo);
    cudaGetSymbolAddress((void**)&w2thi, g_w2thi);
    cudaGetSymbolAddress((void**)&w2tlo, g_w2tlo);
    cudaGetSymbolAddress((void**)&w3thi, g_w3thi);
    cudaGetSymbolAddress((void**)&w3tlo, g_w3tlo);
    cudaGetSymbolAddress((void**)&h1p, g_h1p);
    cudaGetSymbolAddress((void**)&agg1hi, g_agg1hi);
    cudaGetSymbolAddress((void**)&agg1lo, g_agg1lo);
    cudaGetSymbolAddress((void**)&h2p, g_h2p);
    cudaGetSymbolAddress((void**)&h2, g_h2);
    cudaGetSymbolAddress((void**)&h2hi, g_h2hi);
    cudaGetSymbolAddress((void**)&h2lo, g_h2lo);
    cudaGetSymbolAddress((void**)&agg3hi, g_agg3hi);
    cudaGetSymbolAddress((void**)&agg3lo, g_agg3lo);
    cudaGetSymbolAddress((void**)&el, g_el);
    cudaGetSymbolAddress((void**)&er, g_er);
    cudaGetSymbolAddress((void**)&uv, g_uv);
    cudaGetSymbolAddress((void**)&deg, g_deg);
    cudaGetSymbolAddress((void**)&cursor, g_cursor);
    cudaGetSymbolAddress((void**)&rowptr, g_rowptr);
    cudaGetSymbolAddress((void**)&csrsrc, g_csrsrc);

    cudaFuncSetAttribute(ahat_hmma, cudaFuncAttributeMaxDynamicSharedMemorySize, AHAT_SMEM);
    cudaFuncSetAttribute(hmma_gemm, cudaFuncAttributeMaxDynamicSharedMemorySize, HG_SMEM);
    cudaFuncSetAttribute(dec_hmma, cudaFuncAttributeMaxDynamicSharedMemorySize, DEC_SMEM);

    static cudaStream_t s1 = nullptr, s2 = nullptr;
    static cudaEvent_t evRoot, evCSR, evW1, evW, evH2, evAhat;
    if (s1 == nullptr) {
        cudaStreamCreateWithFlags(&s1, cudaStreamNonBlocking);
        cudaStreamCreateWithFlags(&s2, cudaStreamNonBlocking);
        cudaEventCreateWithFlags(&evRoot, cudaEventDisableTiming);
        cudaEventCreateWithFlags(&evCSR, cudaEventDisableTiming);
        cudaEventCreateWithFlags(&evW1, cudaEventDisableTiming);
        cudaEventCreateWithFlags(&evW, cudaEventDisableTiming);
        cudaEventCreateWithFlags(&evH2, cudaEventDisableTiming);
        cudaEventCreateWithFlags(&evAhat, cudaEventDisableTiming);
    }

    float *el1 = el, *el2 = el + NN * 2, *el3 = el + 2 * NN * 2;
    float *er1 = er, *er2 = er + NN * 2, *er3 = er + 2 * NN * 2;

    const int eb = (E + 255) / 256;

    // fork side streams
    cudaEventRecord(evRoot, 0);
    cudaStreamWaitEvent(s1, evRoot, 0);
    cudaStreamWaitEvent(s2, evRoot, 0);

    // ---- s1: CSR build (first needed at k_agg1) ----
    k_zerodeg<<<(NN + 255) / 256, 256, 0, s1>>>(deg);
    k_deg<<<eb, 256, 0, s1>>>(dst, deg, E);
    k_scan<<<1, 256, 0, s1>>>(deg, rowptr, cursor);
    k_scatter<<<eb, 256, 0, s1>>>(src, dst, cursor, csrsrc, E);
    cudaEventRecord(evCSR, s1);

    // ---- s2: weight packs + decoder attention projection ----
    k_pack_w1t<<<256, 256, 0, s2>>>(W1, w1thi, w1tlo);
    cudaEventRecord(evW1, s2);
    k_pack_w2t<<<128, 256, 0, s2>>>(W2, w2thi, w2tlo);
    k_pack_w3t<<<NDEC, 64, 0, s2>>>(W3, w3thi, w3tlo);
    k_uv<<<16, 256, 0, s2>>>(W3, al3, ar3, uv);
    cudaEventRecord(evW, s2);

    // ---- main stream: layer 1 ----
    k_pack_feat<<<NN, 256>>>(feat, feathi, featlo);
    cudaStreamWaitEvent(0, evW1, 0);
    {
        dim3 grid(2, 64);
        hmma_gemm<<<grid, 256, HG_SMEM>>>(feathi, featlo, w1thi, w1tlo, h1p, FINB, FINB, FINB, 256);
    }
    k_elr<<<(NN * 2 * 32 + 255) / 256, 256>>>(h1p, al1, ar1, el1, er1, 128);
    cudaStreamWaitEvent(0, evCSR, 0);
    k_agg1<<<NN, 256>>>(rowptr, csrsrc, el1, er1, h1p, b1, agg1hi, agg1lo);

    // ---- layer 2 ----
    cudaStreamWaitEvent(0, evW, 0);
    {
        dim3 grid(1, 64);
        hmma_gemm<<<grid, 256, HG_SMEM>>>(agg1hi, agg1lo, w2thi, w2tlo, h2p, 256, 256, 256, 128);
    }
    k_elr<<<(NN * 2 * 32 + 255) / 256, 256>>>(h2p, al2, ar2, el2, er2, 64);
    k_agg2<<<NN, 128>>>(rowptr, csrsrc, el2, er2, h2p, b2, h2, h2hi, h2lo);
    cudaEventRecord(evH2, 0);

    // ---- s1: structure decoder a_hat (overlaps attribute decoder) ----
    cudaStreamWaitEvent(s1, evH2, 0);
    {
        dim3 grid(NN / 128, NN / 128);
        ahat_hmma<<<grid, 256, AHAT_SMEM, s1>>>(h2hi, h2lo, a_hat);
    }
    cudaEventRecord(evAhat, s1);

    // ---- main stream: attribute decoder ----
    k_elr3<<<(NN * 2 * 32 + 255) / 256, 256>>>(h2, uv, el3, er3);
    k_agg3<<<NN, 128>>>(rowptr, csrsrc, el3, er3, h2, agg3hi, agg3lo);
    {
        dim3 grid(NDEC / 64, NN / 128);
        dec_hmma<<<grid, 256, DEC_SMEM>>>(agg3hi, agg3lo, w3thi, w3tlo, b3, x_hat);
    }

    // join
    cudaStreamWaitEvent(0, evAhat, 0);
}